// round 3
// baseline (speedup 1.0000x reference)
#include <cuda_runtime.h>

// ---------------- problem constants ----------------
#define BB 64      // batch
#define CC 256     // input channels
#define DD 128     // head dim
#define NN 64      // board positions
#define HH 256     // hidden (2*DD)
#define SCALE_V 0.08838834764831845f   // 1/sqrt(128)

// ---------------- device scratch (no allocations allowed) ----------------
__device__ float g_f[3][BB][DD][NN];     // f_src / f_dst / f_arr          (6 MB)
__device__ float g_srcp[BB][NN][HH];     // src_p  (+ b1 folded in)        (4 MB)
__device__ float g_dstp[BB][NN][HH];     // dst_p                          (4 MB)
__device__ float g_w2t[HH][DD];          // w2 transposed: [h][o]
__device__ float g_G[BB][DD][NN];        // G[b][o][k] = sum_p w3[p][o] * f_arr[b][p][k]
__device__ float g_cv[BB][NN];           // c[b][k]    = sum_p b3[p]     * f_arr[b][p][k]

// ============================================================================
// Kernel P: projections  f[mat][b] = W_mat @ x[b] + bias_mat
// One CTA per (mat, b). Output tile 128(d) x 64(n), K = 256.
// ============================================================================
__global__ void __launch_bounds__(256) proj_kernel(
    const float* __restrict__ x,
    const float* __restrict__ w_src, const float* __restrict__ b_src,
    const float* __restrict__ w_dst, const float* __restrict__ b_dst,
    const float* __restrict__ w_arr, const float* __restrict__ b_arr)
{
    const int mat = blockIdx.x;
    const int b   = blockIdx.y;
    const float* w    = (mat == 0) ? w_src : (mat == 1) ? w_dst : w_arr;
    const float* bias = (mat == 0) ? b_src : (mat == 1) ? b_dst : b_arr;

    __shared__ float Ws[32][DD + 4];   // [kk][d] = w[d][c0+kk]
    __shared__ float Xs[32][NN + 4];   // [kk][n] = x[b][c0+kk][n]

    const int tid = threadIdx.x;
    const int tx  = tid & 15;          // n-group (4 n each)
    const int ty  = tid >> 4;          // d-group (8 d each)

    float acc[8][4];
#pragma unroll
    for (int i = 0; i < 8; i++)
#pragma unroll
        for (int j = 0; j < 4; j++) acc[i][j] = 0.f;

    const float* xb = x + (size_t)b * CC * NN;

#pragma unroll 1
    for (int c0 = 0; c0 < CC; c0 += 32) {
#pragma unroll
        for (int j = 0; j < 16; j++) {
            int i = tid + 256 * j;                 // 0..4095
            int d = i >> 5, kk = i & 31;
            Ws[kk][d] = w[d * CC + c0 + kk];
        }
#pragma unroll
        for (int j = 0; j < 8; j++) {
            int i = tid + 256 * j;                 // 0..2047
            int kk = i >> 6, n = i & 63;
            Xs[kk][n] = xb[(c0 + kk) * NN + n];
        }
        __syncthreads();
#pragma unroll
        for (int kk = 0; kk < 32; kk++) {
            float a[8], xv[4];
#pragma unroll
            for (int i = 0; i < 8; i++) a[i] = Ws[kk][ty * 8 + i];
#pragma unroll
            for (int j = 0; j < 4; j++) xv[j] = Xs[kk][tx * 4 + j];
#pragma unroll
            for (int i = 0; i < 8; i++)
#pragma unroll
                for (int j = 0; j < 4; j++) acc[i][j] += a[i] * xv[j];
        }
        __syncthreads();
    }

    float* out = &g_f[mat][b][0][0];
#pragma unroll
    for (int i = 0; i < 8; i++) {
        int d = ty * 8 + i;
        float bv = bias[d];
        float4 v = make_float4(acc[i][0] + bv, acc[i][1] + bv,
                               acc[i][2] + bv, acc[i][3] + bv);
        *reinterpret_cast<float4*>(&out[d * NN + tx * 4]) = v;
    }
}

// ============================================================================
// Kernel T: transpose w2 (128x256, row-major [o][h]) -> g_w2t[h][o]
// ============================================================================
__global__ void w2t_kernel(const float* __restrict__ w2)
{
    int idx = blockIdx.x * 256 + threadIdx.x;     // grid = 128 -> 32768 elems
    int h = idx >> 7, o = idx & 127;
    g_w2t[h][o] = w2[o * HH + h];
}

// ============================================================================
// Kernel M: move_logits[b][n][m] = scale * sum_d f_src[b][d][n] * f_dst[b][d][m]
// One CTA per b.
// ============================================================================
__global__ void __launch_bounds__(256) move_kernel(float* __restrict__ out_move)
{
    const int b = blockIdx.x;
    __shared__ float Ss[64][NN + 2];
    __shared__ float Dm[64][NN + 2];
    const int tid = threadIdx.x;
    const int tx  = tid & 15;     // m-group (4)
    const int ty  = tid >> 4;     // n-group (4)

    float acc[4][4];
#pragma unroll
    for (int i = 0; i < 4; i++)
#pragma unroll
        for (int j = 0; j < 4; j++) acc[i][j] = 0.f;

#pragma unroll 1
    for (int d0 = 0; d0 < DD; d0 += 64) {
#pragma unroll
        for (int j = 0; j < 16; j++) {
            int i = tid + 256 * j;                 // 0..4095
            int dd = i >> 6, n = i & 63;
            Ss[dd][n] = g_f[0][b][d0 + dd][n];
            Dm[dd][n] = g_f[1][b][d0 + dd][n];
        }
        __syncthreads();
#pragma unroll
        for (int dd = 0; dd < 64; dd++) {
            float sv[4], dv[4];
#pragma unroll
            for (int i = 0; i < 4; i++) sv[i] = Ss[dd][ty * 4 + i];
#pragma unroll
            for (int j = 0; j < 4; j++) dv[j] = Dm[dd][tx * 4 + j];
#pragma unroll
            for (int i = 0; i < 4; i++)
#pragma unroll
                for (int j = 0; j < 4; j++) acc[i][j] += sv[i] * dv[j];
        }
        __syncthreads();
    }
#pragma unroll
    for (int i = 0; i < 4; i++) {
        int n = ty * 4 + i;
        float4 v = make_float4(acc[i][0] * SCALE_V, acc[i][1] * SCALE_V,
                               acc[i][2] * SCALE_V, acc[i][3] * SCALE_V);
        *reinterpret_cast<float4*>(&out_move[(b * NN + n) * NN + tx * 4]) = v;
    }
}

// ============================================================================
// Kernel S: src_p / dst_p
//   type 0: g_srcp[b][n][h] = sum_d f_src[b][d][n] * w1[h][d]       + b1[h]
//   type 1: g_dstp[b][m][h] = sum_d f_dst[b][d][m] * w1[h][128+d]
// One CTA per (type, b). Output tile 64(n) x 256(h), K = 128.
// ============================================================================
__global__ void __launch_bounds__(256) sp_kernel(
    const float* __restrict__ w1, const float* __restrict__ b1)
{
    const int type = blockIdx.x;
    const int b    = blockIdx.y;
    __shared__ float Ws[32][HH + 4];   // [kk][h] = w1[h][off + d0 + kk]
    __shared__ float Fs[32][NN + 4];   // [kk][n] = f[type][b][d0+kk][n]
    const int tid = threadIdx.x;
    const int tx  = tid & 15;          // h-group (16 h each)
    const int ty  = tid >> 4;          // n-group (4 n each)
    const int off = type * DD;

    float acc[4][16];
#pragma unroll
    for (int i = 0; i < 4; i++)
#pragma unroll
        for (int j = 0; j < 16; j++) acc[i][j] = 0.f;

#pragma unroll 1
    for (int d0 = 0; d0 < DD; d0 += 32) {
#pragma unroll
        for (int j = 0; j < 32; j++) {
            int i = tid + 256 * j;                 // 0..8191
            int h = i >> 5, kk = i & 31;
            Ws[kk][h] = w1[h * HH + off + d0 + kk];
        }
#pragma unroll
        for (int j = 0; j < 8; j++) {
            int i = tid + 256 * j;                 // 0..2047
            int kk = i >> 6, n = i & 63;
            Fs[kk][n] = g_f[type][b][d0 + kk][n];
        }
        __syncthreads();
#pragma unroll
        for (int kk = 0; kk < 32; kk++) {
            float fv[4], wv[16];
#pragma unroll
            for (int i = 0; i < 4; i++) fv[i] = Fs[kk][ty * 4 + i];
#pragma unroll
            for (int j = 0; j < 16; j++) wv[j] = Ws[kk][tx * 16 + j];
#pragma unroll
            for (int i = 0; i < 4; i++)
#pragma unroll
                for (int j = 0; j < 16; j++) acc[i][j] += fv[i] * wv[j];
        }
        __syncthreads();
    }

    float* out = (type == 0) ? &g_srcp[b][0][0] : &g_dstp[b][0][0];
#pragma unroll
    for (int i = 0; i < 4; i++) {
        int n = ty * 4 + i;
#pragma unroll
        for (int j4 = 0; j4 < 4; j4++) {
            int h = tx * 16 + j4 * 4;
            float b0 = (type == 0) ? b1[h + 0] : 0.f;
            float b1v = (type == 0) ? b1[h + 1] : 0.f;
            float b2v = (type == 0) ? b1[h + 2] : 0.f;
            float b3v = (type == 0) ? b1[h + 3] : 0.f;
            float4 v = make_float4(acc[i][j4 * 4 + 0] + b0,
                                   acc[i][j4 * 4 + 1] + b1v,
                                   acc[i][j4 * 4 + 2] + b2v,
                                   acc[i][j4 * 4 + 3] + b3v);
            *reinterpret_cast<float4*>(&out[n * HH + h]) = v;
        }
    }
}

// ============================================================================
// Kernel G: fold w3/b3 into f_arr:
//   g_G[b][o][k] = sum_p w3[p][o] * f_arr[b][p][k]
//   g_cv[b][k]   = sum_p b3[p]    * f_arr[b][p][k]
// One CTA per b. Output 128(o) x 64(k), K = 128(p).
// ============================================================================
__global__ void __launch_bounds__(256) g_kernel(
    const float* __restrict__ w3, const float* __restrict__ b3)
{
    const int b = blockIdx.x;
    __shared__ float W3s[32][DD + 4];  // [kk][o] = w3[p0+kk][o]
    __shared__ float Fs[32][NN + 4];   // [kk][k] = f_arr[b][p0+kk][k]
    __shared__ float b3s[32];
    const int tid = threadIdx.x;
    const int tx  = tid & 15;          // k-group (4)
    const int ty  = tid >> 4;          // o-group (8)

    float acc[8][4];
    float cacc[4] = {0.f, 0.f, 0.f, 0.f};
#pragma unroll
    for (int i = 0; i < 8; i++)
#pragma unroll
        for (int j = 0; j < 4; j++) acc[i][j] = 0.f;

#pragma unroll 1
    for (int p0 = 0; p0 < DD; p0 += 32) {
#pragma unroll
        for (int j = 0; j < 16; j++) {
            int i = tid + 256 * j;                 // 0..4095
            int kk = i >> 7, o = i & 127;
            W3s[kk][o] = w3[(p0 + kk) * DD + o];
        }
#pragma unroll
        for (int j = 0; j < 8; j++) {
            int i = tid + 256 * j;                 // 0..2047
            int kk = i >> 6, k = i & 63;
            Fs[kk][k] = g_f[2][b][p0 + kk][k];
        }
        if (tid < 32) b3s[tid] = b3[p0 + tid];
        __syncthreads();
#pragma unroll
        for (int kk = 0; kk < 32; kk++) {
            float wv[8], fv[4];
#pragma unroll
            for (int i = 0; i < 8; i++) wv[i] = W3s[kk][ty * 8 + i];
#pragma unroll
            for (int j = 0; j < 4; j++) fv[j] = Fs[kk][tx * 4 + j];
#pragma unroll
            for (int i = 0; i < 8; i++)
#pragma unroll
                for (int j = 0; j < 4; j++) acc[i][j] += wv[i] * fv[j];
            if (ty == 0) {
                float bv = b3s[kk];
#pragma unroll
                for (int j = 0; j < 4; j++) cacc[j] += bv * fv[j];
            }
        }
        __syncthreads();
    }
#pragma unroll
    for (int i = 0; i < 8; i++) {
        int o = ty * 8 + i;
        float4 v = make_float4(acc[i][0], acc[i][1], acc[i][2], acc[i][3]);
        *reinterpret_cast<float4*>(&g_G[b][o][tx * 4]) = v;
    }
    if (ty == 0) {
        float4 v = make_float4(cacc[0], cacc[1], cacc[2], cacc[3]);
        *reinterpret_cast<float4*>(&g_cv[b][tx * 4]) = v;
    }
}

// ============================================================================
// Kernel C (hot): fused h1 -> h2 -> arrow.
// One CTA per (b, m-pair). Rows: row = lm*64 + n, lm in {0,1}, m = m0+lm.
//   GEMM1: A[128 x 256] (generated: relu(srcp[n]+b1 + dstp[m])) @ w2t -> h2[128x128]
//   GEMM2: h2[128x128] @ G[b][128x64] -> arrow tile, +c, *scale
// Dynamic SMEM layout (floats):
//   Gs  [0      .. 8704 )   G[b] padded [128][68]
//   Cs  [8704   .. 8768 )   c[b] [64]
//   win [8768   .. 25664):  phase1: As[32][132] | Bs[32][132] | Ds2[2][256]
//                           phase2: H2s[128][132]  (aliases the phase-1 window)
// ============================================================================
__global__ void __launch_bounds__(256) main_kernel(
    const float* __restrict__ b2, float* __restrict__ out_arrow)
{
    extern __shared__ float sm[];
    float* Gs  = sm;                   // [128][68]
    float* Cs  = sm + 8704;            // [64]
    float* As  = sm + 8768;            // [32][132]
    float* Bs  = sm + 8768 + 4224;     // [32][132]
    float* Ds2 = sm + 8768 + 8448;     // [2][256]
    float* H2s = sm + 8768;            // [128][132] (phase 2, aliases above)

    const int mt  = blockIdx.x;        // 0..31
    const int b   = blockIdx.y;        // 0..63
    const int m0  = mt * 2;
    const int tid = threadIdx.x;
    const int tx  = tid & 15;
    const int ty  = tid >> 4;

    // --- load G[b] / c[b] (region untouched by phase 1) and dst_p rows ---
    {
        const float4* G4 = reinterpret_cast<const float4*>(&g_G[b][0][0]);
#pragma unroll
        for (int j = 0; j < 8; j++) {
            int i = tid + 256 * j;                 // 0..2047 float4s
            int o = i >> 4, k4 = i & 15;
            *reinterpret_cast<float4*>(&Gs[o * 68 + k4 * 4]) = G4[i];
        }
        if (tid < 64) Cs[tid] = g_cv[b][tid];
    }
    Ds2[tid]       = g_dstp[b][m0][tid];
    Ds2[256 + tid] = g_dstp[b][m0 + 1][tid];
    __syncthreads();

    const int an   = tid >> 2;                     // n handled in A-gen
    const int akk0 = (tid & 3) * 8;

    float acc1[8][8];
#pragma unroll
    for (int i = 0; i < 8; i++)
#pragma unroll
        for (int j = 0; j < 8; j++) acc1[i][j] = 0.f;

    // ---------------- GEMM1: K = 256 in 8 chunks of 32 ----------------
#pragma unroll 1
    for (int kc = 0; kc < 8; kc++) {
        const int h0 = kc * 32;
        // Bs[kk][o] = w2t[h0+kk][o]
        const float4* w2t4 = reinterpret_cast<const float4*>(&g_w2t[h0][0]);
#pragma unroll
        for (int j = 0; j < 4; j++) {
            int i = tid + 256 * j;                 // 0..1023 float4s
            int kk = i >> 5, o4 = i & 31;
            *reinterpret_cast<float4*>(&Bs[kk * 132 + o4 * 4]) = w2t4[kk * 32 + o4];
        }
        // As[kk][lm*64+n] = relu(srcp[b][n][h0+kk] + dstp[b][m0+lm][h0+kk])
        {
            const float* sp = &g_srcp[b][an][h0 + akk0];
            float4 s0 = *reinterpret_cast<const float4*>(sp);
            float4 s1 = *reinterpret_cast<const float4*>(sp + 4);
            float sv[8] = {s0.x, s0.y, s0.z, s0.w, s1.x, s1.y, s1.z, s1.w};
#pragma unroll
            for (int q = 0; q < 8; q++) {
                int kk = akk0 + q;
                As[kk * 132 + an]      = fmaxf(sv[q] + Ds2[h0 + kk],       0.f);
                As[kk * 132 + 64 + an] = fmaxf(sv[q] + Ds2[256 + h0 + kk], 0.f);
            }
        }
        __syncthreads();
#pragma unroll
        for (int kk = 0; kk < 32; kk++) {
            float4 a0 = *reinterpret_cast<const float4*>(&As[kk * 132 + ty * 8]);
            float4 a1 = *reinterpret_cast<const float4*>(&As[kk * 132 + ty * 8 + 4]);
            float4 c0 = *reinterpret_cast<const float4*>(&Bs[kk * 132 + tx * 8]);
            float4 c1 = *reinterpret_cast<const float4*>(&Bs[kk * 132 + tx * 8 + 4]);
            float a[8]  = {a0.x, a0.y, a0.z, a0.w, a1.x, a1.y, a1.z, a1.w};
            float bb[8] = {c0.x, c0.y, c0.z, c0.w, c1.x, c1.y, c1.z, c1.w};
#pragma unroll
            for (int i = 0; i < 8; i++)
#pragma unroll
                for (int j = 0; j < 8; j++) acc1[i][j] += a[i] * bb[j];
        }
        __syncthreads();
    }

    // ---------------- stage h2 = relu(acc1 + b2) transposed [o][row] -------
#pragma unroll
    for (int j = 0; j < 8; j++) {
        int o = tx * 8 + j;
        float bv = __ldg(&b2[o]);
#pragma unroll
        for (int i = 0; i < 8; i++)
            H2s[o * 132 + ty * 8 + i] = fmaxf(acc1[i][j] + bv, 0.f);
    }
    __syncthreads();

    // ---------------- GEMM2: out[row][k] = sum_o h2[row][o]*G[o][k] --------
    float acc2[8][4];
#pragma unroll
    for (int i = 0; i < 8; i++)
#pragma unroll
        for (int j = 0; j < 4; j++) acc2[i][j] = 0.f;

#pragma unroll 4
    for (int o = 0; o < 128; o++) {
        float4 a0 = *reinterpret_cast<const float4*>(&H2s[o * 132 + ty * 8]);
        float4 a1 = *reinterpret_cast<const float4*>(&H2s[o * 132 + ty * 8 + 4]);
        float4 g  = *reinterpret_cast<const float4*>(&Gs[o * 68 + tx * 4]);
        float a[8]  = {a0.x, a0.y, a0.z, a0.w, a1.x, a1.y, a1.z, a1.w};
        float gv[4] = {g.x, g.y, g.z, g.w};
#pragma unroll
        for (int i = 0; i < 8; i++)
#pragma unroll
            for (int j = 0; j < 4; j++) acc2[i][j] += a[i] * gv[j];
    }

    // ---------------- epilogue: arrow[b][n*64+m][k] -------------------------
    float cv[4] = {Cs[tx * 4 + 0], Cs[tx * 4 + 1], Cs[tx * 4 + 2], Cs[tx * 4 + 3]};
#pragma unroll
    for (int i = 0; i < 8; i++) {
        int row = ty * 8 + i;
        int n = row & 63;
        int m = m0 + (row >> 6);
        float4 v = make_float4((acc2[i][0] + cv[0]) * SCALE_V,
                               (acc2[i][1] + cv[1]) * SCALE_V,
                               (acc2[i][2] + cv[2]) * SCALE_V,
                               (acc2[i][3] + cv[3]) * SCALE_V);
        int off = ((b * 4096 + n * 64 + m) << 6) + tx * 4;
        *reinterpret_cast<float4*>(&out_arrow[off]) = v;
    }
}

// ============================================================================
// launch
// ============================================================================
extern "C" void kernel_launch(void* const* d_in, const int* in_sizes, int n_in,
                              void* d_out, int out_size)
{
    (void)in_sizes; (void)n_in; (void)out_size;
    const float* x     = (const float*)d_in[0];
    const float* w_src = (const float*)d_in[1];
    const float* b_src = (const float*)d_in[2];
    const float* w_dst = (const float*)d_in[3];
    const float* b_dst = (const float*)d_in[4];
    const float* w_arr = (const float*)d_in[5];
    const float* b_arr = (const float*)d_in[6];
    const float* w1    = (const float*)d_in[7];
    const float* b1    = (const float*)d_in[8];
    const float* w2    = (const float*)d_in[9];
    const float* b2    = (const float*)d_in[10];
    const float* w3    = (const float*)d_in[11];
    const float* b3    = (const float*)d_in[12];

    float* out_move  = (float*)d_out;                       // 64*64*64
    float* out_arrow = (float*)d_out + 64 * 64 * 64;        // 64*4096*64

    constexpr int SMEM_MAIN = 25664 * 4;   // 102,656 bytes dynamic smem
    cudaFuncSetAttribute(main_kernel, cudaFuncAttributeMaxDynamicSharedMemorySize,
                         SMEM_MAIN);

    proj_kernel<<<dim3(3, 64), 256>>>(x, w_src, b_src, w_dst, b_dst, w_arr, b_arr);
    w2t_kernel<<<128, 256>>>(w2);
    move_kernel<<<64, 256>>>(out_move);
    sp_kernel<<<dim3(2, 64), 256>>>(w1, b1);
    g_kernel<<<64, 256>>>(w3, b3);
    main_kernel<<<dim3(32, 64), 256, SMEM_MAIN>>>(b2, out_arrow);
}

// round 4
// speedup vs baseline: 1.0491x; 1.0491x over previous
#include <cuda_runtime.h>

// ---------------- problem constants ----------------
#define BB 64      // batch
#define CC 256     // input channels
#define DD 128     // head dim
#define NN 64      // board positions
#define HH 256     // hidden (2*DD)
#define SCALE_V 0.08838834764831845f   // 1/sqrt(128)

typedef unsigned long long u64t;

// ---------------- packed f32x2 helpers (sm_100a) ----------------
__device__ __forceinline__ u64t pack2(float x) {
    u64t r; asm("mov.b64 %0, {%1, %1};" : "=l"(r) : "f"(x)); return r;
}
__device__ __forceinline__ void ffma2(u64t& d, u64t a, u64t b) {
    asm("fma.rn.f32x2 %0, %1, %2, %0;" : "+l"(d) : "l"(a), "l"(b));
}
__device__ __forceinline__ float2 unpack2(u64t v) {
    float2 f; asm("mov.b64 {%0, %1}, %2;" : "=f"(f.x), "=f"(f.y) : "l"(v)); return f;
}

// ---------------- device scratch (no allocations allowed) ----------------
__device__ float g_f[3][BB][DD][NN];     // f_src / f_dst / f_arr
__device__ float g_srcp[BB][NN][HH];     // src_p (+ b1 folded in)
__device__ float g_dstp[BB][NN][HH];     // dst_p
__device__ float g_w2t[HH][DD];          // w2 transposed: [h][o]
__device__ float g_G[BB][DD][NN];        // G[b][o][k] = sum_p w3[p][o] * f_arr[b][p][k]
__device__ float g_cv[BB][NN];           // c[b][k]    = sum_p b3[p]    * f_arr[b][p][k]

// ============================================================================
// Kernel P: projections  f[mat][b] = W_mat @ x[b] + bias_mat
// ============================================================================
__global__ void __launch_bounds__(256) proj_kernel(
    const float* __restrict__ x,
    const float* __restrict__ w_src, const float* __restrict__ b_src,
    const float* __restrict__ w_dst, const float* __restrict__ b_dst,
    const float* __restrict__ w_arr, const float* __restrict__ b_arr)
{
    const int mat = blockIdx.x;
    const int b   = blockIdx.y;
    const float* w    = (mat == 0) ? w_src : (mat == 1) ? w_dst : w_arr;
    const float* bias = (mat == 0) ? b_src : (mat == 1) ? b_dst : b_arr;

    __shared__ float Ws[32][DD + 4];   // [kk][d]
    __shared__ float Xs[32][NN + 4];   // [kk][n]

    const int tid = threadIdx.x;
    const int tx  = tid & 15;          // n-group (4)
    const int ty  = tid >> 4;          // d-group (8)

    float acc[8][4];
#pragma unroll
    for (int i = 0; i < 8; i++)
#pragma unroll
        for (int j = 0; j < 4; j++) acc[i][j] = 0.f;

    const float* xb = x + (size_t)b * CC * NN;

#pragma unroll 1
    for (int c0 = 0; c0 < CC; c0 += 32) {
#pragma unroll
        for (int j = 0; j < 16; j++) {
            int i = tid + 256 * j;
            int d = i >> 5, kk = i & 31;
            Ws[kk][d] = w[d * CC + c0 + kk];
        }
#pragma unroll
        for (int j = 0; j < 8; j++) {
            int i = tid + 256 * j;
            int kk = i >> 6, n = i & 63;
            Xs[kk][n] = xb[(c0 + kk) * NN + n];
        }
        __syncthreads();
#pragma unroll
        for (int kk = 0; kk < 32; kk++) {
            float a[8], xv[4];
#pragma unroll
            for (int i = 0; i < 8; i++) a[i] = Ws[kk][ty * 8 + i];
#pragma unroll
            for (int j = 0; j < 4; j++) xv[j] = Xs[kk][tx * 4 + j];
#pragma unroll
            for (int i = 0; i < 8; i++)
#pragma unroll
                for (int j = 0; j < 4; j++) acc[i][j] += a[i] * xv[j];
        }
        __syncthreads();
    }

    float* out = &g_f[mat][b][0][0];
#pragma unroll
    for (int i = 0; i < 8; i++) {
        int d = ty * 8 + i;
        float bv = bias[d];
        float4 v = make_float4(acc[i][0] + bv, acc[i][1] + bv,
                               acc[i][2] + bv, acc[i][3] + bv);
        *reinterpret_cast<float4*>(&out[d * NN + tx * 4]) = v;
    }
}

// ============================================================================
// Kernel T: transpose w2 -> g_w2t[h][o]
// ============================================================================
__global__ void w2t_kernel(const float* __restrict__ w2)
{
    int idx = blockIdx.x * 256 + threadIdx.x;
    int h = idx >> 7, o = idx & 127;
    g_w2t[h][o] = w2[o * HH + h];
}

// ============================================================================
// Kernel M: move_logits
// ============================================================================
__global__ void __launch_bounds__(256) move_kernel(float* __restrict__ out_move)
{
    const int b = blockIdx.x;
    __shared__ float Ss[64][NN + 2];
    __shared__ float Dm[64][NN + 2];
    const int tid = threadIdx.x;
    const int tx  = tid & 15;
    const int ty  = tid >> 4;

    float acc[4][4];
#pragma unroll
    for (int i = 0; i < 4; i++)
#pragma unroll
        for (int j = 0; j < 4; j++) acc[i][j] = 0.f;

#pragma unroll 1
    for (int d0 = 0; d0 < DD; d0 += 64) {
#pragma unroll
        for (int j = 0; j < 16; j++) {
            int i = tid + 256 * j;
            int dd = i >> 6, n = i & 63;
            Ss[dd][n] = g_f[0][b][d0 + dd][n];
            Dm[dd][n] = g_f[1][b][d0 + dd][n];
        }
        __syncthreads();
#pragma unroll
        for (int dd = 0; dd < 64; dd++) {
            float sv[4], dv[4];
#pragma unroll
            for (int i = 0; i < 4; i++) sv[i] = Ss[dd][ty * 4 + i];
#pragma unroll
            for (int j = 0; j < 4; j++) dv[j] = Dm[dd][tx * 4 + j];
#pragma unroll
            for (int i = 0; i < 4; i++)
#pragma unroll
                for (int j = 0; j < 4; j++) acc[i][j] += sv[i] * dv[j];
        }
        __syncthreads();
    }
#pragma unroll
    for (int i = 0; i < 4; i++) {
        int n = ty * 4 + i;
        float4 v = make_float4(acc[i][0] * SCALE_V, acc[i][1] * SCALE_V,
                               acc[i][2] * SCALE_V, acc[i][3] * SCALE_V);
        *reinterpret_cast<float4*>(&out_move[(b * NN + n) * NN + tx * 4]) = v;
    }
}

// ============================================================================
// Kernel S (v2): src_p / dst_p, h-split for parallelism.
//   grid (2 types, 64 b, 2 h-halves); CTA computes out[64n][128h], K = 128.
// ============================================================================
__global__ void __launch_bounds__(256) sp_kernel(
    const float* __restrict__ w1, const float* __restrict__ b1)
{
    const int type  = blockIdx.x;
    const int b     = blockIdx.y;
    const int hbase = blockIdx.z * 128;
    __shared__ float Ws[32][132];   // [kk][h-local]
    __shared__ float Fs[32][68];    // [kk][n]
    const int tid = threadIdx.x;
    const int tx  = tid & 15;       // h-group (8 each)
    const int ty  = tid >> 4;       // n-group (4 each)
    const int off = type * DD;

    float acc[4][8];
#pragma unroll
    for (int i = 0; i < 4; i++)
#pragma unroll
        for (int j = 0; j < 8; j++) acc[i][j] = 0.f;

#pragma unroll 1
    for (int d0 = 0; d0 < DD; d0 += 32) {
#pragma unroll
        for (int j = 0; j < 16; j++) {
            int i = tid + 256 * j;              // 0..4095
            int h = i >> 5, kk = i & 31;
            Ws[kk][h] = w1[(hbase + h) * HH + off + d0 + kk];
        }
#pragma unroll
        for (int j = 0; j < 2; j++) {
            int i = tid + 256 * j;              // 0..511 float4s
            int kk = i >> 4, n4 = i & 15;
            *reinterpret_cast<float4*>(&Fs[kk][n4 * 4]) =
                *reinterpret_cast<const float4*>(&g_f[type][b][d0 + kk][n4 * 4]);
        }
        __syncthreads();
#pragma unroll
        for (int kk = 0; kk < 32; kk++) {
            float4 fv = *reinterpret_cast<const float4*>(&Fs[kk][ty * 4]);
            float4 w0 = *reinterpret_cast<const float4*>(&Ws[kk][tx * 8]);
            float4 w1v = *reinterpret_cast<const float4*>(&Ws[kk][tx * 8 + 4]);
            float f[4] = {fv.x, fv.y, fv.z, fv.w};
            float wv[8] = {w0.x, w0.y, w0.z, w0.w, w1v.x, w1v.y, w1v.z, w1v.w};
#pragma unroll
            for (int i = 0; i < 4; i++)
#pragma unroll
                for (int j = 0; j < 8; j++) acc[i][j] += f[i] * wv[j];
        }
        __syncthreads();
    }

    float* out = (type == 0) ? &g_srcp[b][0][0] : &g_dstp[b][0][0];
    float bv[8];
#pragma unroll
    for (int j = 0; j < 8; j++)
        bv[j] = (type == 0) ? b1[hbase + tx * 8 + j] : 0.f;
#pragma unroll
    for (int i = 0; i < 4; i++) {
        int n = ty * 4 + i;
        float4 v0 = make_float4(acc[i][0] + bv[0], acc[i][1] + bv[1],
                                acc[i][2] + bv[2], acc[i][3] + bv[3]);
        float4 v1 = make_float4(acc[i][4] + bv[4], acc[i][5] + bv[5],
                                acc[i][6] + bv[6], acc[i][7] + bv[7]);
        *reinterpret_cast<float4*>(&out[n * HH + hbase + tx * 8])     = v0;
        *reinterpret_cast<float4*>(&out[n * HH + hbase + tx * 8 + 4]) = v1;
    }
}

// ============================================================================
// Kernel G: fold w3/b3 into f_arr.
// ============================================================================
__global__ void __launch_bounds__(256) g_kernel(
    const float* __restrict__ w3, const float* __restrict__ b3)
{
    const int b = blockIdx.x;
    __shared__ float W3s[32][DD + 4];
    __shared__ float Fs[32][NN + 4];
    __shared__ float b3s[32];
    const int tid = threadIdx.x;
    const int tx  = tid & 15;
    const int ty  = tid >> 4;

    float acc[8][4];
    float cacc[4] = {0.f, 0.f, 0.f, 0.f};
#pragma unroll
    for (int i = 0; i < 8; i++)
#pragma unroll
        for (int j = 0; j < 4; j++) acc[i][j] = 0.f;

#pragma unroll 1
    for (int p0 = 0; p0 < DD; p0 += 32) {
#pragma unroll
        for (int j = 0; j < 16; j++) {
            int i = tid + 256 * j;
            int kk = i >> 7, o = i & 127;
            W3s[kk][o] = w3[(p0 + kk) * DD + o];
        }
#pragma unroll
        for (int j = 0; j < 8; j++) {
            int i = tid + 256 * j;
            int kk = i >> 6, k = i & 63;
            Fs[kk][k] = g_f[2][b][p0 + kk][k];
        }
        if (tid < 32) b3s[tid] = b3[p0 + tid];
        __syncthreads();
#pragma unroll
        for (int kk = 0; kk < 32; kk++) {
            float wv[8], fv[4];
#pragma unroll
            for (int i = 0; i < 8; i++) wv[i] = W3s[kk][ty * 8 + i];
#pragma unroll
            for (int j = 0; j < 4; j++) fv[j] = Fs[kk][tx * 4 + j];
#pragma unroll
            for (int i = 0; i < 8; i++)
#pragma unroll
                for (int j = 0; j < 4; j++) acc[i][j] += wv[i] * fv[j];
            if (ty == 0) {
                float bvv = b3s[kk];
#pragma unroll
                for (int j = 0; j < 4; j++) cacc[j] += bvv * fv[j];
            }
        }
        __syncthreads();
    }
#pragma unroll
    for (int i = 0; i < 8; i++) {
        int o = ty * 8 + i;
        float4 v = make_float4(acc[i][0], acc[i][1], acc[i][2], acc[i][3]);
        *reinterpret_cast<float4*>(&g_G[b][o][tx * 4]) = v;
    }
    if (ty == 0) {
        float4 v = make_float4(cacc[0], cacc[1], cacc[2], cacc[3]);
        *reinterpret_cast<float4*>(&g_cv[b][tx * 4]) = v;
    }
}

// ============================================================================
// Kernel C (hot): fused h1 -> h2 -> arrow, packed-f32x2 FMA, 2 CTAs/SM.
// Dynamic SMEM (floats):
//   Gs  [0      .. 8704 )   G[b] padded [128][68]
//   Cs  [8704   .. 8768 )   c[b] [64]
//   win [8768   .. 25664):  phase1: As[32][132] | Bs[32][132] | Ds2[2][256]
//                           phase2: H2s[128][132] (aliases phase-1 window)
//   B2s [25664  .. 25792)   b2 [128]
// ============================================================================
__global__ void __launch_bounds__(256, 2) main_kernel(
    const float* __restrict__ b2, float* __restrict__ out_arrow)
{
    extern __shared__ float sm[];
    float* Gs  = sm;                   // [128][68]
    float* Cs  = sm + 8704;            // [64]
    float* As  = sm + 8768;            // [32][132]
    float* Bs  = sm + 8768 + 4224;     // [32][132]
    float* Ds2 = sm + 8768 + 8448;     // [2][256]
    float* H2s = sm + 8768;            // [128][132] (phase 2)
    float* B2s = sm + 25664;           // [128]

    const int mt  = blockIdx.x;        // 0..31
    const int b   = blockIdx.y;        // 0..63
    const int m0  = mt * 2;
    const int tid = threadIdx.x;
    const int tx  = tid & 15;
    const int ty  = tid >> 4;

    // --- prologue loads ---
    {
        const float4* G4 = reinterpret_cast<const float4*>(&g_G[b][0][0]);
#pragma unroll
        for (int j = 0; j < 8; j++) {
            int i = tid + 256 * j;                 // 0..2047 float4s
            int o = i >> 4, k4 = i & 15;
            *reinterpret_cast<float4*>(&Gs[o * 68 + k4 * 4]) = G4[i];
        }
        if (tid < 64) Cs[tid] = g_cv[b][tid];
        if (tid < 128) B2s[tid] = b2[tid];
    }
    Ds2[tid]       = g_dstp[b][m0][tid];
    Ds2[256 + tid] = g_dstp[b][m0 + 1][tid];
    __syncthreads();

    const int an   = tid >> 2;                     // n handled in A-gen
    const int akk0 = (tid & 3) * 8;

    u64t acc1p[32];                                // 4 row-pairs x 8 cols
#pragma unroll
    for (int i = 0; i < 32; i++) acc1p[i] = 0ull;

    // ---------------- GEMM1: K = 256 in 8 chunks of 32 ----------------
#pragma unroll 1
    for (int kc = 0; kc < 8; kc++) {
        const int h0 = kc * 32;
        const float4* w2t4 = reinterpret_cast<const float4*>(&g_w2t[h0][0]);
#pragma unroll
        for (int j = 0; j < 4; j++) {
            int i = tid + 256 * j;                 // 0..1023 float4s
            int kk = i >> 5, o4 = i & 31;
            *reinterpret_cast<float4*>(&Bs[kk * 132 + o4 * 4]) = w2t4[kk * 32 + o4];
        }
        {
            const float* sp = &g_srcp[b][an][h0 + akk0];
            float4 s0 = *reinterpret_cast<const float4*>(sp);
            float4 s1 = *reinterpret_cast<const float4*>(sp + 4);
            float sv[8] = {s0.x, s0.y, s0.z, s0.w, s1.x, s1.y, s1.z, s1.w};
#pragma unroll
            for (int q = 0; q < 8; q++) {
                int kk = akk0 + q;
                As[kk * 132 + an]      = fmaxf(sv[q] + Ds2[h0 + kk],       0.f);
                As[kk * 132 + 64 + an] = fmaxf(sv[q] + Ds2[256 + h0 + kk], 0.f);
            }
        }
        __syncthreads();
#pragma unroll
        for (int kk = 0; kk < 32; kk++) {
            ulonglong2 a01 = *reinterpret_cast<const ulonglong2*>(&As[kk * 132 + ty * 8]);
            ulonglong2 a23 = *reinterpret_cast<const ulonglong2*>(&As[kk * 132 + ty * 8 + 4]);
            float4 c0 = *reinterpret_cast<const float4*>(&Bs[kk * 132 + tx * 8]);
            float4 c1 = *reinterpret_cast<const float4*>(&Bs[kk * 132 + tx * 8 + 4]);
            u64t ap[4] = {a01.x, a01.y, a23.x, a23.y};
            u64t bp[8] = {pack2(c0.x), pack2(c0.y), pack2(c0.z), pack2(c0.w),
                          pack2(c1.x), pack2(c1.y), pack2(c1.z), pack2(c1.w)};
#pragma unroll
            for (int r = 0; r < 4; r++)
#pragma unroll
                for (int j = 0; j < 8; j++)
                    ffma2(acc1p[r * 8 + j], ap[r], bp[j]);
        }
        __syncthreads();
    }

    // ---------------- stage h2 = relu(acc1 + b2) transposed [o][row] -------
#pragma unroll
    for (int j = 0; j < 8; j++) {
        int o = tx * 8 + j;
        float bv = B2s[o];
#pragma unroll
        for (int r = 0; r < 4; r++) {
            float2 v = unpack2(acc1p[r * 8 + j]);
            H2s[o * 132 + ty * 8 + 2 * r]     = fmaxf(v.x + bv, 0.f);
            H2s[o * 132 + ty * 8 + 2 * r + 1] = fmaxf(v.y + bv, 0.f);
        }
    }
    __syncthreads();

    // ---------------- GEMM2: out[row][k] = sum_o h2[row][o]*G[o][k] --------
    u64t acc2p[16];                                // 4 row-pairs x 4 k
#pragma unroll
    for (int i = 0; i < 16; i++) acc2p[i] = 0ull;

#pragma unroll 4
    for (int o = 0; o < 128; o++) {
        ulonglong2 h01 = *reinterpret_cast<const ulonglong2*>(&H2s[o * 132 + ty * 8]);
        ulonglong2 h23 = *reinterpret_cast<const ulonglong2*>(&H2s[o * 132 + ty * 8 + 4]);
        float4 g = *reinterpret_cast<const float4*>(&Gs[o * 68 + tx * 4]);
        u64t hp[4] = {h01.x, h01.y, h23.x, h23.y};
        u64t gp[4] = {pack2(g.x), pack2(g.y), pack2(g.z), pack2(g.w)};
#pragma unroll
        for (int r = 0; r < 4; r++)
#pragma unroll
            for (int k = 0; k < 4; k++)
                ffma2(acc2p[r * 4 + k], hp[r], gp[k]);
    }

    // ---------------- epilogue: arrow[b][n*64+m][k] -------------------------
    float cv[4] = {Cs[tx * 4 + 0], Cs[tx * 4 + 1], Cs[tx * 4 + 2], Cs[tx * 4 + 3]};
#pragma unroll
    for (int r = 0; r < 4; r++) {
        float2 t0 = unpack2(acc2p[r * 4 + 0]);
        float2 t1 = unpack2(acc2p[r * 4 + 1]);
        float2 t2 = unpack2(acc2p[r * 4 + 2]);
        float2 t3 = unpack2(acc2p[r * 4 + 3]);
        int row0 = ty * 8 + 2 * r;                 // even; pair never crosses 63/64
        int n0 = row0 & 63;
        int m  = m0 + (row0 >> 6);
        float4 v0 = make_float4((t0.x + cv[0]) * SCALE_V, (t1.x + cv[1]) * SCALE_V,
                                (t2.x + cv[2]) * SCALE_V, (t3.x + cv[3]) * SCALE_V);
        float4 v1 = make_float4((t0.y + cv[0]) * SCALE_V, (t1.y + cv[1]) * SCALE_V,
                                (t2.y + cv[2]) * SCALE_V, (t3.y + cv[3]) * SCALE_V);
        int off0 = ((b * 4096 + n0 * 64 + m) << 6) + tx * 4;
        int off1 = ((b * 4096 + (n0 + 1) * 64 + m) << 6) + tx * 4;
        *reinterpret_cast<float4*>(&out_arrow[off0]) = v0;
        *reinterpret_cast<float4*>(&out_arrow[off1]) = v1;
    }
}

// ============================================================================
// launch
// ============================================================================
extern "C" void kernel_launch(void* const* d_in, const int* in_sizes, int n_in,
                              void* d_out, int out_size)
{
    (void)in_sizes; (void)n_in; (void)out_size;
    const float* x     = (const float*)d_in[0];
    const float* w_src = (const float*)d_in[1];
    const float* b_src = (const float*)d_in[2];
    const float* w_dst = (const float*)d_in[3];
    const float* b_dst = (const float*)d_in[4];
    const float* w_arr = (const float*)d_in[5];
    const float* b_arr = (const float*)d_in[6];
    const float* w1    = (const float*)d_in[7];
    const float* b1    = (const float*)d_in[8];
    const float* w2    = (const float*)d_in[9];
    const float* b2    = (const float*)d_in[10];
    const float* w3    = (const float*)d_in[11];
    const float* b3    = (const float*)d_in[12];

    float* out_move  = (float*)d_out;                       // 64*64*64
    float* out_arrow = (float*)d_out + 64 * 64 * 64;        // 64*4096*64

    constexpr int SMEM_MAIN = 25792 * 4;   // 103,168 bytes dynamic smem
    cudaFuncSetAttribute(main_kernel, cudaFuncAttributeMaxDynamicSharedMemorySize,
                         SMEM_MAIN);

    proj_kernel<<<dim3(3, 64), 256>>>(x, w_src, b_src, w_dst, b_dst, w_arr, b_arr);
    w2t_kernel<<<128, 256>>>(w2);
    move_kernel<<<64, 256>>>(out_move);
    sp_kernel<<<dim3(2, 64, 2), 256>>>(w1, b1);
    g_kernel<<<64, 256>>>(w3, b3);
    main_kernel<<<dim3(32, 64), 256, SMEM_MAIN>>>(b2, out_arrow);
}

// round 6
// speedup vs baseline: 1.5279x; 1.4565x over previous
#include <cuda_runtime.h>
#include <cuda_fp16.h>
#include <cstdint>

// ---------------- problem constants ----------------
#define BB 64
#define CC 256
#define DD 128
#define NN 64
#define HH 256
#define SCALE_V 0.08838834764831845f   // 1/sqrt(128)

// ---------------- device scratch ----------------
__device__ float g_f[3][BB][DD][NN];     // f_src / f_dst / f_arr
__device__ float g_srcp[BB][NN][HH];     // src_p (+ b1 folded in)
__device__ float g_dstp[BB][NN][HH];     // dst_p
__device__ float g_cv[BB][NN];           // c[b][k] = sum_p b3[p]*f_arr[b][p][k]
// fp16 hi/lo images
__device__ __align__(16) __half g_w2h[32768];       // [o(128)][h(256)]
__device__ __align__(16) __half g_w2l[32768];
__device__ __align__(16) __half g_Gh[BB * 8192];    // [b][k_out(64)][o(128)]
__device__ __align__(16) __half g_Gl[BB * 8192];

// ---------------- helpers ----------------
__device__ __forceinline__ uint32_t smem_u32(const void* p) {
    uint32_t a;
    asm("{ .reg .u64 t; cvta.to.shared.u64 t, %1; cvt.u32.u64 %0, t; }" : "=r"(a) : "l"(p));
    return a;
}
__device__ __forceinline__ void ldmx4(uint32_t r[4], uint32_t addr) {
    asm volatile("ldmatrix.sync.aligned.m8n8.x4.shared.b16 {%0,%1,%2,%3}, [%4];"
                 : "=r"(r[0]), "=r"(r[1]), "=r"(r[2]), "=r"(r[3]) : "r"(addr));
}
__device__ __forceinline__ void mma16816(float c[4], const uint32_t a[4],
                                         uint32_t b0, uint32_t b1) {
    asm volatile(
        "mma.sync.aligned.m16n8k16.row.col.f32.f16.f16.f32 "
        "{%0,%1,%2,%3}, {%4,%5,%6,%7}, {%8,%9}, {%0,%1,%2,%3};"
        : "+f"(c[0]), "+f"(c[1]), "+f"(c[2]), "+f"(c[3])
        : "r"(a[0]), "r"(a[1]), "r"(a[2]), "r"(a[3]), "r"(b0), "r"(b1));
}
__device__ __forceinline__ void split2(float x, float y, uint32_t& hi, uint32_t& lo) {
    __half hx = __float2half_rn(x), hy = __float2half_rn(y);
    __half2 H = __halves2half2(hx, hy);
    __half2 L = __floats2half2_rn(x - __half2float(hx), y - __half2float(hy));
    hi = *reinterpret_cast<uint32_t*>(&H);
    lo = *reinterpret_cast<uint32_t*>(&L);
}

// ============================================================================
// Kernel P: projections  f[mat][b] = W_mat @ x[b] + bias_mat
// ============================================================================
__global__ void __launch_bounds__(256) proj_kernel(
    const float* __restrict__ x,
    const float* __restrict__ w_src, const float* __restrict__ b_src,
    const float* __restrict__ w_dst, const float* __restrict__ b_dst,
    const float* __restrict__ w_arr, const float* __restrict__ b_arr)
{
    const int mat = blockIdx.x;
    const int b   = blockIdx.y;
    const float* w    = (mat == 0) ? w_src : (mat == 1) ? w_dst : w_arr;
    const float* bias = (mat == 0) ? b_src : (mat == 1) ? b_dst : b_arr;

    __shared__ float Ws[32][DD + 4];
    __shared__ float Xs[32][NN + 4];

    const int tid = threadIdx.x;
    const int tx  = tid & 15;
    const int ty  = tid >> 4;

    float acc[8][4];
#pragma unroll
    for (int i = 0; i < 8; i++)
#pragma unroll
        for (int j = 0; j < 4; j++) acc[i][j] = 0.f;

    const float* xb = x + (size_t)b * CC * NN;

#pragma unroll 1
    for (int c0 = 0; c0 < CC; c0 += 32) {
#pragma unroll
        for (int j = 0; j < 16; j++) {
            int i = tid + 256 * j;
            int d = i >> 5, kk = i & 31;
            Ws[kk][d] = w[d * CC + c0 + kk];
        }
#pragma unroll
        for (int j = 0; j < 8; j++) {
            int i = tid + 256 * j;
            int kk = i >> 6, n = i & 63;
            Xs[kk][n] = xb[(c0 + kk) * NN + n];
        }
        __syncthreads();
#pragma unroll
        for (int kk = 0; kk < 32; kk++) {
            float a[8], xv[4];
#pragma unroll
            for (int i = 0; i < 8; i++) a[i] = Ws[kk][ty * 8 + i];
#pragma unroll
            for (int j = 0; j < 4; j++) xv[j] = Xs[kk][tx * 4 + j];
#pragma unroll
            for (int i = 0; i < 8; i++)
#pragma unroll
                for (int j = 0; j < 4; j++) acc[i][j] += a[i] * xv[j];
        }
        __syncthreads();
    }

    float* out = &g_f[mat][b][0][0];
#pragma unroll
    for (int i = 0; i < 8; i++) {
        int d = ty * 8 + i;
        float bv = bias[d];
        float4 v = make_float4(acc[i][0] + bv, acc[i][1] + bv,
                               acc[i][2] + bv, acc[i][3] + bv);
        *reinterpret_cast<float4*>(&out[d * NN + tx * 4]) = v;
    }
}

// ============================================================================
// Kernel M: move_logits
// ============================================================================
__global__ void __launch_bounds__(256) move_kernel(float* __restrict__ out_move)
{
    const int b = blockIdx.x;
    __shared__ float Ss[64][NN + 2];
    __shared__ float Dm[64][NN + 2];
    const int tid = threadIdx.x;
    const int tx  = tid & 15;
    const int ty  = tid >> 4;

    float acc[4][4];
#pragma unroll
    for (int i = 0; i < 4; i++)
#pragma unroll
        for (int j = 0; j < 4; j++) acc[i][j] = 0.f;

#pragma unroll 1
    for (int d0 = 0; d0 < DD; d0 += 64) {
#pragma unroll
        for (int j = 0; j < 16; j++) {
            int i = tid + 256 * j;
            int dd = i >> 6, n = i & 63;
            Ss[dd][n] = g_f[0][b][d0 + dd][n];
            Dm[dd][n] = g_f[1][b][d0 + dd][n];
        }
        __syncthreads();
#pragma unroll
        for (int dd = 0; dd < 64; dd++) {
            float sv[4], dv[4];
#pragma unroll
            for (int i = 0; i < 4; i++) sv[i] = Ss[dd][ty * 4 + i];
#pragma unroll
            for (int j = 0; j < 4; j++) dv[j] = Dm[dd][tx * 4 + j];
#pragma unroll
            for (int i = 0; i < 4; i++)
#pragma unroll
                for (int j = 0; j < 4; j++) acc[i][j] += sv[i] * dv[j];
        }
        __syncthreads();
    }
#pragma unroll
    for (int i = 0; i < 4; i++) {
        int n = ty * 4 + i;
        float4 v = make_float4(acc[i][0] * SCALE_V, acc[i][1] * SCALE_V,
                               acc[i][2] * SCALE_V, acc[i][3] * SCALE_V);
        *reinterpret_cast<float4*>(&out_move[(b * NN + n) * NN + tx * 4]) = v;
    }
}

// ============================================================================
// Kernel S: src_p / dst_p (h-split)
// ============================================================================
__global__ void __launch_bounds__(256) sp_kernel(
    const float* __restrict__ w1, const float* __restrict__ b1)
{
    const int type  = blockIdx.x;
    const int b     = blockIdx.y;
    const int hbase = blockIdx.z * 128;
    __shared__ float Ws[32][132];
    __shared__ float Fs[32][68];
    const int tid = threadIdx.x;
    const int tx  = tid & 15;
    const int ty  = tid >> 4;
    const int off = type * DD;

    float acc[4][8];
#pragma unroll
    for (int i = 0; i < 4; i++)
#pragma unroll
        for (int j = 0; j < 8; j++) acc[i][j] = 0.f;

#pragma unroll 1
    for (int d0 = 0; d0 < DD; d0 += 32) {
#pragma unroll
        for (int j = 0; j < 16; j++) {
            int i = tid + 256 * j;
            int h = i >> 5, kk = i & 31;
            Ws[kk][h] = w1[(hbase + h) * HH + off + d0 + kk];
        }
#pragma unroll
        for (int j = 0; j < 2; j++) {
            int i = tid + 256 * j;
            int kk = i >> 4, n4 = i & 15;
            *reinterpret_cast<float4*>(&Fs[kk][n4 * 4]) =
                *reinterpret_cast<const float4*>(&g_f[type][b][d0 + kk][n4 * 4]);
        }
        __syncthreads();
#pragma unroll
        for (int kk = 0; kk < 32; kk++) {
            float4 fv = *reinterpret_cast<const float4*>(&Fs[kk][ty * 4]);
            float4 w0 = *reinterpret_cast<const float4*>(&Ws[kk][tx * 8]);
            float4 w1v = *reinterpret_cast<const float4*>(&Ws[kk][tx * 8 + 4]);
            float f[4] = {fv.x, fv.y, fv.z, fv.w};
            float wv[8] = {w0.x, w0.y, w0.z, w0.w, w1v.x, w1v.y, w1v.z, w1v.w};
#pragma unroll
            for (int i = 0; i < 4; i++)
#pragma unroll
                for (int j = 0; j < 8; j++) acc[i][j] += f[i] * wv[j];
        }
        __syncthreads();
    }

    float* out = (type == 0) ? &g_srcp[b][0][0] : &g_dstp[b][0][0];
    float bv[8];
#pragma unroll
    for (int j = 0; j < 8; j++)
        bv[j] = (type == 0) ? b1[hbase + tx * 8 + j] : 0.f;
#pragma unroll
    for (int i = 0; i < 4; i++) {
        int n = ty * 4 + i;
        float4 v0 = make_float4(acc[i][0] + bv[0], acc[i][1] + bv[1],
                                acc[i][2] + bv[2], acc[i][3] + bv[3]);
        float4 v1 = make_float4(acc[i][4] + bv[4], acc[i][5] + bv[5],
                                acc[i][6] + bv[6], acc[i][7] + bv[7]);
        *reinterpret_cast<float4*>(&out[n * HH + hbase + tx * 8])     = v0;
        *reinterpret_cast<float4*>(&out[n * HH + hbase + tx * 8 + 4]) = v1;
    }
}

// ============================================================================
// Kernel G: fold w3/b3 into f_arr -> fp16 hi/lo images (transposed) + g_cv
//   G[b][o][k] = sum_p w3[p][o]*f_arr[b][p][k]; images stored [k][o].
// ============================================================================
__global__ void __launch_bounds__(256) g_kernel(
    const float* __restrict__ w3, const float* __restrict__ b3)
{
    const int b = blockIdx.x;
    __shared__ float W3s[32][DD + 4];
    __shared__ float Fs[32][NN + 4];
    __shared__ float b3s[32];
    const int tid = threadIdx.x;
    const int tx  = tid & 15;
    const int ty  = tid >> 4;

    float acc[8][4];
    float cacc[4] = {0.f, 0.f, 0.f, 0.f};
#pragma unroll
    for (int i = 0; i < 8; i++)
#pragma unroll
        for (int j = 0; j < 4; j++) acc[i][j] = 0.f;

#pragma unroll 1
    for (int p0 = 0; p0 < DD; p0 += 32) {
#pragma unroll
        for (int j = 0; j < 16; j++) {
            int i = tid + 256 * j;
            int kk = i >> 7, o = i & 127;
            W3s[kk][o] = w3[(p0 + kk) * DD + o];
        }
#pragma unroll
        for (int j = 0; j < 8; j++) {
            int i = tid + 256 * j;
            int kk = i >> 6, k = i & 63;
            Fs[kk][k] = g_f[2][b][p0 + kk][k];
        }
        if (tid < 32) b3s[tid] = b3[p0 + tid];
        __syncthreads();
#pragma unroll
        for (int kk = 0; kk < 32; kk++) {
            float wv[8], fv[4];
#pragma unroll
            for (int i = 0; i < 8; i++) wv[i] = W3s[kk][ty * 8 + i];
#pragma unroll
            for (int j = 0; j < 4; j++) fv[j] = Fs[kk][tx * 4 + j];
#pragma unroll
            for (int i = 0; i < 8; i++)
#pragma unroll
                for (int j = 0; j < 4; j++) acc[i][j] += wv[i] * fv[j];
            if (ty == 0) {
                float bvv = b3s[kk];
#pragma unroll
                for (int j = 0; j < 4; j++) cacc[j] += bvv * fv[j];
            }
        }
        __syncthreads();
    }
    // store transposed fp16 hi/lo: image[b][k][o] = acc(o, k)
#pragma unroll
    for (int i = 0; i < 8; i++) {
        int o = ty * 8 + i;
#pragma unroll
        for (int j = 0; j < 4; j++) {
            int k = tx * 4 + j;
            float v = acc[i][j];
            __half hv = __float2half_rn(v);
            __half lv = __float2half_rn(v - __half2float(hv));
            g_Gh[b * 8192 + k * 128 + o] = hv;
            g_Gl[b * 8192 + k * 128 + o] = lv;
        }
    }
    if (ty == 0) {
        float4 v = make_float4(cacc[0], cacc[1], cacc[2], cacc[3]);
        *reinterpret_cast<float4*>(&g_cv[b][tx * 4]) = v;
    }
}

// ============================================================================
// Prep: w2 (f32 [o][h]) -> fp16 hi/lo images (same layout)
// ============================================================================
__global__ void w2img_kernel(const float* __restrict__ w2)
{
    int idx = blockIdx.x * 256 + threadIdx.x;    // grid 128 -> 32768
    float v = w2[idx];
    __half hv = __float2half_rn(v);
    __half lv = __float2half_rn(v - __half2float(hv));
    g_w2h[idx] = hv;
    g_w2l[idx] = lv;
}

// ============================================================================
// Main (hot): warp-mma fp16 3-split fused  h1 -> h2 -> arrow
//   CTA (mt, b): 256 thr, 8 warps x 16 rows (row = lm*64+n, m = mt*2+lm)
//   GEMM1: A[128x256]=relu(srcp+dstp) @ w2[h][o] -> h2[128x128] (regs)
//   GEMM2: h2 @ G[o][k] -> arrow tile (in-register A chaining)
// Dynamic SMEM (bytes), all fp16 tiles rows of 64 halves (128B), XOR-swizzled:
//   [0,      131072) W2 tiles [s(2)][kc(4)][128 o][64 h]    (16KB each)
//   [131072, 163840) G  tiles [s(2)][kh(2)][64 k][64 o]     (8KB each)
//   [163840, 196608) A  tile hi/lo [128 r][64 h]            (16KB each)
// ============================================================================
__global__ void __launch_bounds__(256, 1) main_kernel(
    const float* __restrict__ b2, float* __restrict__ out_arrow)
{
    extern __shared__ char smc[];
    __shared__ float s_cv[64];
    __shared__ float s_b2[128];

    const uint32_t sb = smem_u32(smc);
    const int tid  = threadIdx.x;
    const int wid  = tid >> 5;
    const int lane = tid & 31;
    const int mt = blockIdx.x, b = blockIdx.y, m0 = mt * 2;

    const int G_BASE = 131072, A_HI = 163840, A_LO = 180224;

    // ---- prologue: copy fp16 images into swizzled smem tiles ----
    {
        // w2: 8192 16B-groups
        for (int i = tid; i < 8192; i += 256) {
            int s = i >> 12, rem = i & 4095;
            int o = rem >> 5, grp = rem & 31;
            int kc = grp >> 3, cgl = grp & 7;
            const uint4* src = reinterpret_cast<const uint4*>(
                (s ? g_w2l : g_w2h) + o * 256 + grp * 8);
            uint32_t dst = (uint32_t)((s * 4 + kc) * 16384 + o * 128 +
                                      ((cgl ^ (o & 7)) << 4));
            *reinterpret_cast<uint4*>(smc + dst) = *src;
        }
        // G: 2048 16B-groups
        for (int i = tid; i < 2048; i += 256) {
            int s = i >> 10, rem = i & 1023;
            int r = rem >> 4, grp = rem & 15;
            int kh = grp >> 3, cgl = grp & 7;
            const uint4* src = reinterpret_cast<const uint4*>(
                (s ? g_Gl : g_Gh) + b * 8192 + r * 128 + grp * 8);
            uint32_t dst = (uint32_t)(G_BASE + (s * 2 + kh) * 8192 + r * 128 +
                                      ((cgl ^ (r & 7)) << 4));
            *reinterpret_cast<uint4*>(smc + dst) = *src;
        }
        if (tid < 64)  s_cv[tid] = g_cv[b][tid];
        if (tid < 128) s_b2[tid] = b2[tid];
    }

    // ---- per-lane ldmatrix address components ----
    const int rowinm = lane & 7, mi = lane >> 3;
    const int rm0 = wid * 16;
    // A fragment lane address: row fixed
    const int a_r = rm0 + ((mi & 1) << 3) + rowinm;
    const uint32_t a_off = (uint32_t)(a_r * 128);
    const int a_sw = a_r & 7;
    const int a_kx = mi >> 1;       // k-block selector bit
    // B fragment lane address
    const int b_rl = ((mi >> 1) << 3) + rowinm;   // row within ntp*16 block
    const int b_sw = rowinm;
    const int b_kx = mi & 1;

    // ---- A generation setup ----
    const int gr = tid >> 1, gsub = tid & 1;
    const float* srow = &g_srcp[b][gr & 63][0];
    const float* drow = &g_dstp[b][m0 + (gr >> 6)][0];
    const int grsw = gr & 7;

    float c1[16][4];
#pragma unroll
    for (int i = 0; i < 16; i++)
#pragma unroll
        for (int j = 0; j < 4; j++) c1[i][j] = 0.f;

    // ================= GEMM1: 4 K-chunks of 64 =================
#pragma unroll 1
    for (int kc = 0; kc < 4; kc++) {
        // generate A chunk: relu(srcp + dstp), fp16 split, swizzled
#pragma unroll
        for (int q = 0; q < 4; q++) {
            int cg = gsub * 4 + q;
            int h = kc * 64 + cg * 8;
            float4 s0 = *(const float4*)(srow + h);
            float4 s1 = *(const float4*)(srow + h + 4);
            float4 d0 = *(const float4*)(drow + h);
            float4 d1 = *(const float4*)(drow + h + 4);
            float v[8] = { fmaxf(s0.x + d0.x, 0.f), fmaxf(s0.y + d0.y, 0.f),
                           fmaxf(s0.z + d0.z, 0.f), fmaxf(s0.w + d0.w, 0.f),
                           fmaxf(s1.x + d1.x, 0.f), fmaxf(s1.y + d1.y, 0.f),
                           fmaxf(s1.z + d1.z, 0.f), fmaxf(s1.w + d1.w, 0.f) };
            uint32_t hp[4], lp[4];
#pragma unroll
            for (int p = 0; p < 4; p++) split2(v[2 * p], v[2 * p + 1], hp[p], lp[p]);
            uint32_t off = (uint32_t)(gr * 128 + ((cg ^ grsw) << 4));
            *reinterpret_cast<uint4*>(smc + A_HI + off) = make_uint4(hp[0], hp[1], hp[2], hp[3]);
            *reinterpret_cast<uint4*>(smc + A_LO + off) = make_uint4(lp[0], lp[1], lp[2], lp[3]);
        }
        __syncthreads();

        // load A fragments for the 4 k-steps (hi & lo)
        uint32_t aH[4][4], aL[4][4];
#pragma unroll
        for (int ks = 0; ks < 4; ks++) {
            uint32_t co = (uint32_t)((((ks * 2 + a_kx) ^ a_sw)) << 4);
            ldmx4(aH[ks], sb + A_HI + a_off + co);
            ldmx4(aL[ks], sb + A_LO + a_off + co);
        }
        __syncthreads();

        const uint32_t wHi = sb + (uint32_t)(kc * 16384);
        const uint32_t wLo = sb + (uint32_t)(65536 + kc * 16384);
#pragma unroll
        for (int ks = 0; ks < 4; ks++) {
            uint32_t kco = (uint32_t)(((ks * 2 + b_kx) ^ b_sw) << 4);
#pragma unroll
            for (int ntp = 0; ntp < 8; ntp++) {
                uint32_t roff = (uint32_t)((ntp * 16 + b_rl) * 128) + kco;
                uint32_t bh[4], bl[4];
                ldmx4(bh, wHi + roff);
                mma16816(c1[2 * ntp],     aH[ks], bh[0], bh[1]);
                mma16816(c1[2 * ntp + 1], aH[ks], bh[2], bh[3]);
                mma16816(c1[2 * ntp],     aL[ks], bh[0], bh[1]);
                mma16816(c1[2 * ntp + 1], aL[ks], bh[2], bh[3]);
                ldmx4(bl, wLo + roff);
                mma16816(c1[2 * ntp],     aH[ks], bl[0], bl[1]);
                mma16816(c1[2 * ntp + 1], aH[ks], bl[2], bl[3]);
            }
        }
    }

    // ================= bias + relu + convert to GEMM2 A fragments ==========
    const int ccol = (lane & 3) * 2;
    uint32_t aH2[8][4], aL2[8][4];
#pragma unroll
    for (int ko = 0; ko < 8; ko++) {
#pragma unroll
        for (int hn = 0; hn < 2; hn++) {
            int nt = 2 * ko + hn;
            float bv0 = s_b2[nt * 8 + ccol];
            float bv1 = s_b2[nt * 8 + ccol + 1];
            float v00 = fmaxf(c1[nt][0] + bv0, 0.f);
            float v01 = fmaxf(c1[nt][1] + bv1, 0.f);
            float v10 = fmaxf(c1[nt][2] + bv0, 0.f);
            float v11 = fmaxf(c1[nt][3] + bv1, 0.f);
            split2(v00, v01, aH2[ko][hn * 2],     aL2[ko][hn * 2]);
            split2(v10, v11, aH2[ko][hn * 2 + 1], aL2[ko][hn * 2 + 1]);
        }
    }

    // ================= GEMM2: K=128 (o), N=64 (k_out) =======================
    float c2[8][4];
#pragma unroll
    for (int i = 0; i < 8; i++)
#pragma unroll
        for (int j = 0; j < 4; j++) c2[i][j] = 0.f;

#pragma unroll
    for (int ko = 0; ko < 8; ko++) {
        int kh = ko >> 2, ks = ko & 3;
        const uint32_t gHi = sb + (uint32_t)(G_BASE + kh * 8192);
        const uint32_t gLo = sb + (uint32_t)(G_BASE + 16384 + kh * 8192);
        uint32_t kco = (uint32_t)(((ks * 2 + b_kx) ^ b_sw) << 4);
#pragma unroll
        for (int ntp = 0; ntp < 4; ntp++) {
            uint32_t roff = (uint32_t)((ntp * 16 + b_rl) * 128) + kco;
            uint32_t bh[4], bl[4];
            ldmx4(bh, gHi + roff);
            mma16816(c2[2 * ntp],     aH2[ko], bh[0], bh[1]);
            mma16816(c2[2 * ntp + 1], aH2[ko], bh[2], bh[3]);
            mma16816(c2[2 * ntp],     aL2[ko], bh[0], bh[1]);
            mma16816(c2[2 * ntp + 1], aL2[ko], bh[2], bh[3]);
            ldmx4(bl, gLo + roff);
            mma16816(c2[2 * ntp],     aH2[ko], bl[0], bl[1]);
            mma16816(c2[2 * ntp + 1], aH2[ko], bl[2], bl[3]);
        }
    }

    // ================= epilogue =================
    {
        int r0 = rm0 + (lane >> 2);
        int r1 = r0 + 8;
        float* p0 = out_arrow + (((size_t)b * 4096 +
                                  (size_t)(r0 & 63) * 64 + m0 + (r0 >> 6)) << 6);
        float* p1 = out_arrow + (((size_t)b * 4096 +
                                  (size_t)(r1 & 63) * 64 + m0 + (r1 >> 6)) << 6);
#pragma unroll
        for (int nt = 0; nt < 8; nt++) {
            int k = nt * 8 + ccol;
            float cv0 = s_cv[k], cv1 = s_cv[k + 1];
            float2 v0 = make_float2((c2[nt][0] + cv0) * SCALE_V,
                                    (c2[nt][1] + cv1) * SCALE_V);
            float2 v1 = make_float2((c2[nt][2] + cv0) * SCALE_V,
                                    (c2[nt][3] + cv1) * SCALE_V);
            *reinterpret_cast<float2*>(p0 + k) = v0;
            *reinterpret_cast<float2*>(p1 + k) = v1;
        }
    }
}

// ============================================================================
// launch
// ============================================================================
extern "C" void kernel_launch(void* const* d_in, const int* in_sizes, int n_in,
                              void* d_out, int out_size)
{
    (void)in_sizes; (void)n_in; (void)out_size;
    const float* x     = (const float*)d_in[0];
    const float* w_src = (const float*)d_in[1];
    const float* b_src = (const float*)d_in[2];
    const float* w_dst = (const float*)d_in[3];
    const float* b_dst = (const float*)d_in[4];
    const float* w_arr = (const float*)d_in[5];
    const float* b_arr = (const float*)d_in[6];
    const float* w1    = (const float*)d_in[7];
    const float* b1    = (const float*)d_in[8];
    const float* w2    = (const float*)d_in[9];
    const float* b2    = (const float*)d_in[10];
    const float* w3    = (const float*)d_in[11];
    const float* b3    = (const float*)d_in[12];

    float* out_move  = (float*)d_out;                       // 64*64*64
    float* out_arrow = (float*)d_out + 64 * 64 * 64;        // 64*4096*64

    constexpr int SMEM_MAIN = 196608;
    cudaFuncSetAttribute(main_kernel, cudaFuncAttributeMaxDynamicSharedMemorySize,
                         SMEM_MAIN);

    proj_kernel<<<dim3(3, 64), 256>>>(x, w_src, b_src, w_dst, b_dst, w_arr, b_arr);
    w2img_kernel<<<128, 256>>>(w2);
    move_kernel<<<64, 256>>>(out_move);
    sp_kernel<<<dim3(2, 64, 2), 256>>>(w1, b1);
    g_kernel<<<64, 256>>>(w3, b3);
    main_kernel<<<dim3(32, 64), 256, SMEM_MAIN>>>(b2, out_arrow);
}

// round 7
// speedup vs baseline: 1.6313x; 1.0677x over previous
#include <cuda_runtime.h>
#include <cuda_fp16.h>
#include <cstdint>

// ---------------- problem constants ----------------
#define BB 64
#define CC 256
#define DD 128
#define NN 64
#define HH 256
#define SCALE_V 0.08838834764831845f   // 1/sqrt(128)

// ---------------- device scratch ----------------
__device__ float g_f[3][BB][DD][NN];     // f_src / f_dst / f_arr
__device__ float g_srcp[BB][NN][HH];     // src_p (+ b1 folded in)
__device__ float g_dstp[BB][NN][HH];     // dst_p
__device__ float g_cv[BB][NN];           // c[b][k] = sum_p b3[p]*f_arr[b][p][k]
// fp16 images
__device__ __align__(16) __half g_w2h[32768];       // [o(128)][h(256)]  (hi only)
__device__ __align__(16) __half g_Gh[BB * 8192];    // [b][k_out(64)][o(128)]
__device__ __align__(16) __half g_Gl[BB * 8192];

// ---------------- helpers ----------------
__device__ __forceinline__ uint32_t smem_u32(const void* p) {
    uint32_t a;
    asm("{ .reg .u64 t; cvta.to.shared.u64 t, %1; cvt.u32.u64 %0, t; }" : "=r"(a) : "l"(p));
    return a;
}
__device__ __forceinline__ void ldmx4(uint32_t r[4], uint32_t addr) {
    asm volatile("ldmatrix.sync.aligned.m8n8.x4.shared.b16 {%0,%1,%2,%3}, [%4];"
                 : "=r"(r[0]), "=r"(r[1]), "=r"(r[2]), "=r"(r[3]) : "r"(addr));
}
__device__ __forceinline__ void mma16816(float c[4], const uint32_t a[4],
                                         uint32_t b0, uint32_t b1) {
    asm volatile(
        "mma.sync.aligned.m16n8k16.row.col.f32.f16.f16.f32 "
        "{%0,%1,%2,%3}, {%4,%5,%6,%7}, {%8,%9}, {%0,%1,%2,%3};"
        : "+f"(c[0]), "+f"(c[1]), "+f"(c[2]), "+f"(c[3])
        : "r"(a[0]), "r"(a[1]), "r"(a[2]), "r"(a[3]), "r"(b0), "r"(b1));
}
__device__ __forceinline__ void split2(float x, float y, uint32_t& hi, uint32_t& lo) {
    __half hx = __float2half_rn(x), hy = __float2half_rn(y);
    __half2 H = __halves2half2(hx, hy);
    __half2 L = __floats2half2_rn(x - __half2float(hx), y - __half2float(hy));
    hi = *reinterpret_cast<uint32_t*>(&H);
    lo = *reinterpret_cast<uint32_t*>(&L);
}

// ============================================================================
// Kernel P: projections  f[mat][b] = W_mat @ x[b] + bias_mat
// ============================================================================
__global__ void __launch_bounds__(256) proj_kernel(
    const float* __restrict__ x,
    const float* __restrict__ w_src, const float* __restrict__ b_src,
    const float* __restrict__ w_dst, const float* __restrict__ b_dst,
    const float* __restrict__ w_arr, const float* __restrict__ b_arr)
{
    const int mat = blockIdx.x;
    const int b   = blockIdx.y;
    const float* w    = (mat == 0) ? w_src : (mat == 1) ? w_dst : w_arr;
    const float* bias = (mat == 0) ? b_src : (mat == 1) ? b_dst : b_arr;

    __shared__ float Ws[32][DD + 4];
    __shared__ float Xs[32][NN + 4];

    const int tid = threadIdx.x;
    const int tx  = tid & 15;
    const int ty  = tid >> 4;

    float acc[8][4];
#pragma unroll
    for (int i = 0; i < 8; i++)
#pragma unroll
        for (int j = 0; j < 4; j++) acc[i][j] = 0.f;

    const float* xb = x + (size_t)b * CC * NN;

#pragma unroll 1
    for (int c0 = 0; c0 < CC; c0 += 32) {
#pragma unroll
        for (int j = 0; j < 16; j++) {
            int i = tid + 256 * j;
            int d = i >> 5, kk = i & 31;
            Ws[kk][d] = w[d * CC + c0 + kk];
        }
#pragma unroll
        for (int j = 0; j < 8; j++) {
            int i = tid + 256 * j;
            int kk = i >> 6, n = i & 63;
            Xs[kk][n] = xb[(c0 + kk) * NN + n];
        }
        __syncthreads();
#pragma unroll
        for (int kk = 0; kk < 32; kk++) {
            float a[8], xv[4];
#pragma unroll
            for (int i = 0; i < 8; i++) a[i] = Ws[kk][ty * 8 + i];
#pragma unroll
            for (int j = 0; j < 4; j++) xv[j] = Xs[kk][tx * 4 + j];
#pragma unroll
            for (int i = 0; i < 8; i++)
#pragma unroll
                for (int j = 0; j < 4; j++) acc[i][j] += a[i] * xv[j];
        }
        __syncthreads();
    }

    float* out = &g_f[mat][b][0][0];
#pragma unroll
    for (int i = 0; i < 8; i++) {
        int d = ty * 8 + i;
        float bv = bias[d];
        float4 v = make_float4(acc[i][0] + bv, acc[i][1] + bv,
                               acc[i][2] + bv, acc[i][3] + bv);
        *reinterpret_cast<float4*>(&out[d * NN + tx * 4]) = v;
    }
}

// ============================================================================
// Prep: w2 (f32 [o][h]) -> fp16 hi image
// ============================================================================
__global__ void w2img_kernel(const float* __restrict__ w2)
{
    int idx = blockIdx.x * 256 + threadIdx.x;    // grid 128 -> 32768
    g_w2h[idx] = __float2half_rn(w2[idx]);
}

// ============================================================================
// Stage-2 merged kernel: sp (0..255) | g (256..319) | move (320..383)
// ============================================================================
__device__ void sp_body(float* sh, int bid, const float* __restrict__ w1,
                        const float* __restrict__ b1)
{
    const int type  = bid & 1;
    const int b     = (bid >> 1) & 63;
    const int hbase = (bid >> 7) * 128;
    float (*Ws)[132] = reinterpret_cast<float(*)[132]>(sh);          // 32x132
    float (*Fs)[68]  = reinterpret_cast<float(*)[68]>(sh + 4224);    // 32x68
    const int tid = threadIdx.x;
    const int tx  = tid & 15;
    const int ty  = tid >> 4;
    const int off = type * DD;

    float acc[4][8];
#pragma unroll
    for (int i = 0; i < 4; i++)
#pragma unroll
        for (int j = 0; j < 8; j++) acc[i][j] = 0.f;

#pragma unroll 1
    for (int d0 = 0; d0 < DD; d0 += 32) {
#pragma unroll
        for (int j = 0; j < 16; j++) {
            int i = tid + 256 * j;
            int h = i >> 5, kk = i & 31;
            Ws[kk][h] = w1[(hbase + h) * HH + off + d0 + kk];
        }
#pragma unroll
        for (int j = 0; j < 2; j++) {
            int i = tid + 256 * j;
            int kk = i >> 4, n4 = i & 15;
            *reinterpret_cast<float4*>(&Fs[kk][n4 * 4]) =
                *reinterpret_cast<const float4*>(&g_f[type][b][d0 + kk][n4 * 4]);
        }
        __syncthreads();
#pragma unroll
        for (int kk = 0; kk < 32; kk++) {
            float4 fv = *reinterpret_cast<const float4*>(&Fs[kk][ty * 4]);
            float4 w0 = *reinterpret_cast<const float4*>(&Ws[kk][tx * 8]);
            float4 w1v = *reinterpret_cast<const float4*>(&Ws[kk][tx * 8 + 4]);
            float f[4] = {fv.x, fv.y, fv.z, fv.w};
            float wv[8] = {w0.x, w0.y, w0.z, w0.w, w1v.x, w1v.y, w1v.z, w1v.w};
#pragma unroll
            for (int i = 0; i < 4; i++)
#pragma unroll
                for (int j = 0; j < 8; j++) acc[i][j] += f[i] * wv[j];
        }
        __syncthreads();
    }

    float* out = (type == 0) ? &g_srcp[b][0][0] : &g_dstp[b][0][0];
    float bv[8];
#pragma unroll
    for (int j = 0; j < 8; j++)
        bv[j] = (type == 0) ? b1[hbase + tx * 8 + j] : 0.f;
#pragma unroll
    for (int i = 0; i < 4; i++) {
        int n = ty * 4 + i;
        float4 v0 = make_float4(acc[i][0] + bv[0], acc[i][1] + bv[1],
                                acc[i][2] + bv[2], acc[i][3] + bv[3]);
        float4 v1 = make_float4(acc[i][4] + bv[4], acc[i][5] + bv[5],
                                acc[i][6] + bv[6], acc[i][7] + bv[7]);
        *reinterpret_cast<float4*>(&out[n * HH + hbase + tx * 8])     = v0;
        *reinterpret_cast<float4*>(&out[n * HH + hbase + tx * 8 + 4]) = v1;
    }
}

__device__ void g_body(float* sh, int b, const float* __restrict__ w3,
                       const float* __restrict__ b3)
{
    float (*W3s)[132] = reinterpret_cast<float(*)[132]>(sh);          // 32x132
    float (*Fs)[68]   = reinterpret_cast<float(*)[68]>(sh + 4224);    // 32x68
    float* b3s        = sh + 4224 + 2176;                             // 32
    const int tid = threadIdx.x;
    const int tx  = tid & 15;
    const int ty  = tid >> 4;

    float acc[8][4];
    float cacc[4] = {0.f, 0.f, 0.f, 0.f};
#pragma unroll
    for (int i = 0; i < 8; i++)
#pragma unroll
        for (int j = 0; j < 4; j++) acc[i][j] = 0.f;

#pragma unroll 1
    for (int p0 = 0; p0 < DD; p0 += 32) {
#pragma unroll
        for (int j = 0; j < 16; j++) {
            int i = tid + 256 * j;
            int kk = i >> 7, o = i & 127;
            W3s[kk][o] = w3[(p0 + kk) * DD + o];
        }
#pragma unroll
        for (int j = 0; j < 8; j++) {
            int i = tid + 256 * j;
            int kk = i >> 6, k = i & 63;
            Fs[kk][k] = g_f[2][b][p0 + kk][k];
        }
        if (tid < 32) b3s[tid] = b3[p0 + tid];
        __syncthreads();
#pragma unroll
        for (int kk = 0; kk < 32; kk++) {
            float wv[8], fv[4];
#pragma unroll
            for (int i = 0; i < 8; i++) wv[i] = W3s[kk][ty * 8 + i];
#pragma unroll
            for (int j = 0; j < 4; j++) fv[j] = Fs[kk][tx * 4 + j];
#pragma unroll
            for (int i = 0; i < 8; i++)
#pragma unroll
                for (int j = 0; j < 4; j++) acc[i][j] += wv[i] * fv[j];
            if (ty == 0) {
                float bvv = b3s[kk];
#pragma unroll
                for (int j = 0; j < 4; j++) cacc[j] += bvv * fv[j];
            }
        }
        __syncthreads();
    }
#pragma unroll
    for (int i = 0; i < 8; i++) {
        int o = ty * 8 + i;
#pragma unroll
        for (int j = 0; j < 4; j++) {
            int k = tx * 4 + j;
            float v = acc[i][j];
            __half hv = __float2half_rn(v);
            __half lv = __float2half_rn(v - __half2float(hv));
            g_Gh[b * 8192 + k * 128 + o] = hv;
            g_Gl[b * 8192 + k * 128 + o] = lv;
        }
    }
    if (ty == 0) {
        float4 v = make_float4(cacc[0], cacc[1], cacc[2], cacc[3]);
        *reinterpret_cast<float4*>(&g_cv[b][tx * 4]) = v;
    }
}

__device__ void move_body(float* sh, int b, float* __restrict__ out_move)
{
    float (*Ss)[66] = reinterpret_cast<float(*)[66]>(sh);             // 64x66
    float (*Dm)[66] = reinterpret_cast<float(*)[66]>(sh + 4224);      // 64x66
    const int tid = threadIdx.x;
    const int tx  = tid & 15;
    const int ty  = tid >> 4;

    float acc[4][4];
#pragma unroll
    for (int i = 0; i < 4; i++)
#pragma unroll
        for (int j = 0; j < 4; j++) acc[i][j] = 0.f;

#pragma unroll 1
    for (int d0 = 0; d0 < DD; d0 += 64) {
#pragma unroll
        for (int j = 0; j < 16; j++) {
            int i = tid + 256 * j;
            int dd = i >> 6, n = i & 63;
            Ss[dd][n] = g_f[0][b][d0 + dd][n];
            Dm[dd][n] = g_f[1][b][d0 + dd][n];
        }
        __syncthreads();
#pragma unroll
        for (int dd = 0; dd < 64; dd++) {
            float sv[4], dv[4];
#pragma unroll
            for (int i = 0; i < 4; i++) sv[i] = Ss[dd][ty * 4 + i];
#pragma unroll
            for (int j = 0; j < 4; j++) dv[j] = Dm[dd][tx * 4 + j];
#pragma unroll
            for (int i = 0; i < 4; i++)
#pragma unroll
                for (int j = 0; j < 4; j++) acc[i][j] += sv[i] * dv[j];
        }
        __syncthreads();
    }
#pragma unroll
    for (int i = 0; i < 4; i++) {
        int n = ty * 4 + i;
        float4 v = make_float4(acc[i][0] * SCALE_V, acc[i][1] * SCALE_V,
                               acc[i][2] * SCALE_V, acc[i][3] * SCALE_V);
        *reinterpret_cast<float4*>(&out_move[(b * NN + n) * NN + tx * 4]) = v;
    }
}

__global__ void __launch_bounds__(256) stage2_kernel(
    const float* __restrict__ w1, const float* __restrict__ b1,
    const float* __restrict__ w3, const float* __restrict__ b3,
    float* __restrict__ out_move)
{
    __shared__ float sh[8448];   // 33 KB, reused by all three bodies
    const int bid = blockIdx.x;
    if (bid < 256)      sp_body(sh, bid, w1, b1);
    else if (bid < 320) g_body(sh, bid - 256, w3, b3);
    else                move_body(sh, bid - 320, out_move);
}

// ============================================================================
// Main (hot): warp-mma fp16 fused  h1 -> h2 -> arrow
//   GEMM1: (Ah+Al) @ w2_fp16 (2-product); GEMM2: 3-product hi/lo.
// Dynamic SMEM (bytes), fp16 tile rows of 64 halves (128B), XOR-swizzled:
//   [0,      65536)  W2 hi tiles [kc(4)][128 o][64 h]
//   [65536,  98304)  G tiles [s(2)][kh(2)][64 k][64 o]
//   [98304, 131072)  A tile hi/lo [128 r][64 h]
// ============================================================================
__global__ void __launch_bounds__(256, 1) main_kernel(
    const float* __restrict__ b2, float* __restrict__ out_arrow)
{
    extern __shared__ char smc[];
    __shared__ float s_cv[64];
    __shared__ float s_b2[128];

    const uint32_t sb = smem_u32(smc);
    const int tid  = threadIdx.x;
    const int wid  = tid >> 5;
    const int lane = tid & 31;
    const int mt = blockIdx.x, b = blockIdx.y, m0 = mt * 2;

    const int G_BASE = 65536, A_HI = 98304, A_LO = 114688;

    // ---- prologue: copy fp16 images into swizzled smem tiles ----
    {
        // w2 hi: 4096 16B-groups
        for (int i = tid; i < 4096; i += 256) {
            int o = i >> 5, grp = i & 31;
            int kc = grp >> 3, cgl = grp & 7;
            const uint4* src = reinterpret_cast<const uint4*>(g_w2h + o * 256 + grp * 8);
            uint32_t dst = (uint32_t)(kc * 16384 + o * 128 + ((cgl ^ (o & 7)) << 4));
            *reinterpret_cast<uint4*>(smc + dst) = *src;
        }
        // G hi/lo: 2048 16B-groups
        for (int i = tid; i < 2048; i += 256) {
            int s = i >> 10, rem = i & 1023;
            int r = rem >> 4, grp = rem & 15;
            int kh = grp >> 3, cgl = grp & 7;
            const uint4* src = reinterpret_cast<const uint4*>(
                (s ? g_Gl : g_Gh) + b * 8192 + r * 128 + grp * 8);
            uint32_t dst = (uint32_t)(G_BASE + (s * 2 + kh) * 8192 + r * 128 +
                                      ((cgl ^ (r & 7)) << 4));
            *reinterpret_cast<uint4*>(smc + dst) = *src;
        }
        if (tid < 64)  s_cv[tid] = g_cv[b][tid];
        if (tid < 128) s_b2[tid] = b2[tid];
    }

    // ---- per-lane ldmatrix address components ----
    const int rowinm = lane & 7, mi = lane >> 3;
    const int rm0 = wid * 16;
    const int a_r = rm0 + ((mi & 1) << 3) + rowinm;
    const uint32_t a_off = (uint32_t)(a_r * 128);
    const int a_sw = a_r & 7;
    const int a_kx = mi >> 1;
    const int b_rl = ((mi >> 1) << 3) + rowinm;
    const int b_sw = rowinm;
    const int b_kx = mi & 1;

    // ---- A generation setup ----
    const int gr = tid >> 1, gsub = tid & 1;
    const float* srow = &g_srcp[b][gr & 63][0];
    const float* drow = &g_dstp[b][m0 + (gr >> 6)][0];
    const int grsw = gr & 7;

    float c1[16][4];
#pragma unroll
    for (int i = 0; i < 16; i++)
#pragma unroll
        for (int j = 0; j < 4; j++) c1[i][j] = 0.f;

    // ================= GEMM1: 4 K-chunks of 64, 2-product =================
#pragma unroll 1
    for (int kc = 0; kc < 4; kc++) {
#pragma unroll
        for (int q = 0; q < 4; q++) {
            int cg = gsub * 4 + q;
            int h = kc * 64 + cg * 8;
            float4 s0 = *(const float4*)(srow + h);
            float4 s1 = *(const float4*)(srow + h + 4);
            float4 d0 = *(const float4*)(drow + h);
            float4 d1 = *(const float4*)(drow + h + 4);
            float v[8] = { fmaxf(s0.x + d0.x, 0.f), fmaxf(s0.y + d0.y, 0.f),
                           fmaxf(s0.z + d0.z, 0.f), fmaxf(s0.w + d0.w, 0.f),
                           fmaxf(s1.x + d1.x, 0.f), fmaxf(s1.y + d1.y, 0.f),
                           fmaxf(s1.z + d1.z, 0.f), fmaxf(s1.w + d1.w, 0.f) };
            uint32_t hp[4], lp[4];
#pragma unroll
            for (int p = 0; p < 4; p++) split2(v[2 * p], v[2 * p + 1], hp[p], lp[p]);
            uint32_t off = (uint32_t)(gr * 128 + ((cg ^ grsw) << 4));
            *reinterpret_cast<uint4*>(smc + A_HI + off) = make_uint4(hp[0], hp[1], hp[2], hp[3]);
            *reinterpret_cast<uint4*>(smc + A_LO + off) = make_uint4(lp[0], lp[1], lp[2], lp[3]);
        }
        __syncthreads();

        uint32_t aH[4][4], aL[4][4];
#pragma unroll
        for (int ks = 0; ks < 4; ks++) {
            uint32_t co = (uint32_t)((((ks * 2 + a_kx) ^ a_sw)) << 4);
            ldmx4(aH[ks], sb + A_HI + a_off + co);
            ldmx4(aL[ks], sb + A_LO + a_off + co);
        }
        __syncthreads();

        const uint32_t wHi = sb + (uint32_t)(kc * 16384);
#pragma unroll
        for (int ks = 0; ks < 4; ks++) {
            uint32_t kco = (uint32_t)(((ks * 2 + b_kx) ^ b_sw) << 4);
#pragma unroll
            for (int ntp = 0; ntp < 8; ntp++) {
                uint32_t roff = (uint32_t)((ntp * 16 + b_rl) * 128) + kco;
                uint32_t bh[4];
                ldmx4(bh, wHi + roff);
                mma16816(c1[2 * ntp],     aH[ks], bh[0], bh[1]);
                mma16816(c1[2 * ntp + 1], aH[ks], bh[2], bh[3]);
                mma16816(c1[2 * ntp],     aL[ks], bh[0], bh[1]);
                mma16816(c1[2 * ntp + 1], aL[ks], bh[2], bh[3]);
            }
        }
    }

    // ================= bias + relu + convert to GEMM2 A fragments ==========
    const int ccol = (lane & 3) * 2;
    uint32_t aH2[8][4], aL2[8][4];
#pragma unroll
    for (int ko = 0; ko < 8; ko++) {
#pragma unroll
        for (int hn = 0; hn < 2; hn++) {
            int nt = 2 * ko + hn;
            float bv0 = s_b2[nt * 8 + ccol];
            float bv1 = s_b2[nt * 8 + ccol + 1];
            float v00 = fmaxf(c1[nt][0] + bv0, 0.f);
            float v01 = fmaxf(c1[nt][1] + bv1, 0.f);
            float v10 = fmaxf(c1[nt][2] + bv0, 0.f);
            float v11 = fmaxf(c1[nt][3] + bv1, 0.f);
            split2(v00, v01, aH2[ko][hn * 2],     aL2[ko][hn * 2]);
            split2(v10, v11, aH2[ko][hn * 2 + 1], aL2[ko][hn * 2 + 1]);
        }
    }

    // ================= GEMM2: K=128 (o), N=64 (k_out), 3-product ============
    float c2[8][4];
#pragma unroll
    for (int i = 0; i < 8; i++)
#pragma unroll
        for (int j = 0; j < 4; j++) c2[i][j] = 0.f;

#pragma unroll
    for (int ko = 0; ko < 8; ko++) {
        int kh = ko >> 2, ks = ko & 3;
        const uint32_t gHi = sb + (uint32_t)(G_BASE + kh * 8192);
        const uint32_t gLo = sb + (uint32_t)(G_BASE + 16384 + kh * 8192);
        uint32_t kco = (uint32_t)(((ks * 2 + b_kx) ^ b_sw) << 4);
#pragma unroll
        for (int ntp = 0; ntp < 4; ntp++) {
            uint32_t roff = (uint32_t)((ntp * 16 + b_rl) * 128) + kco;
            uint32_t bh[4], bl[4];
            ldmx4(bh, gHi + roff);
            mma16816(c2[2 * ntp],     aH2[ko], bh[0], bh[1]);
            mma16816(c2[2 * ntp + 1], aH2[ko], bh[2], bh[3]);
            mma16816(c2[2 * ntp],     aL2[ko], bh[0], bh[1]);
            mma16816(c2[2 * ntp + 1], aL2[ko], bh[2], bh[3]);
            ldmx4(bl, gLo + roff);
            mma16816(c2[2 * ntp],     aH2[ko], bl[0], bl[1]);
            mma16816(c2[2 * ntp + 1], aH2[ko], bl[2], bl[3]);
        }
    }

    // ================= epilogue =================
    {
        int r0 = rm0 + (lane >> 2);
        int r1 = r0 + 8;
        float* p0 = out_arrow + (((size_t)b * 4096 +
                                  (size_t)(r0 & 63) * 64 + m0 + (r0 >> 6)) << 6);
        float* p1 = out_arrow + (((size_t)b * 4096 +
                                  (size_t)(r1 & 63) * 64 + m0 + (r1 >> 6)) << 6);
#pragma unroll
        for (int nt = 0; nt < 8; nt++) {
            int k = nt * 8 + ccol;
            float cv0 = s_cv[k], cv1 = s_cv[k + 1];
            float2 v0 = make_float2((c2[nt][0] + cv0) * SCALE_V,
                                    (c2[nt][1] + cv1) * SCALE_V);
            float2 v1 = make_float2((c2[nt][2] + cv0) * SCALE_V,
                                    (c2[nt][3] + cv1) * SCALE_V);
            *reinterpret_cast<float2*>(p0 + k) = v0;
            *reinterpret_cast<float2*>(p1 + k) = v1;
        }
    }
}

// ============================================================================
// launch
// ============================================================================
extern "C" void kernel_launch(void* const* d_in, const int* in_sizes, int n_in,
                              void* d_out, int out_size)
{
    (void)in_sizes; (void)n_in; (void)out_size;
    const float* x     = (const float*)d_in[0];
    const float* w_src = (const float*)d_in[1];
    const float* b_src = (const float*)d_in[2];
    const float* w_dst = (const float*)d_in[3];
    const float* b_dst = (const float*)d_in[4];
    const float* w_arr = (const float*)d_in[5];
    const float* b_arr = (const float*)d_in[6];
    const float* w1    = (const float*)d_in[7];
    const float* b1    = (const float*)d_in[8];
    const float* w2    = (const float*)d_in[9];
    const float* b2    = (const float*)d_in[10];
    const float* w3    = (const float*)d_in[11];
    const float* b3    = (const float*)d_in[12];

    float* out_move  = (float*)d_out;                       // 64*64*64
    float* out_arrow = (float*)d_out + 64 * 64 * 64;        // 64*4096*64

    constexpr int SMEM_MAIN = 131072;
    cudaFuncSetAttribute(main_kernel, cudaFuncAttributeMaxDynamicSharedMemorySize,
                         SMEM_MAIN);

    proj_kernel<<<dim3(3, 64), 256>>>(x, w_src, b_src, w_dst, b_dst, w_arr, b_arr);
    w2img_kernel<<<128, 256>>>(w2);
    stage2_kernel<<<384, 256>>>(w1, b1, w3, b3, out_move);
    main_kernel<<<dim3(32, 64), 256, SMEM_MAIN>>>(b2, out_arrow);
}

// round 8
// speedup vs baseline: 2.4729x; 1.5159x over previous
#include <cuda_runtime.h>
#include <cuda_fp16.h>
#include <cstdint>

// ---------------- problem constants ----------------
#define BB 64
#define CC 256
#define DD 128
#define NN 64
#define HH 256
#define SCALE_V 0.08838834764831845f   // 1/sqrt(128)

// ---------------- device scratch ----------------
__device__ float g_f[3][BB][DD][NN];     // f_src / f_dst / f_arr
__device__ float g_srcp[BB][NN][HH];     // src_p (+ b1 folded in)
__device__ float g_dstp[BB][NN][HH];     // dst_p
__device__ float g_cv[BB][NN];           // c[b][k] = sum_p b3[p]*f_arr[b][p][k]
// fp16 images
__device__ __align__(16) __half g_w2h[32768];       // [o(128)][h(256)]
__device__ __align__(16) __half g_Gh[BB * 8192];    // [b][k_out(64)][o(128)]

// ---------------- helpers ----------------
__device__ __forceinline__ uint32_t smem_u32(const void* p) {
    uint32_t a;
    asm("{ .reg .u64 t; cvta.to.shared.u64 t, %1; cvt.u32.u64 %0, t; }" : "=r"(a) : "l"(p));
    return a;
}
__device__ __forceinline__ void ldmx4(uint32_t r[4], uint32_t addr) {
    asm volatile("ldmatrix.sync.aligned.m8n8.x4.shared.b16 {%0,%1,%2,%3}, [%4];"
                 : "=r"(r[0]), "=r"(r[1]), "=r"(r[2]), "=r"(r[3]) : "r"(addr));
}
__device__ __forceinline__ void mma16816(float c[4], const uint32_t a[4],
                                         uint32_t b0, uint32_t b1) {
    asm volatile(
        "mma.sync.aligned.m16n8k16.row.col.f32.f16.f16.f32 "
        "{%0,%1,%2,%3}, {%4,%5,%6,%7}, {%8,%9}, {%0,%1,%2,%3};"
        : "+f"(c[0]), "+f"(c[1]), "+f"(c[2]), "+f"(c[3])
        : "r"(a[0]), "r"(a[1]), "r"(a[2]), "r"(a[3]), "r"(b0), "r"(b1));
}
__device__ __forceinline__ uint32_t packh2(float x, float y) {
    __half2 h = __floats2half2_rn(x, y);
    return *reinterpret_cast<uint32_t*>(&h);
}

// ============================================================================
// Kernel P: projections  f[mat][b] = W_mat @ x[b] + bias_mat
// ============================================================================
__global__ void __launch_bounds__(256) proj_kernel(
    const float* __restrict__ x,
    const float* __restrict__ w_src, const float* __restrict__ b_src,
    const float* __restrict__ w_dst, const float* __restrict__ b_dst,
    const float* __restrict__ w_arr, const float* __restrict__ b_arr)
{
    const int mat = blockIdx.x;
    const int b   = blockIdx.y;
    const float* w    = (mat == 0) ? w_src : (mat == 1) ? w_dst : w_arr;
    const float* bias = (mat == 0) ? b_src : (mat == 1) ? b_dst : b_arr;

    __shared__ float Ws[32][DD + 4];
    __shared__ float Xs[32][NN + 4];

    const int tid = threadIdx.x;
    const int tx  = tid & 15;
    const int ty  = tid >> 4;

    float acc[8][4];
#pragma unroll
    for (int i = 0; i < 8; i++)
#pragma unroll
        for (int j = 0; j < 4; j++) acc[i][j] = 0.f;

    const float* xb = x + (size_t)b * CC * NN;

#pragma unroll 1
    for (int c0 = 0; c0 < CC; c0 += 32) {
#pragma unroll
        for (int j = 0; j < 16; j++) {
            int i = tid + 256 * j;
            int d = i >> 5, kk = i & 31;
            Ws[kk][d] = w[d * CC + c0 + kk];
        }
#pragma unroll
        for (int j = 0; j < 8; j++) {
            int i = tid + 256 * j;
            int kk = i >> 6, n = i & 63;
            Xs[kk][n] = xb[(c0 + kk) * NN + n];
        }
        __syncthreads();
#pragma unroll
        for (int kk = 0; kk < 32; kk++) {
            float a[8], xv[4];
#pragma unroll
            for (int i = 0; i < 8; i++) a[i] = Ws[kk][ty * 8 + i];
#pragma unroll
            for (int j = 0; j < 4; j++) xv[j] = Xs[kk][tx * 4 + j];
#pragma unroll
            for (int i = 0; i < 8; i++)
#pragma unroll
                for (int j = 0; j < 4; j++) acc[i][j] += a[i] * xv[j];
        }
        __syncthreads();
    }

    float* out = &g_f[mat][b][0][0];
#pragma unroll
    for (int i = 0; i < 8; i++) {
        int d = ty * 8 + i;
        float bv = bias[d];
        float4 v = make_float4(acc[i][0] + bv, acc[i][1] + bv,
                               acc[i][2] + bv, acc[i][3] + bv);
        *reinterpret_cast<float4*>(&out[d * NN + tx * 4]) = v;
    }
}

// ============================================================================
// Prep: w2 (f32 [o][h]) -> fp16 image
// ============================================================================
__global__ void w2img_kernel(const float* __restrict__ w2)
{
    int idx = blockIdx.x * 256 + threadIdx.x;    // grid 128 -> 32768
    g_w2h[idx] = __float2half_rn(w2[idx]);
}

// ============================================================================
// Stage-2 merged kernel: sp (0..255) | g (256..319) | move (320..383)
// ============================================================================
__device__ void sp_body(float* sh, int bid, const float* __restrict__ w1,
                        const float* __restrict__ b1)
{
    const int type  = bid & 1;
    const int b     = (bid >> 1) & 63;
    const int hbase = (bid >> 7) * 128;
    float (*Ws)[132] = reinterpret_cast<float(*)[132]>(sh);          // 32x132
    float (*Fs)[68]  = reinterpret_cast<float(*)[68]>(sh + 4224);    // 32x68
    const int tid = threadIdx.x;
    const int tx  = tid & 15;
    const int ty  = tid >> 4;
    const int off = type * DD;

    float acc[4][8];
#pragma unroll
    for (int i = 0; i < 4; i++)
#pragma unroll
        for (int j = 0; j < 8; j++) acc[i][j] = 0.f;

#pragma unroll 1
    for (int d0 = 0; d0 < DD; d0 += 32) {
#pragma unroll
        for (int j = 0; j < 16; j++) {
            int i = tid + 256 * j;
            int h = i >> 5, kk = i & 31;
            Ws[kk][h] = w1[(hbase + h) * HH + off + d0 + kk];
        }
#pragma unroll
        for (int j = 0; j < 2; j++) {
            int i = tid + 256 * j;
            int kk = i >> 4, n4 = i & 15;
            *reinterpret_cast<float4*>(&Fs[kk][n4 * 4]) =
                *reinterpret_cast<const float4*>(&g_f[type][b][d0 + kk][n4 * 4]);
        }
        __syncthreads();
#pragma unroll
        for (int kk = 0; kk < 32; kk++) {
            float4 fv = *reinterpret_cast<const float4*>(&Fs[kk][ty * 4]);
            float4 w0 = *reinterpret_cast<const float4*>(&Ws[kk][tx * 8]);
            float4 w1v = *reinterpret_cast<const float4*>(&Ws[kk][tx * 8 + 4]);
            float f[4] = {fv.x, fv.y, fv.z, fv.w};
            float wv[8] = {w0.x, w0.y, w0.z, w0.w, w1v.x, w1v.y, w1v.z, w1v.w};
#pragma unroll
            for (int i = 0; i < 4; i++)
#pragma unroll
                for (int j = 0; j < 8; j++) acc[i][j] += f[i] * wv[j];
        }
        __syncthreads();
    }

    float* out = (type == 0) ? &g_srcp[b][0][0] : &g_dstp[b][0][0];
    float bv[8];
#pragma unroll
    for (int j = 0; j < 8; j++)
        bv[j] = (type == 0) ? b1[hbase + tx * 8 + j] : 0.f;
#pragma unroll
    for (int i = 0; i < 4; i++) {
        int n = ty * 4 + i;
        float4 v0 = make_float4(acc[i][0] + bv[0], acc[i][1] + bv[1],
                                acc[i][2] + bv[2], acc[i][3] + bv[3]);
        float4 v1 = make_float4(acc[i][4] + bv[4], acc[i][5] + bv[5],
                                acc[i][6] + bv[6], acc[i][7] + bv[7]);
        *reinterpret_cast<float4*>(&out[n * HH + hbase + tx * 8])     = v0;
        *reinterpret_cast<float4*>(&out[n * HH + hbase + tx * 8 + 4]) = v1;
    }
}

__device__ void g_body(float* sh, int b, const float* __restrict__ w3,
                       const float* __restrict__ b3)
{
    float (*W3s)[132] = reinterpret_cast<float(*)[132]>(sh);          // 32x132
    float (*Fs)[68]   = reinterpret_cast<float(*)[68]>(sh + 4224);    // 32x68
    float* b3s        = sh + 4224 + 2176;                             // 32
    const int tid = threadIdx.x;
    const int tx  = tid & 15;
    const int ty  = tid >> 4;

    float acc[8][4];
    float cacc[4] = {0.f, 0.f, 0.f, 0.f};
#pragma unroll
    for (int i = 0; i < 8; i++)
#pragma unroll
        for (int j = 0; j < 4; j++) acc[i][j] = 0.f;

#pragma unroll 1
    for (int p0 = 0; p0 < DD; p0 += 32) {
#pragma unroll
        for (int j = 0; j < 16; j++) {
            int i = tid + 256 * j;
            int kk = i >> 7, o = i & 127;
            W3s[kk][o] = w3[(p0 + kk) * DD + o];
        }
#pragma unroll
        for (int j = 0; j < 8; j++) {
            int i = tid + 256 * j;
            int kk = i >> 6, k = i & 63;
            Fs[kk][k] = g_f[2][b][p0 + kk][k];
        }
        if (tid < 32) b3s[tid] = b3[p0 + tid];
        __syncthreads();
#pragma unroll
        for (int kk = 0; kk < 32; kk++) {
            float wv[8], fv[4];
#pragma unroll
            for (int i = 0; i < 8; i++) wv[i] = W3s[kk][ty * 8 + i];
#pragma unroll
            for (int j = 0; j < 4; j++) fv[j] = Fs[kk][tx * 4 + j];
#pragma unroll
            for (int i = 0; i < 8; i++)
#pragma unroll
                for (int j = 0; j < 4; j++) acc[i][j] += wv[i] * fv[j];
            if (ty == 0) {
                float bvv = b3s[kk];
#pragma unroll
                for (int j = 0; j < 4; j++) cacc[j] += bvv * fv[j];
            }
        }
        __syncthreads();
    }
#pragma unroll
    for (int i = 0; i < 8; i++) {
        int o = ty * 8 + i;
#pragma unroll
        for (int j = 0; j < 4; j++) {
            int k = tx * 4 + j;
            g_Gh[b * 8192 + k * 128 + o] = __float2half_rn(acc[i][j]);
        }
    }
    if (ty == 0) {
        float4 v = make_float4(cacc[0], cacc[1], cacc[2], cacc[3]);
        *reinterpret_cast<float4*>(&g_cv[b][tx * 4]) = v;
    }
}

__device__ void move_body(float* sh, int b, float* __restrict__ out_move)
{
    float (*Ss)[66] = reinterpret_cast<float(*)[66]>(sh);             // 64x66
    float (*Dm)[66] = reinterpret_cast<float(*)[66]>(sh + 4224);      // 64x66
    const int tid = threadIdx.x;
    const int tx  = tid & 15;
    const int ty  = tid >> 4;

    float acc[4][4];
#pragma unroll
    for (int i = 0; i < 4; i++)
#pragma unroll
        for (int j = 0; j < 4; j++) acc[i][j] = 0.f;

#pragma unroll 1
    for (int d0 = 0; d0 < DD; d0 += 64) {
#pragma unroll
        for (int j = 0; j < 16; j++) {
            int i = tid + 256 * j;
            int dd = i >> 6, n = i & 63;
            Ss[dd][n] = g_f[0][b][d0 + dd][n];
            Dm[dd][n] = g_f[1][b][d0 + dd][n];
        }
        __syncthreads();
#pragma unroll
        for (int dd = 0; dd < 64; dd++) {
            float sv[4], dv[4];
#pragma unroll
            for (int i = 0; i < 4; i++) sv[i] = Ss[dd][ty * 4 + i];
#pragma unroll
            for (int j = 0; j < 4; j++) dv[j] = Dm[dd][tx * 4 + j];
#pragma unroll
            for (int i = 0; i < 4; i++)
#pragma unroll
                for (int j = 0; j < 4; j++) acc[i][j] += sv[i] * dv[j];
        }
        __syncthreads();
    }
#pragma unroll
    for (int i = 0; i < 4; i++) {
        int n = ty * 4 + i;
        float4 v = make_float4(acc[i][0] * SCALE_V, acc[i][1] * SCALE_V,
                               acc[i][2] * SCALE_V, acc[i][3] * SCALE_V);
        *reinterpret_cast<float4*>(&out_move[(b * NN + n) * NN + tx * 4]) = v;
    }
}

__global__ void __launch_bounds__(256) stage2_kernel(
    const float* __restrict__ w1, const float* __restrict__ b1,
    const float* __restrict__ w3, const float* __restrict__ b3,
    float* __restrict__ out_move)
{
    __shared__ float sh[8448];   // 33 KB, reused by all three bodies
    const int bid = blockIdx.x;
    if (bid < 256)      sp_body(sh, bid, w1, b1);
    else if (bid < 320) g_body(sh, bid - 256, w3, b3);
    else                move_body(sh, bid - 320, out_move);
}

// ============================================================================
// Main (hot): warp-mma fp16 single-product fused  h1 -> h2 -> arrow
//   CTA (mt, b): 256 thr, 8 warps x 16 rows. 2 CTAs/SM.
// Dynamic SMEM (bytes), fp16 tile rows of 64 halves (128B), XOR-swizzled:
//   [0,     65536)  W2 tiles [kc(4)][128 o][64 h]
//   [65536, 81920)  G tiles [kh(2)][64 k][64 o]
//   [81920, 98304)  A tile [128 r][64 h]
// ============================================================================
__global__ void __launch_bounds__(256, 2) main_kernel(
    const float* __restrict__ b2, float* __restrict__ out_arrow)
{
    extern __shared__ char smc[];
    __shared__ float s_cv[64];
    __shared__ float s_b2[128];

    const uint32_t sb = smem_u32(smc);
    const int tid  = threadIdx.x;
    const int wid  = tid >> 5;
    const int lane = tid & 31;
    const int mt = blockIdx.x, b = blockIdx.y, m0 = mt * 2;

    const int G_BASE = 65536, A_BASE = 81920;

    // ---- prologue: copy fp16 images into swizzled smem tiles ----
    {
        // w2: 4096 16B-groups
        for (int i = tid; i < 4096; i += 256) {
            int o = i >> 5, grp = i & 31;
            int kc = grp >> 3, cgl = grp & 7;
            const uint4* src = reinterpret_cast<const uint4*>(g_w2h + o * 256 + grp * 8);
            uint32_t dst = (uint32_t)(kc * 16384 + o * 128 + ((cgl ^ (o & 7)) << 4));
            *reinterpret_cast<uint4*>(smc + dst) = *src;
        }
        // G: 1024 16B-groups
        for (int i = tid; i < 1024; i += 256) {
            int r = i >> 4, grp = i & 15;
            int kh = grp >> 3, cgl = grp & 7;
            const uint4* src = reinterpret_cast<const uint4*>(
                g_Gh + b * 8192 + r * 128 + grp * 8);
            uint32_t dst = (uint32_t)(G_BASE + kh * 8192 + r * 128 +
                                      ((cgl ^ (r & 7)) << 4));
            *reinterpret_cast<uint4*>(smc + dst) = *src;
        }
        if (tid < 64)  s_cv[tid] = g_cv[b][tid];
        if (tid < 128) s_b2[tid] = b2[tid];
    }

    // ---- per-lane ldmatrix address components ----
    const int rowinm = lane & 7, mi = lane >> 3;
    const int rm0 = wid * 16;
    const int a_r = rm0 + ((mi & 1) << 3) + rowinm;
    const uint32_t a_off = (uint32_t)(a_r * 128);
    const int a_sw = a_r & 7;
    const int a_kx = mi >> 1;
    const int b_rl = ((mi >> 1) << 3) + rowinm;
    const int b_sw = rowinm;
    const int b_kx = mi & 1;

    // ---- A generation setup ----
    const int gr = tid >> 1, gsub = tid & 1;
    const float* srow = &g_srcp[b][gr & 63][0];
    const float* drow = &g_dstp[b][m0 + (gr >> 6)][0];
    const int grsw = gr & 7;

    float c1[16][4];
#pragma unroll
    for (int i = 0; i < 16; i++)
#pragma unroll
        for (int j = 0; j < 4; j++) c1[i][j] = 0.f;

    // ================= GEMM1: 4 K-chunks of 64, single product ==============
#pragma unroll 1
    for (int kc = 0; kc < 4; kc++) {
        // generate A chunk: relu(srcp + dstp) -> fp16, swizzled
#pragma unroll
        for (int q = 0; q < 4; q++) {
            int cg = gsub * 4 + q;
            int h = kc * 64 + cg * 8;
            float4 s0 = *(const float4*)(srow + h);
            float4 s1 = *(const float4*)(srow + h + 4);
            float4 d0 = *(const float4*)(drow + h);
            float4 d1 = *(const float4*)(drow + h + 4);
            uint32_t hp[4];
            hp[0] = packh2(fmaxf(s0.x + d0.x, 0.f), fmaxf(s0.y + d0.y, 0.f));
            hp[1] = packh2(fmaxf(s0.z + d0.z, 0.f), fmaxf(s0.w + d0.w, 0.f));
            hp[2] = packh2(fmaxf(s1.x + d1.x, 0.f), fmaxf(s1.y + d1.y, 0.f));
            hp[3] = packh2(fmaxf(s1.z + d1.z, 0.f), fmaxf(s1.w + d1.w, 0.f));
            uint32_t off = (uint32_t)(gr * 128 + ((cg ^ grsw) << 4));
            *reinterpret_cast<uint4*>(smc + A_BASE + off) =
                make_uint4(hp[0], hp[1], hp[2], hp[3]);
        }
        __syncthreads();

        uint32_t aH[4][4];
#pragma unroll
        for (int ks = 0; ks < 4; ks++) {
            uint32_t co = (uint32_t)((((ks * 2 + a_kx) ^ a_sw)) << 4);
            ldmx4(aH[ks], sb + A_BASE + a_off + co);
        }
        __syncthreads();

        const uint32_t wHi = sb + (uint32_t)(kc * 16384);
#pragma unroll
        for (int ks = 0; ks < 4; ks++) {
            uint32_t kco = (uint32_t)(((ks * 2 + b_kx) ^ b_sw) << 4);
#pragma unroll
            for (int ng = 0; ng < 2; ng++) {
                // load 4 B fragments (distinct ntp), then 8 independent MMAs
                uint32_t bh[4][4];
#pragma unroll
                for (int q = 0; q < 4; q++) {
                    int ntp = ng * 4 + q;
                    ldmx4(bh[q], wHi + (uint32_t)((ntp * 16 + b_rl) * 128) + kco);
                }
#pragma unroll
                for (int q = 0; q < 4; q++) {
                    int nt = (ng * 4 + q) * 2;
                    mma16816(c1[nt],     aH[ks], bh[q][0], bh[q][1]);
                    mma16816(c1[nt + 1], aH[ks], bh[q][2], bh[q][3]);
                }
            }
        }
    }

    // ================= bias + relu + convert to GEMM2 A fragments ==========
    const int ccol = (lane & 3) * 2;
    uint32_t aH2[8][4];
#pragma unroll
    for (int ko = 0; ko < 8; ko++) {
#pragma unroll
        for (int hn = 0; hn < 2; hn++) {
            int nt = 2 * ko + hn;
            float bv0 = s_b2[nt * 8 + ccol];
            float bv1 = s_b2[nt * 8 + ccol + 1];
            aH2[ko][hn * 2]     = packh2(fmaxf(c1[nt][0] + bv0, 0.f),
                                         fmaxf(c1[nt][1] + bv1, 0.f));
            aH2[ko][hn * 2 + 1] = packh2(fmaxf(c1[nt][2] + bv0, 0.f),
                                         fmaxf(c1[nt][3] + bv1, 0.f));
        }
    }

    // ================= GEMM2: K=128 (o), N=64 (k_out), single product =======
    float c2[8][4];
#pragma unroll
    for (int i = 0; i < 8; i++)
#pragma unroll
        for (int j = 0; j < 4; j++) c2[i][j] = 0.f;

#pragma unroll
    for (int ko = 0; ko < 8; ko++) {
        int kh = ko >> 2, ks = ko & 3;
        const uint32_t gHi = sb + (uint32_t)(G_BASE + kh * 8192);
        uint32_t kco = (uint32_t)(((ks * 2 + b_kx) ^ b_sw) << 4);
        uint32_t bh[4][4];
#pragma unroll
        for (int ntp = 0; ntp < 4; ntp++)
            ldmx4(bh[ntp], gHi + (uint32_t)((ntp * 16 + b_rl) * 128) + kco);
#pragma unroll
        for (int ntp = 0; ntp < 4; ntp++) {
            mma16816(c2[2 * ntp],     aH2[ko], bh[ntp][0], bh[ntp][1]);
            mma16816(c2[2 * ntp + 1], aH2[ko], bh[ntp][2], bh[ntp][3]);
        }
    }

    // ================= epilogue =================
    {
        int r0 = rm0 + (lane >> 2);
        int r1 = r0 + 8;
        float* p0 = out_arrow + (((size_t)b * 4096 +
                                  (size_t)(r0 & 63) * 64 + m0 + (r0 >> 6)) << 6);
        float* p1 = out_arrow + (((size_t)b * 4096 +
                                  (size_t)(r1 & 63) * 64 + m0 + (r1 >> 6)) << 6);
#pragma unroll
        for (int nt = 0; nt < 8; nt++) {
            int k = nt * 8 + ccol;
            float cv0 = s_cv[k], cv1 = s_cv[k + 1];
            float2 v0 = make_float2((c2[nt][0] + cv0) * SCALE_V,
                                    (c2[nt][1] + cv1) * SCALE_V);
            float2 v1 = make_float2((c2[nt][2] + cv0) * SCALE_V,
                                    (c2[nt][3] + cv1) * SCALE_V);
            *reinterpret_cast<float2*>(p0 + k) = v0;
            *reinterpret_cast<float2*>(p1 + k) = v1;
        }
    }
}

// ============================================================================
// launch
// ============================================================================
extern "C" void kernel_launch(void* const* d_in, const int* in_sizes, int n_in,
                              void* d_out, int out_size)
{
    (void)in_sizes; (void)n_in; (void)out_size;
    const float* x     = (const float*)d_in[0];
    const float* w_src = (const float*)d_in[1];
    const float* b_src = (const float*)d_in[2];
    const float* w_dst = (const float*)d_in[3];
    const float* b_dst = (const float*)d_in[4];
    const float* w_arr = (const float*)d_in[5];
    const float* b_arr = (const float*)d_in[6];
    const float* w1    = (const float*)d_in[7];
    const float* b1    = (const float*)d_in[8];
    const float* w2    = (const float*)d_in[9];
    const float* b2    = (const float*)d_in[10];
    const float* w3    = (const float*)d_in[11];
    const float* b3    = (const float*)d_in[12];

    float* out_move  = (float*)d_out;                       // 64*64*64
    float* out_arrow = (float*)d_out + 64 * 64 * 64;        // 64*4096*64

    constexpr int SMEM_MAIN = 98304;
    cudaFuncSetAttribute(main_kernel, cudaFuncAttributeMaxDynamicSharedMemorySize,
                         SMEM_MAIN);

    proj_kernel<<<dim3(3, 64), 256>>>(x, w_src, b_src, w_dst, b_dst, w_arr, b_arr);
    w2img_kernel<<<128, 256>>>(w2);
    stage2_kernel<<<384, 256>>>(w1, b1, w3, b3, out_move);
    main_kernel<<<dim3(32, 64), 256, SMEM_MAIN>>>(b2, out_arrow);
}

// round 9
// speedup vs baseline: 3.4652x; 1.4013x over previous
#include <cuda_runtime.h>
#include <cuda_fp16.h>
#include <cstdint>

// ---------------- problem constants ----------------
#define BB 64
#define CC 256
#define DD 128
#define NN 64
#define HH 256
#define SCALE_V 0.08838834764831845f   // 1/sqrt(128)

// ---------------- device scratch ----------------
__device__ float g_f[3][BB][DD][NN];     // f_src / f_dst / f_arr
__device__ float g_srcp[BB][NN][HH];     // src_p (+ b1 folded in)
__device__ float g_dstp[BB][NN][HH];     // dst_p
__device__ float g_cv[BB][NN];           // c[b][k] = sum_p b3[p]*f_arr[b][p][k]
// fp16 images
__device__ __align__(16) __half g_w2h[32768];       // [o(128)][h(256)]
__device__ __align__(16) __half g_Gh[BB * 8192];    // [b][k_out(64)][o(128)]

// ---------------- helpers ----------------
__device__ __forceinline__ uint32_t smem_u32(const void* p) {
    uint32_t a;
    asm("{ .reg .u64 t; cvta.to.shared.u64 t, %1; cvt.u32.u64 %0, t; }" : "=r"(a) : "l"(p));
    return a;
}
__device__ __forceinline__ void ldmx4(uint32_t r[4], uint32_t addr) {
    asm volatile("ldmatrix.sync.aligned.m8n8.x4.shared.b16 {%0,%1,%2,%3}, [%4];"
                 : "=r"(r[0]), "=r"(r[1]), "=r"(r[2]), "=r"(r[3]) : "r"(addr));
}
__device__ __forceinline__ void mma16816(float c[4], const uint32_t a[4],
                                         uint32_t b0, uint32_t b1) {
    asm volatile(
        "mma.sync.aligned.m16n8k16.row.col.f32.f16.f16.f32 "
        "{%0,%1,%2,%3}, {%4,%5,%6,%7}, {%8,%9}, {%0,%1,%2,%3};"
        : "+f"(c[0]), "+f"(c[1]), "+f"(c[2]), "+f"(c[3])
        : "r"(a[0]), "r"(a[1]), "r"(a[2]), "r"(a[3]), "r"(b0), "r"(b1));
}
__device__ __forceinline__ uint32_t packh2(float x, float y) {
    __half2 h = __floats2half2_rn(x, y);
    return *reinterpret_cast<uint32_t*>(&h);
}

// ============================================================================
// Kernel P: projections  f[mat][b] = W_mat @ x[b] + bias_mat
// ============================================================================
__global__ void __launch_bounds__(256) proj_kernel(
    const float* __restrict__ x,
    const float* __restrict__ w_src, const float* __restrict__ b_src,
    const float* __restrict__ w_dst, const float* __restrict__ b_dst,
    const float* __restrict__ w_arr, const float* __restrict__ b_arr)
{
    const int mat = blockIdx.x;
    const int b   = blockIdx.y;
    const float* w    = (mat == 0) ? w_src : (mat == 1) ? w_dst : w_arr;
    const float* bias = (mat == 0) ? b_src : (mat == 1) ? b_dst : b_arr;

    __shared__ float Ws[32][DD + 4];
    __shared__ float Xs[32][NN + 4];

    const int tid = threadIdx.x;
    const int tx  = tid & 15;
    const int ty  = tid >> 4;

    float acc[8][4];
#pragma unroll
    for (int i = 0; i < 8; i++)
#pragma unroll
        for (int j = 0; j < 4; j++) acc[i][j] = 0.f;

    const float* xb = x + (size_t)b * CC * NN;

#pragma unroll 1
    for (int c0 = 0; c0 < CC; c0 += 32) {
#pragma unroll
        for (int j = 0; j < 16; j++) {
            int i = tid + 256 * j;
            int d = i >> 5, kk = i & 31;
            Ws[kk][d] = w[d * CC + c0 + kk];
        }
#pragma unroll
        for (int j = 0; j < 8; j++) {
            int i = tid + 256 * j;
            int kk = i >> 6, n = i & 63;
            Xs[kk][n] = xb[(c0 + kk) * NN + n];
        }
        __syncthreads();
#pragma unroll
        for (int kk = 0; kk < 32; kk++) {
            float a[8], xv[4];
#pragma unroll
            for (int i = 0; i < 8; i++) a[i] = Ws[kk][ty * 8 + i];
#pragma unroll
            for (int j = 0; j < 4; j++) xv[j] = Xs[kk][tx * 4 + j];
#pragma unroll
            for (int i = 0; i < 8; i++)
#pragma unroll
                for (int j = 0; j < 4; j++) acc[i][j] += a[i] * xv[j];
        }
        __syncthreads();
    }

    float* out = &g_f[mat][b][0][0];
#pragma unroll
    for (int i = 0; i < 8; i++) {
        int d = ty * 8 + i;
        float bv = bias[d];
        float4 v = make_float4(acc[i][0] + bv, acc[i][1] + bv,
                               acc[i][2] + bv, acc[i][3] + bv);
        *reinterpret_cast<float4*>(&out[d * NN + tx * 4]) = v;
    }
}

// ============================================================================
// Prep: w2 (f32 [o][h]) -> fp16 image
// ============================================================================
__global__ void w2img_kernel(const float* __restrict__ w2)
{
    int idx = blockIdx.x * 256 + threadIdx.x;    // grid 128 -> 32768
    g_w2h[idx] = __float2half_rn(w2[idx]);
}

// ============================================================================
// Stage-2 merged kernel: sp (0..255) | g (256..319) | move (320..383)
// ============================================================================
__device__ void sp_body(float* sh, int bid, const float* __restrict__ w1,
                        const float* __restrict__ b1)
{
    const int type  = bid & 1;
    const int b     = (bid >> 1) & 63;
    const int hbase = (bid >> 7) * 128;
    float (*Ws)[132] = reinterpret_cast<float(*)[132]>(sh);          // 32x132
    float (*Fs)[68]  = reinterpret_cast<float(*)[68]>(sh + 4224);    // 32x68
    const int tid = threadIdx.x;
    const int tx  = tid & 15;
    const int ty  = tid >> 4;
    const int off = type * DD;

    float acc[4][8];
#pragma unroll
    for (int i = 0; i < 4; i++)
#pragma unroll
        for (int j = 0; j < 8; j++) acc[i][j] = 0.f;

#pragma unroll 1
    for (int d0 = 0; d0 < DD; d0 += 32) {
#pragma unroll
        for (int j = 0; j < 16; j++) {
            int i = tid + 256 * j;
            int h = i >> 5, kk = i & 31;
            Ws[kk][h] = w1[(hbase + h) * HH + off + d0 + kk];
        }
#pragma unroll
        for (int j = 0; j < 2; j++) {
            int i = tid + 256 * j;
            int kk = i >> 4, n4 = i & 15;
            *reinterpret_cast<float4*>(&Fs[kk][n4 * 4]) =
                *reinterpret_cast<const float4*>(&g_f[type][b][d0 + kk][n4 * 4]);
        }
        __syncthreads();
#pragma unroll
        for (int kk = 0; kk < 32; kk++) {
            float4 fv = *reinterpret_cast<const float4*>(&Fs[kk][ty * 4]);
            float4 w0 = *reinterpret_cast<const float4*>(&Ws[kk][tx * 8]);
            float4 w1v = *reinterpret_cast<const float4*>(&Ws[kk][tx * 8 + 4]);
            float f[4] = {fv.x, fv.y, fv.z, fv.w};
            float wv[8] = {w0.x, w0.y, w0.z, w0.w, w1v.x, w1v.y, w1v.z, w1v.w};
#pragma unroll
            for (int i = 0; i < 4; i++)
#pragma unroll
                for (int j = 0; j < 8; j++) acc[i][j] += f[i] * wv[j];
        }
        __syncthreads();
    }

    float* out = (type == 0) ? &g_srcp[b][0][0] : &g_dstp[b][0][0];
    float bv[8];
#pragma unroll
    for (int j = 0; j < 8; j++)
        bv[j] = (type == 0) ? b1[hbase + tx * 8 + j] : 0.f;
#pragma unroll
    for (int i = 0; i < 4; i++) {
        int n = ty * 4 + i;
        float4 v0 = make_float4(acc[i][0] + bv[0], acc[i][1] + bv[1],
                                acc[i][2] + bv[2], acc[i][3] + bv[3]);
        float4 v1 = make_float4(acc[i][4] + bv[4], acc[i][5] + bv[5],
                                acc[i][6] + bv[6], acc[i][7] + bv[7]);
        *reinterpret_cast<float4*>(&out[n * HH + hbase + tx * 8])     = v0;
        *reinterpret_cast<float4*>(&out[n * HH + hbase + tx * 8 + 4]) = v1;
    }
}

__device__ void g_body(float* sh, int b, const float* __restrict__ w3,
                       const float* __restrict__ b3)
{
    float (*W3s)[132] = reinterpret_cast<float(*)[132]>(sh);          // 32x132
    float (*Fs)[68]   = reinterpret_cast<float(*)[68]>(sh + 4224);    // 32x68
    float* b3s        = sh + 4224 + 2176;                             // 32
    const int tid = threadIdx.x;
    const int tx  = tid & 15;
    const int ty  = tid >> 4;

    float acc[8][4];
    float cacc[4] = {0.f, 0.f, 0.f, 0.f};
#pragma unroll
    for (int i = 0; i < 8; i++)
#pragma unroll
        for (int j = 0; j < 4; j++) acc[i][j] = 0.f;

#pragma unroll 1
    for (int p0 = 0; p0 < DD; p0 += 32) {
#pragma unroll
        for (int j = 0; j < 16; j++) {
            int i = tid + 256 * j;
            int kk = i >> 7, o = i & 127;
            W3s[kk][o] = w3[(p0 + kk) * DD + o];
        }
#pragma unroll
        for (int j = 0; j < 8; j++) {
            int i = tid + 256 * j;
            int kk = i >> 6, k = i & 63;
            Fs[kk][k] = g_f[2][b][p0 + kk][k];
        }
        if (tid < 32) b3s[tid] = b3[p0 + tid];
        __syncthreads();
#pragma unroll
        for (int kk = 0; kk < 32; kk++) {
            float wv[8], fv[4];
#pragma unroll
            for (int i = 0; i < 8; i++) wv[i] = W3s[kk][ty * 8 + i];
#pragma unroll
            for (int j = 0; j < 4; j++) fv[j] = Fs[kk][tx * 4 + j];
#pragma unroll
            for (int i = 0; i < 8; i++)
#pragma unroll
                for (int j = 0; j < 4; j++) acc[i][j] += wv[i] * fv[j];
            if (ty == 0) {
                float bvv = b3s[kk];
#pragma unroll
                for (int j = 0; j < 4; j++) cacc[j] += bvv * fv[j];
            }
        }
        __syncthreads();
    }
#pragma unroll
    for (int i = 0; i < 8; i++) {
        int o = ty * 8 + i;
#pragma unroll
        for (int j = 0; j < 4; j++) {
            int k = tx * 4 + j;
            g_Gh[b * 8192 + k * 128 + o] = __float2half_rn(acc[i][j]);
        }
    }
    if (ty == 0) {
        float4 v = make_float4(cacc[0], cacc[1], cacc[2], cacc[3]);
        *reinterpret_cast<float4*>(&g_cv[b][tx * 4]) = v;
    }
}

__device__ void move_body(float* sh, int b, float* __restrict__ out_move)
{
    float (*Ss)[66] = reinterpret_cast<float(*)[66]>(sh);             // 64x66
    float (*Dm)[66] = reinterpret_cast<float(*)[66]>(sh + 4224);      // 64x66
    const int tid = threadIdx.x;
    const int tx  = tid & 15;
    const int ty  = tid >> 4;

    float acc[4][4];
#pragma unroll
    for (int i = 0; i < 4; i++)
#pragma unroll
        for (int j = 0; j < 4; j++) acc[i][j] = 0.f;

#pragma unroll 1
    for (int d0 = 0; d0 < DD; d0 += 64) {
#pragma unroll
        for (int j = 0; j < 16; j++) {
            int i = tid + 256 * j;
            int dd = i >> 6, n = i & 63;
            Ss[dd][n] = g_f[0][b][d0 + dd][n];
            Dm[dd][n] = g_f[1][b][d0 + dd][n];
        }
        __syncthreads();
#pragma unroll
        for (int dd = 0; dd < 64; dd++) {
            float sv[4], dv[4];
#pragma unroll
            for (int i = 0; i < 4; i++) sv[i] = Ss[dd][ty * 4 + i];
#pragma unroll
            for (int j = 0; j < 4; j++) dv[j] = Dm[dd][tx * 4 + j];
#pragma unroll
            for (int i = 0; i < 4; i++)
#pragma unroll
                for (int j = 0; j < 4; j++) acc[i][j] += sv[i] * dv[j];
        }
        __syncthreads();
    }
#pragma unroll
    for (int i = 0; i < 4; i++) {
        int n = ty * 4 + i;
        float4 v = make_float4(acc[i][0] * SCALE_V, acc[i][1] * SCALE_V,
                               acc[i][2] * SCALE_V, acc[i][3] * SCALE_V);
        *reinterpret_cast<float4*>(&out_move[(b * NN + n) * NN + tx * 4]) = v;
    }
}

__global__ void __launch_bounds__(256) stage2_kernel(
    const float* __restrict__ w1, const float* __restrict__ b1,
    const float* __restrict__ w3, const float* __restrict__ b3,
    float* __restrict__ out_move)
{
    __shared__ float sh[8448];   // 33 KB, reused by all three bodies
    const int bid = blockIdx.x;
    if (bid < 256)      sp_body(sh, bid, w1, b1);
    else if (bid < 320) g_body(sh, bid - 256, w3, b3);
    else                move_body(sh, bid - 320, out_move);
}

// ============================================================================
// Main (hot): warp-mma fp16 single-product fused  h1 -> h2 -> arrow
//   CTA (mt, b): 256 thr, 8 warps x 16 rows. 2 CTAs/SM.
// Dynamic SMEM (bytes), fp16 tile rows of 64 halves (128B), XOR-swizzled:
//   [0,     65536)  W2 tiles [kc(4)][128 o][64 h]
//   [65536, 81920)  G tiles [kh(2)][64 k][64 o]
//   [81920, 98304)  A tile [128 r][64 h]
// ============================================================================
__global__ void __launch_bounds__(256, 2) main_kernel(
    const float* __restrict__ b2, float* __restrict__ out_arrow)
{
    extern __shared__ char smc[];
    __shared__ float s_cv[64];
    __shared__ float s_b2[128];

    const uint32_t sb = smem_u32(smc);
    const int tid  = threadIdx.x;
    const int wid  = tid >> 5;
    const int lane = tid & 31;
    const int mt = blockIdx.x, b = blockIdx.y, m0 = mt * 2;

    const int G_BASE = 65536, A_BASE = 81920;

    // ---- prologue: copy fp16 images into swizzled smem tiles ----
    {
        // w2: 4096 16B-groups
        for (int i = tid; i < 4096; i += 256) {
            int o = i >> 5, grp = i & 31;
            int kc = grp >> 3, cgl = grp & 7;
            const uint4* src = reinterpret_cast<const uint4*>(g_w2h + o * 256 + grp * 8);
            uint32_t dst = (uint32_t)(kc * 16384 + o * 128 + ((cgl ^ (o & 7)) << 4));
            *reinterpret_cast<uint4*>(smc + dst) = *src;
        }
        // G: 1024 16B-groups
        for (int i = tid; i < 1024; i += 256) {
            int r = i >> 4, grp = i & 15;
            int kh = grp >> 3, cgl = grp & 7;
            const uint4* src = reinterpret_cast<const uint4*>(
                g_Gh + b * 8192 + r * 128 + grp * 8);
            uint32_t dst = (uint32_t)(G_BASE + kh * 8192 + r * 128 +
                                      ((cgl ^ (r & 7)) << 4));
            *reinterpret_cast<uint4*>(smc + dst) = *src;
        }
        if (tid < 64)  s_cv[tid] = g_cv[b][tid];
        if (tid < 128) s_b2[tid] = b2[tid];
    }

    // ---- per-lane ldmatrix address components ----
    const int rowinm = lane & 7, mi = lane >> 3;
    const int rm0 = wid * 16;
    const int a_r = rm0 + ((mi & 1) << 3) + rowinm;
    const uint32_t a_off = (uint32_t)(a_r * 128);
    const int a_sw = a_r & 7;
    const int a_kx = mi >> 1;
    const int b_rl = ((mi >> 1) << 3) + rowinm;
    const int b_sw = rowinm;
    const int b_kx = mi & 1;

    // ---- coalesced A-generation indexing ----
    // idx = tid + 256*j ; row = idx>>4 (0..127), h4 = (idx&15)*4 (0..60)
    const int ag_h4   = (tid & 15) * 4;
    const int ag_cgsh = ((ag_h4 >> 3) << 4) + ((ag_h4 & 4) << 1);  // group + sub-offset

    float c1[16][4];
#pragma unroll
    for (int i = 0; i < 16; i++)
#pragma unroll
        for (int j = 0; j < 4; j++) c1[i][j] = 0.f;

    // ================= GEMM1: 4 K-chunks of 64, single product ==============
#pragma unroll 1
    for (int kc = 0; kc < 4; kc++) {
        // generate A chunk: relu(srcp + dstp) -> fp16, swizzled, COALESCED
#pragma unroll
        for (int j = 0; j < 8; j++) {
            int row = (tid >> 4) + 16 * j;                 // 0..127
            int n = row & 63, lm = row >> 6;
            const float4 s = *reinterpret_cast<const float4*>(
                &g_srcp[b][n][kc * 64 + ag_h4]);
            const float4 d = *reinterpret_cast<const float4*>(
                &g_dstp[b][m0 + lm][kc * 64 + ag_h4]);
            uint32_t p0 = packh2(fmaxf(s.x + d.x, 0.f), fmaxf(s.y + d.y, 0.f));
            uint32_t p1 = packh2(fmaxf(s.z + d.z, 0.f), fmaxf(s.w + d.w, 0.f));
            uint32_t off = (uint32_t)(row * 128 +
                            (ag_cgsh ^ ((row & 7) << 4)));
            *reinterpret_cast<uint2*>(smc + A_BASE + off) = make_uint2(p0, p1);
        }
        __syncthreads();

        uint32_t aH[4][4];
#pragma unroll
        for (int ks = 0; ks < 4; ks++) {
            uint32_t co = (uint32_t)((((ks * 2 + a_kx) ^ a_sw)) << 4);
            ldmx4(aH[ks], sb + A_BASE + a_off + co);
        }
        __syncthreads();

        const uint32_t wHi = sb + (uint32_t)(kc * 16384);
#pragma unroll
        for (int ks = 0; ks < 4; ks++) {
            uint32_t kco = (uint32_t)(((ks * 2 + b_kx) ^ b_sw) << 4);
#pragma unroll
            for (int ng = 0; ng < 2; ng++) {
                uint32_t bh[4][4];
#pragma unroll
                for (int q = 0; q < 4; q++) {
                    int ntp = ng * 4 + q;
                    ldmx4(bh[q], wHi + (uint32_t)((ntp * 16 + b_rl) * 128) + kco);
                }
#pragma unroll
                for (int q = 0; q < 4; q++) {
                    int nt = (ng * 4 + q) * 2;
                    mma16816(c1[nt],     aH[ks], bh[q][0], bh[q][1]);
                    mma16816(c1[nt + 1], aH[ks], bh[q][2], bh[q][3]);
                }
            }
        }
    }

    // ================= bias + relu + convert to GEMM2 A fragments ==========
    const int ccol = (lane & 3) * 2;
    uint32_t aH2[8][4];
#pragma unroll
    for (int ko = 0; ko < 8; ko++) {
#pragma unroll
        for (int hn = 0; hn < 2; hn++) {
            int nt = 2 * ko + hn;
            float bv0 = s_b2[nt * 8 + ccol];
            float bv1 = s_b2[nt * 8 + ccol + 1];
            aH2[ko][hn * 2]     = packh2(fmaxf(c1[nt][0] + bv0, 0.f),
                                         fmaxf(c1[nt][1] + bv1, 0.f));
            aH2[ko][hn * 2 + 1] = packh2(fmaxf(c1[nt][2] + bv0, 0.f),
                                         fmaxf(c1[nt][3] + bv1, 0.f));
        }
    }

    // ================= GEMM2: K=128 (o), N=64 (k_out), single product =======
    float c2[8][4];
#pragma unroll
    for (int i = 0; i < 8; i++)
#pragma unroll
        for (int j = 0; j < 4; j++) c2[i][j] = 0.f;

#pragma unroll
    for (int ko = 0; ko < 8; ko++) {
        int kh = ko >> 2, ks = ko & 3;
        const uint32_t gHi = sb + (uint32_t)(G_BASE + kh * 8192);
        uint32_t kco = (uint32_t)(((ks * 2 + b_kx) ^ b_sw) << 4);
        uint32_t bh[4][4];
#pragma unroll
        for (int ntp = 0; ntp < 4; ntp++)
            ldmx4(bh[ntp], gHi + (uint32_t)((ntp * 16 + b_rl) * 128) + kco);
#pragma unroll
        for (int ntp = 0; ntp < 4; ntp++) {
            mma16816(c2[2 * ntp],     aH2[ko], bh[ntp][0], bh[ntp][1]);
            mma16816(c2[2 * ntp + 1], aH2[ko], bh[ntp][2], bh[ntp][3]);
        }
    }

    // ================= epilogue =================
    {
        int r0 = rm0 + (lane >> 2);
        int r1 = r0 + 8;
        float* p0 = out_arrow + (((size_t)b * 4096 +
                                  (size_t)(r0 & 63) * 64 + m0 + (r0 >> 6)) << 6);
        float* p1 = out_arrow + (((size_t)b * 4096 +
                                  (size_t)(r1 & 63) * 64 + m0 + (r1 >> 6)) << 6);
#pragma unroll
        for (int nt = 0; nt < 8; nt++) {
            int k = nt * 8 + ccol;
            float cv0 = s_cv[k], cv1 = s_cv[k + 1];
            float2 v0 = make_float2((c2[nt][0] + cv0) * SCALE_V,
                                    (c2[nt][1] + cv1) * SCALE_V);
            float2 v1 = make_float2((c2[nt][2] + cv0) * SCALE_V,
                                    (c2[nt][3] + cv1) * SCALE_V);
            *reinterpret_cast<float2*>(p0 + k) = v0;
            *reinterpret_cast<float2*>(p1 + k) = v1;
        }
    }
}

// ============================================================================
// launch
// ============================================================================
extern "C" void kernel_launch(void* const* d_in, const int* in_sizes, int n_in,
                              void* d_out, int out_size)
{
    (void)in_sizes; (void)n_in; (void)out_size;
    const float* x     = (const float*)d_in[0];
    const float* w_src = (const float*)d_in[1];
    const float* b_src = (const float*)d_in[2];
    const float* w_dst = (const float*)d_in[3];
    const float* b_dst = (const float*)d_in[4];
    const float* w_arr = (const float*)d_in[5];
    const float* b_arr = (const float*)d_in[6];
    const float* w1    = (const float*)d_in[7];
    const float* b1    = (const float*)d_in[8];
    const float* w2    = (const float*)d_in[9];
    const float* b2    = (const float*)d_in[10];
    const float* w3    = (const float*)d_in[11];
    const float* b3    = (const float*)d_in[12];

    float* out_move  = (float*)d_out;                       // 64*64*64
    float* out_arrow = (float*)d_out + 64 * 64 * 64;        // 64*4096*64

    constexpr int SMEM_MAIN = 98304;
    cudaFuncSetAttribute(main_kernel, cudaFuncAttributeMaxDynamicSharedMemorySize,
                         SMEM_MAIN);

    proj_kernel<<<dim3(3, 64), 256>>>(x, w_src, b_src, w_dst, b_dst, w_arr, b_arr);
    w2img_kernel<<<128, 256>>>(w2);
    stage2_kernel<<<384, 256>>>(w1, b1, w3, b3, out_move);
    main_kernel<<<dim3(32, 64), 256, SMEM_MAIN>>>(b2, out_arrow);
}

// round 10
// speedup vs baseline: 3.6091x; 1.0415x over previous
#include <cuda_runtime.h>
#include <cuda_fp16.h>
#include <cstdint>

// ---------------- problem constants ----------------
#define BB 64
#define CC 256
#define DD 128
#define NN 64
#define HH 256
#define SCALE_V 0.08838834764831845f   // 1/sqrt(128)

// ---------------- device scratch ----------------
__device__ float g_f[3][BB][DD][NN];     // f_src / f_dst / f_arr
__device__ float g_cv[BB][NN];           // c[b][k] = sum_p b3[p]*f_arr[b][p][k]
// fp16 images
__device__ __align__(16) __half g_srcp_h[BB][NN][HH];   // src_p (+b1), fp16
__device__ __align__(16) __half g_dstp_h[BB][NN][HH];   // dst_p, fp16
__device__ __align__(16) __half g_w2h[32768];           // [o(128)][h(256)]
__device__ __align__(16) __half g_Gh[BB * 8192];        // [b][k_out(64)][o(128)]

// ---------------- helpers ----------------
__device__ __forceinline__ uint32_t smem_u32(const void* p) {
    uint32_t a;
    asm("{ .reg .u64 t; cvta.to.shared.u64 t, %1; cvt.u32.u64 %0, t; }" : "=r"(a) : "l"(p));
    return a;
}
__device__ __forceinline__ void ldmx4(uint32_t r[4], uint32_t addr) {
    asm volatile("ldmatrix.sync.aligned.m8n8.x4.shared.b16 {%0,%1,%2,%3}, [%4];"
                 : "=r"(r[0]), "=r"(r[1]), "=r"(r[2]), "=r"(r[3]) : "r"(addr));
}
__device__ __forceinline__ void mma16816(float c[4], const uint32_t a[4],
                                         uint32_t b0, uint32_t b1) {
    asm volatile(
        "mma.sync.aligned.m16n8k16.row.col.f32.f16.f16.f32 "
        "{%0,%1,%2,%3}, {%4,%5,%6,%7}, {%8,%9}, {%0,%1,%2,%3};"
        : "+f"(c[0]), "+f"(c[1]), "+f"(c[2]), "+f"(c[3])
        : "r"(a[0]), "r"(a[1]), "r"(a[2]), "r"(a[3]), "r"(b0), "r"(b1));
}
__device__ __forceinline__ uint32_t packh2(float x, float y) {
    __half2 h = __floats2half2_rn(x, y);
    return *reinterpret_cast<uint32_t*>(&h);
}

// ============================================================================
// Kernel P: projections  f[mat][b] = W_mat @ x[b] + bias_mat
// ============================================================================
__global__ void __launch_bounds__(256) proj_kernel(
    const float* __restrict__ x,
    const float* __restrict__ w_src, const float* __restrict__ b_src,
    const float* __restrict__ w_dst, const float* __restrict__ b_dst,
    const float* __restrict__ w_arr, const float* __restrict__ b_arr)
{
    const int mat = blockIdx.x;
    const int b   = blockIdx.y;
    const float* w    = (mat == 0) ? w_src : (mat == 1) ? w_dst : w_arr;
    const float* bias = (mat == 0) ? b_src : (mat == 1) ? b_dst : b_arr;

    __shared__ float Ws[32][DD + 4];
    __shared__ float Xs[32][NN + 4];

    const int tid = threadIdx.x;
    const int tx  = tid & 15;
    const int ty  = tid >> 4;

    float acc[8][4];
#pragma unroll
    for (int i = 0; i < 8; i++)
#pragma unroll
        for (int j = 0; j < 4; j++) acc[i][j] = 0.f;

    const float* xb = x + (size_t)b * CC * NN;

#pragma unroll 1
    for (int c0 = 0; c0 < CC; c0 += 32) {
#pragma unroll
        for (int j = 0; j < 16; j++) {
            int i = tid + 256 * j;
            int d = i >> 5, kk = i & 31;
            Ws[kk][d] = w[d * CC + c0 + kk];
        }
#pragma unroll
        for (int j = 0; j < 8; j++) {
            int i = tid + 256 * j;
            int kk = i >> 6, n = i & 63;
            Xs[kk][n] = xb[(c0 + kk) * NN + n];
        }
        __syncthreads();
#pragma unroll
        for (int kk = 0; kk < 32; kk++) {
            float a[8], xv[4];
#pragma unroll
            for (int i = 0; i < 8; i++) a[i] = Ws[kk][ty * 8 + i];
#pragma unroll
            for (int j = 0; j < 4; j++) xv[j] = Xs[kk][tx * 4 + j];
#pragma unroll
            for (int i = 0; i < 8; i++)
#pragma unroll
                for (int j = 0; j < 4; j++) acc[i][j] += a[i] * xv[j];
        }
        __syncthreads();
    }

    float* out = &g_f[mat][b][0][0];
#pragma unroll
    for (int i = 0; i < 8; i++) {
        int d = ty * 8 + i;
        float bv = bias[d];
        float4 v = make_float4(acc[i][0] + bv, acc[i][1] + bv,
                               acc[i][2] + bv, acc[i][3] + bv);
        *reinterpret_cast<float4*>(&out[d * NN + tx * 4]) = v;
    }
}

// ============================================================================
// Prep: w2 (f32 [o][h]) -> fp16 image
// ============================================================================
__global__ void w2img_kernel(const float* __restrict__ w2)
{
    int idx = blockIdx.x * 256 + threadIdx.x;    // grid 128 -> 32768
    g_w2h[idx] = __float2half_rn(w2[idx]);
}

// ============================================================================
// Stage-2 merged kernel: sp (0..255) | g (256..319) | move (320..383)
// ============================================================================
__device__ void sp_body(float* sh, int bid, const float* __restrict__ w1,
                        const float* __restrict__ b1)
{
    const int type  = bid & 1;
    const int b     = (bid >> 1) & 63;
    const int hbase = (bid >> 7) * 128;
    float (*Ws)[132] = reinterpret_cast<float(*)[132]>(sh);          // 32x132
    float (*Fs)[68]  = reinterpret_cast<float(*)[68]>(sh + 4224);    // 32x68
    const int tid = threadIdx.x;
    const int tx  = tid & 15;
    const int ty  = tid >> 4;
    const int off = type * DD;

    float acc[4][8];
#pragma unroll
    for (int i = 0; i < 4; i++)
#pragma unroll
        for (int j = 0; j < 8; j++) acc[i][j] = 0.f;

#pragma unroll 1
    for (int d0 = 0; d0 < DD; d0 += 32) {
#pragma unroll
        for (int j = 0; j < 16; j++) {
            int i = tid + 256 * j;
            int h = i >> 5, kk = i & 31;
            Ws[kk][h] = w1[(hbase + h) * HH + off + d0 + kk];
        }
#pragma unroll
        for (int j = 0; j < 2; j++) {
            int i = tid + 256 * j;
            int kk = i >> 4, n4 = i & 15;
            *reinterpret_cast<float4*>(&Fs[kk][n4 * 4]) =
                *reinterpret_cast<const float4*>(&g_f[type][b][d0 + kk][n4 * 4]);
        }
        __syncthreads();
#pragma unroll
        for (int kk = 0; kk < 32; kk++) {
            float4 fv = *reinterpret_cast<const float4*>(&Fs[kk][ty * 4]);
            float4 w0 = *reinterpret_cast<const float4*>(&Ws[kk][tx * 8]);
            float4 w1v = *reinterpret_cast<const float4*>(&Ws[kk][tx * 8 + 4]);
            float f[4] = {fv.x, fv.y, fv.z, fv.w};
            float wv[8] = {w0.x, w0.y, w0.z, w0.w, w1v.x, w1v.y, w1v.z, w1v.w};
#pragma unroll
            for (int i = 0; i < 4; i++)
#pragma unroll
                for (int j = 0; j < 8; j++) acc[i][j] += f[i] * wv[j];
        }
        __syncthreads();
    }

    __half* out = (type == 0) ? &g_srcp_h[b][0][0] : &g_dstp_h[b][0][0];
    float bv[8];
#pragma unroll
    for (int j = 0; j < 8; j++)
        bv[j] = (type == 0) ? b1[hbase + tx * 8 + j] : 0.f;
#pragma unroll
    for (int i = 0; i < 4; i++) {
        int n = ty * 4 + i;
        uint4 v;
        v.x = packh2(acc[i][0] + bv[0], acc[i][1] + bv[1]);
        v.y = packh2(acc[i][2] + bv[2], acc[i][3] + bv[3]);
        v.z = packh2(acc[i][4] + bv[4], acc[i][5] + bv[5]);
        v.w = packh2(acc[i][6] + bv[6], acc[i][7] + bv[7]);
        *reinterpret_cast<uint4*>(&out[n * HH + hbase + tx * 8]) = v;
    }
}

__device__ void g_body(float* sh, int b, const float* __restrict__ w3,
                       const float* __restrict__ b3)
{
    float (*W3s)[132] = reinterpret_cast<float(*)[132]>(sh);          // 32x132
    float (*Fs)[68]   = reinterpret_cast<float(*)[68]>(sh + 4224);    // 32x68
    float* b3s        = sh + 4224 + 2176;                             // 32
    const int tid = threadIdx.x;
    const int tx  = tid & 15;
    const int ty  = tid >> 4;

    float acc[8][4];
    float cacc[4] = {0.f, 0.f, 0.f, 0.f};
#pragma unroll
    for (int i = 0; i < 8; i++)
#pragma unroll
        for (int j = 0; j < 4; j++) acc[i][j] = 0.f;

#pragma unroll 1
    for (int p0 = 0; p0 < DD; p0 += 32) {
#pragma unroll
        for (int j = 0; j < 16; j++) {
            int i = tid + 256 * j;
            int kk = i >> 7, o = i & 127;
            W3s[kk][o] = w3[(p0 + kk) * DD + o];
        }
#pragma unroll
        for (int j = 0; j < 8; j++) {
            int i = tid + 256 * j;
            int kk = i >> 6, k = i & 63;
            Fs[kk][k] = g_f[2][b][p0 + kk][k];
        }
        if (tid < 32) b3s[tid] = b3[p0 + tid];
        __syncthreads();
#pragma unroll
        for (int kk = 0; kk < 32; kk++) {
            float wv[8], fv[4];
#pragma unroll
            for (int i = 0; i < 8; i++) wv[i] = W3s[kk][ty * 8 + i];
#pragma unroll
            for (int j = 0; j < 4; j++) fv[j] = Fs[kk][tx * 4 + j];
#pragma unroll
            for (int i = 0; i < 8; i++)
#pragma unroll
                for (int j = 0; j < 4; j++) acc[i][j] += wv[i] * fv[j];
            if (ty == 0) {
                float bvv = b3s[kk];
#pragma unroll
                for (int j = 0; j < 4; j++) cacc[j] += bvv * fv[j];
            }
        }
        __syncthreads();
    }
#pragma unroll
    for (int i = 0; i < 8; i++) {
        int o = ty * 8 + i;
#pragma unroll
        for (int j = 0; j < 4; j++) {
            int k = tx * 4 + j;
            g_Gh[b * 8192 + k * 128 + o] = __float2half_rn(acc[i][j]);
        }
    }
    if (ty == 0) {
        float4 v = make_float4(cacc[0], cacc[1], cacc[2], cacc[3]);
        *reinterpret_cast<float4*>(&g_cv[b][tx * 4]) = v;
    }
}

__device__ void move_body(float* sh, int b, float* __restrict__ out_move)
{
    float (*Ss)[66] = reinterpret_cast<float(*)[66]>(sh);             // 64x66
    float (*Dm)[66] = reinterpret_cast<float(*)[66]>(sh + 4224);      // 64x66
    const int tid = threadIdx.x;
    const int tx  = tid & 15;
    const int ty  = tid >> 4;

    float acc[4][4];
#pragma unroll
    for (int i = 0; i < 4; i++)
#pragma unroll
        for (int j = 0; j < 4; j++) acc[i][j] = 0.f;

#pragma unroll 1
    for (int d0 = 0; d0 < DD; d0 += 64) {
#pragma unroll
        for (int j = 0; j < 16; j++) {
            int i = tid + 256 * j;
            int dd = i >> 6, n = i & 63;
            Ss[dd][n] = g_f[0][b][d0 + dd][n];
            Dm[dd][n] = g_f[1][b][d0 + dd][n];
        }
        __syncthreads();
#pragma unroll
        for (int dd = 0; dd < 64; dd++) {
            float sv[4], dv[4];
#pragma unroll
            for (int i = 0; i < 4; i++) sv[i] = Ss[dd][ty * 4 + i];
#pragma unroll
            for (int j = 0; j < 4; j++) dv[j] = Dm[dd][tx * 4 + j];
#pragma unroll
            for (int i = 0; i < 4; i++)
#pragma unroll
                for (int j = 0; j < 4; j++) acc[i][j] += sv[i] * dv[j];
        }
        __syncthreads();
    }
#pragma unroll
    for (int i = 0; i < 4; i++) {
        int n = ty * 4 + i;
        float4 v = make_float4(acc[i][0] * SCALE_V, acc[i][1] * SCALE_V,
                               acc[i][2] * SCALE_V, acc[i][3] * SCALE_V);
        *reinterpret_cast<float4*>(&out_move[(b * NN + n) * NN + tx * 4]) = v;
    }
}

__global__ void __launch_bounds__(256) stage2_kernel(
    const float* __restrict__ w1, const float* __restrict__ b1,
    const float* __restrict__ w3, const float* __restrict__ b3,
    float* __restrict__ out_move)
{
    __shared__ float sh[8448];
    const int bid = blockIdx.x;
    if (bid < 256)      sp_body(sh, bid, w1, b1);
    else if (bid < 320) g_body(sh, bid - 256, w3, b3);
    else                move_body(sh, bid - 320, out_move);
}

// ============================================================================
// Main (hot): warp-mma fp16, 4M x 2N warp tile, K-split GEMM2 + smem reduce.
// Dynamic SMEM (bytes):
//   [0,     65536)  W2 tiles [kc(4)][128 o][64 h]   (reused as fp32 reduce buf)
//   [65536, 81920)  G tiles [kh(2)][64 k][64 o]
//   [81920, 98304)  A tile [128 r][64 h]
// ============================================================================
__global__ void __launch_bounds__(256, 2) main_kernel(
    const float* __restrict__ b2, float* __restrict__ out_arrow)
{
    extern __shared__ char smc[];
    __shared__ float s_cv[64];
    __shared__ float s_b2[128];

    const uint32_t sb = smem_u32(smc);
    const int tid  = threadIdx.x;
    const int wid  = tid >> 5;
    const int lane = tid & 31;
    const int mt = blockIdx.x, b = blockIdx.y, m0 = mt * 2;

    const int G_BASE = 65536, A_BASE = 81920;
    const int im = wid & 3;      // M group (32 rows)
    const int in = wid >> 2;     // N half (64 o cols / G kh half)

    // ---- prologue: copy fp16 images into swizzled smem tiles ----
    {
        for (int i = tid; i < 4096; i += 256) {
            int o = i >> 5, grp = i & 31;
            int kc = grp >> 3, cgl = grp & 7;
            const uint4* src = reinterpret_cast<const uint4*>(g_w2h + o * 256 + grp * 8);
            uint32_t dst = (uint32_t)(kc * 16384 + o * 128 + ((cgl ^ (o & 7)) << 4));
            *reinterpret_cast<uint4*>(smc + dst) = *src;
        }
        for (int i = tid; i < 1024; i += 256) {
            int r = i >> 4, grp = i & 15;
            int kh = grp >> 3, cgl = grp & 7;
            const uint4* src = reinterpret_cast<const uint4*>(
                g_Gh + b * 8192 + r * 128 + grp * 8);
            uint32_t dst = (uint32_t)(G_BASE + kh * 8192 + r * 128 +
                                      ((cgl ^ (r & 7)) << 4));
            *reinterpret_cast<uint4*>(smc + dst) = *src;
        }
        if (tid < 64)  s_cv[tid] = g_cv[b][tid];
        if (tid < 128) s_b2[tid] = b2[tid];
    }

    // ---- per-lane ldmatrix address components ----
    const int rowinm = lane & 7, mi = lane >> 3;
    const int a_kx = mi >> 1;
    const int a_rl = ((mi & 1) << 3) + rowinm;       // row within 16-row m-tile
    const int b_rl = ((mi >> 1) << 3) + rowinm;      // row within 16-row n-tile
    const int b_sw = rowinm;
    const int b_kx = mi & 1;

    // ---- A generation indexing (fp16 inputs, coalesced) ----
    const int ag_grp  = tid & 7;                     // 16B group in 128B row
    const int ag_row0 = tid >> 3;                    // 0..31

    float c1[2][8][4];
#pragma unroll
    for (int m = 0; m < 2; m++)
#pragma unroll
        for (int i = 0; i < 8; i++)
#pragma unroll
            for (int j = 0; j < 4; j++) c1[m][i][j] = 0.f;

    const __half2 zz = __floats2half2_rn(0.f, 0.f);

    // ================= GEMM1: 4 K-chunks of 64 ==============================
#pragma unroll 1
    for (int kc = 0; kc < 4; kc++) {
        // A-gen: relu(srcp_h + dstp_h) fp16, swizzled, coalesced
#pragma unroll
        for (int j = 0; j < 4; j++) {
            int row = ag_row0 + 32 * j;              // 0..127
            int n = row & 63, lm = row >> 6;
            uint4 s = *reinterpret_cast<const uint4*>(
                &g_srcp_h[b][n][kc * 64 + ag_grp * 8]);
            uint4 d = *reinterpret_cast<const uint4*>(
                &g_dstp_h[b][m0 + lm][kc * 64 + ag_grp * 8]);
            const __half2* sh2 = reinterpret_cast<const __half2*>(&s);
            const __half2* dh2 = reinterpret_cast<const __half2*>(&d);
            uint4 v;
            __half2 t0 = __hmax2(__hadd2(sh2[0], dh2[0]), zz);
            __half2 t1 = __hmax2(__hadd2(sh2[1], dh2[1]), zz);
            __half2 t2 = __hmax2(__hadd2(sh2[2], dh2[2]), zz);
            __half2 t3 = __hmax2(__hadd2(sh2[3], dh2[3]), zz);
            v.x = *reinterpret_cast<uint32_t*>(&t0);
            v.y = *reinterpret_cast<uint32_t*>(&t1);
            v.z = *reinterpret_cast<uint32_t*>(&t2);
            v.w = *reinterpret_cast<uint32_t*>(&t3);
            uint32_t off = (uint32_t)(row * 128 + ((ag_grp ^ (row & 7)) << 4));
            *reinterpret_cast<uint4*>(smc + A_BASE + off) = v;
        }
        __syncthreads();

        const uint32_t wHi = sb + (uint32_t)(kc * 16384);
#pragma unroll
        for (int ks = 0; ks < 4; ks++) {
            // A frags: 2 m-tiles
            uint32_t aH[2][4];
#pragma unroll
            for (int m = 0; m < 2; m++) {
                int a_r = im * 32 + m * 16 + a_rl;
                uint32_t co = (uint32_t)(((ks * 2 + a_kx) ^ (a_r & 7)) << 4);
                ldmx4(aH[m], sb + A_BASE + (uint32_t)(a_r * 128) + co);
            }
            // B frags: 4 ntp within this warp's o-half
            uint32_t kco = (uint32_t)(((ks * 2 + b_kx) ^ b_sw) << 4);
            uint32_t bh[4][4];
#pragma unroll
            for (int q = 0; q < 4; q++) {
                int o_row = in * 64 + q * 16 + b_rl;
                ldmx4(bh[q], wHi + (uint32_t)(o_row * 128) + kco);
            }
#pragma unroll
            for (int q = 0; q < 4; q++)
#pragma unroll
                for (int m = 0; m < 2; m++) {
                    mma16816(c1[m][2 * q],     aH[m], bh[q][0], bh[q][1]);
                    mma16816(c1[m][2 * q + 1], aH[m], bh[q][2], bh[q][3]);
                }
        }
        __syncthreads();
    }

    // ====== bias + relu + convert c1 -> GEMM2 A fragments (o-half K) ========
    const int ccol = (lane & 3) * 2;
    uint32_t aH2[2][4][4];
#pragma unroll
    for (int m = 0; m < 2; m++)
#pragma unroll
        for (int ko = 0; ko < 4; ko++) {
#pragma unroll
            for (int hn = 0; hn < 2; hn++) {
                int nt = 2 * ko + hn;
                float bv0 = s_b2[in * 64 + nt * 8 + ccol];
                float bv1 = s_b2[in * 64 + nt * 8 + ccol + 1];
                aH2[m][ko][hn * 2]     = packh2(fmaxf(c1[m][nt][0] + bv0, 0.f),
                                                fmaxf(c1[m][nt][1] + bv1, 0.f));
                aH2[m][ko][hn * 2 + 1] = packh2(fmaxf(c1[m][nt][2] + bv0, 0.f),
                                                fmaxf(c1[m][nt][3] + bv1, 0.f));
            }
        }

    // ================= GEMM2 partial: K = this warp's 64 o ==================
    float c2[2][8][4];
#pragma unroll
    for (int m = 0; m < 2; m++)
#pragma unroll
        for (int i = 0; i < 8; i++)
#pragma unroll
            for (int j = 0; j < 4; j++) c2[m][i][j] = 0.f;

    const uint32_t gBase = sb + (uint32_t)(G_BASE + in * 8192);
#pragma unroll
    for (int ko = 0; ko < 4; ko++) {
        uint32_t kco = (uint32_t)(((ko * 2 + b_kx) ^ b_sw) << 4);
        uint32_t bh[4][4];
#pragma unroll
        for (int q = 0; q < 4; q++)
            ldmx4(bh[q], gBase + (uint32_t)((q * 16 + b_rl) * 128) + kco);
#pragma unroll
        for (int q = 0; q < 4; q++)
#pragma unroll
            for (int m = 0; m < 2; m++) {
                mma16816(c2[m][2 * q],     aH2[m][ko], bh[q][0], bh[q][1]);
                mma16816(c2[m][2 * q + 1], aH2[m][ko], bh[q][2], bh[q][3]);
            }
    }

    // ================= cross-warp K reduction + epilogue =====================
    // reduce buffer: fp32 [128 rows][64 k], stride 72 floats (reuses w2 region)
    float* rbuf = reinterpret_cast<float*>(smc);
    if (in == 1) {
#pragma unroll
        for (int m = 0; m < 2; m++) {
            int r0 = im * 32 + m * 16 + (lane >> 2);
#pragma unroll
            for (int kt = 0; kt < 8; kt++) {
                int k = kt * 8 + ccol;
                *reinterpret_cast<float2*>(&rbuf[r0 * 72 + k]) =
                    make_float2(c2[m][kt][0], c2[m][kt][1]);
                *reinterpret_cast<float2*>(&rbuf[(r0 + 8) * 72 + k]) =
                    make_float2(c2[m][kt][2], c2[m][kt][3]);
            }
        }
    }
    __syncthreads();
    if (in == 0) {
#pragma unroll
        for (int m = 0; m < 2; m++) {
            int r0 = im * 32 + m * 16 + (lane >> 2);
            int r1 = r0 + 8;
            float* p0 = out_arrow + (((size_t)b * 4096 +
                                      (size_t)(r0 & 63) * 64 + m0 + (r0 >> 6)) << 6);
            float* p1 = out_arrow + (((size_t)b * 4096 +
                                      (size_t)(r1 & 63) * 64 + m0 + (r1 >> 6)) << 6);
#pragma unroll
            for (int kt = 0; kt < 8; kt++) {
                int k = kt * 8 + ccol;
                float2 q0 = *reinterpret_cast<const float2*>(&rbuf[r0 * 72 + k]);
                float2 q1 = *reinterpret_cast<const float2*>(&rbuf[r1 * 72 + k]);
                float cv0 = s_cv[k], cv1 = s_cv[k + 1];
                float2 v0 = make_float2((c2[m][kt][0] + q0.x + cv0) * SCALE_V,
                                        (c2[m][kt][1] + q0.y + cv1) * SCALE_V);
                float2 v1 = make_float2((c2[m][kt][2] + q1.x + cv0) * SCALE_V,
                                        (c2[m][kt][3] + q1.y + cv1) * SCALE_V);
                *reinterpret_cast<float2*>(p0 + k) = v0;
                *reinterpret_cast<float2*>(p1 + k) = v1;
            }
        }
    }
}

// ============================================================================
// launch
// ============================================================================
extern "C" void kernel_launch(void* const* d_in, const int* in_sizes, int n_in,
                              void* d_out, int out_size)
{
    (void)in_sizes; (void)n_in; (void)out_size;
    const float* x     = (const float*)d_in[0];
    const float* w_src = (const float*)d_in[1];
    const float* b_src = (const float*)d_in[2];
    const float* w_dst = (const float*)d_in[3];
    const float* b_dst = (const float*)d_in[4];
    const float* w_arr = (const float*)d_in[5];
    const float* b_arr = (const float*)d_in[6];
    const float* w1    = (const float*)d_in[7];
    const float* b1    = (const float*)d_in[8];
    const float* w2    = (const float*)d_in[9];
    const float* b2    = (const float*)d_in[10];
    const float* w3    = (const float*)d_in[11];
    const float* b3    = (const float*)d_in[12];

    float* out_move  = (float*)d_out;                       // 64*64*64
    float* out_arrow = (float*)d_out + 64 * 64 * 64;        // 64*4096*64

    constexpr int SMEM_MAIN = 98304;
    cudaFuncSetAttribute(main_kernel, cudaFuncAttributeMaxDynamicSharedMemorySize,
                         SMEM_MAIN);

    proj_kernel<<<dim3(3, 64), 256>>>(x, w_src, b_src, w_dst, b_dst, w_arr, b_arr);
    w2img_kernel<<<128, 256>>>(w2);
    stage2_kernel<<<384, 256>>>(w1, b1, w3, b3, out_move);
    main_kernel<<<dim3(32, 64), 256, SMEM_MAIN>>>(b2, out_arrow);
}

// round 11
// speedup vs baseline: 3.7914x; 1.0505x over previous
#include <cuda_runtime.h>
#include <cuda_fp16.h>
#include <cstdint>

// ---------------- problem constants ----------------
#define BB 64
#define CC 256
#define DD 128
#define NN 64
#define HH 256
#define SCALE_V 0.08838834764831845f   // 1/sqrt(128)

// ---------------- device scratch ----------------
__device__ float g_f[3][BB][DD][NN];     // f_src / f_dst / f_arr
__device__ float g_cv[BB][NN];           // c[b][k] = sum_p b3[p]*f_arr[b][p][k]
// fp16 images
__device__ __align__(16) __half g_srcp_h[BB][NN][HH];   // src_p (+b1), fp16
__device__ __align__(16) __half g_dstp_h[BB][NN][HH];   // dst_p, fp16
__device__ __align__(16) __half g_w2h[32768];           // [o(128)][h(256)]
__device__ __align__(16) __half g_Gh[BB * 8192];        // [b][k_out(64)][o(128)]

// ---------------- helpers ----------------
__device__ __forceinline__ uint32_t smem_u32(const void* p) {
    uint32_t a;
    asm("{ .reg .u64 t; cvta.to.shared.u64 t, %1; cvt.u32.u64 %0, t; }" : "=r"(a) : "l"(p));
    return a;
}
__device__ __forceinline__ void ldmx4(uint32_t r[4], uint32_t addr) {
    asm volatile("ldmatrix.sync.aligned.m8n8.x4.shared.b16 {%0,%1,%2,%3}, [%4];"
                 : "=r"(r[0]), "=r"(r[1]), "=r"(r[2]), "=r"(r[3]) : "r"(addr));
}
__device__ __forceinline__ void mma16816(float c[4], const uint32_t a[4],
                                         uint32_t b0, uint32_t b1) {
    asm volatile(
        "mma.sync.aligned.m16n8k16.row.col.f32.f16.f16.f32 "
        "{%0,%1,%2,%3}, {%4,%5,%6,%7}, {%8,%9}, {%0,%1,%2,%3};"
        : "+f"(c[0]), "+f"(c[1]), "+f"(c[2]), "+f"(c[3])
        : "r"(a[0]), "r"(a[1]), "r"(a[2]), "r"(a[3]), "r"(b0), "r"(b1));
}
__device__ __forceinline__ uint32_t packh2(float x, float y) {
    __half2 h = __floats2half2_rn(x, y);
    return *reinterpret_cast<uint32_t*>(&h);
}
__device__ __forceinline__ uint4 reluadd4(uint4 s, uint4 d) {
    const __half2 zz = __floats2half2_rn(0.f, 0.f);
    const __half2* sh2 = reinterpret_cast<const __half2*>(&s);
    const __half2* dh2 = reinterpret_cast<const __half2*>(&d);
    __half2 t0 = __hmax2(__hadd2(sh2[0], dh2[0]), zz);
    __half2 t1 = __hmax2(__hadd2(sh2[1], dh2[1]), zz);
    __half2 t2 = __hmax2(__hadd2(sh2[2], dh2[2]), zz);
    __half2 t3 = __hmax2(__hadd2(sh2[3], dh2[3]), zz);
    uint4 v;
    v.x = *reinterpret_cast<uint32_t*>(&t0);
    v.y = *reinterpret_cast<uint32_t*>(&t1);
    v.z = *reinterpret_cast<uint32_t*>(&t2);
    v.w = *reinterpret_cast<uint32_t*>(&t3);
    return v;
}

// ============================================================================
// Kernel P: projections  f[mat][b] = W_mat @ x[b] + bias_mat
// ============================================================================
__global__ void __launch_bounds__(256) proj_kernel(
    const float* __restrict__ x,
    const float* __restrict__ w_src, const float* __restrict__ b_src,
    const float* __restrict__ w_dst, const float* __restrict__ b_dst,
    const float* __restrict__ w_arr, const float* __restrict__ b_arr)
{
    const int mat = blockIdx.x;
    const int b   = blockIdx.y;
    const float* w    = (mat == 0) ? w_src : (mat == 1) ? w_dst : w_arr;
    const float* bias = (mat == 0) ? b_src : (mat == 1) ? b_dst : b_arr;

    __shared__ float Ws[32][DD + 4];
    __shared__ float Xs[32][NN + 4];

    const int tid = threadIdx.x;
    const int tx  = tid & 15;
    const int ty  = tid >> 4;

    float acc[8][4];
#pragma unroll
    for (int i = 0; i < 8; i++)
#pragma unroll
        for (int j = 0; j < 4; j++) acc[i][j] = 0.f;

    const float* xb = x + (size_t)b * CC * NN;

#pragma unroll 1
    for (int c0 = 0; c0 < CC; c0 += 32) {
#pragma unroll
        for (int j = 0; j < 16; j++) {
            int i = tid + 256 * j;
            int d = i >> 5, kk = i & 31;
            Ws[kk][d] = w[d * CC + c0 + kk];
        }
#pragma unroll
        for (int j = 0; j < 8; j++) {
            int i = tid + 256 * j;
            int kk = i >> 6, n = i & 63;
            Xs[kk][n] = xb[(c0 + kk) * NN + n];
        }
        __syncthreads();
#pragma unroll
        for (int kk = 0; kk < 32; kk++) {
            float a[8], xv[4];
#pragma unroll
            for (int i = 0; i < 8; i++) a[i] = Ws[kk][ty * 8 + i];
#pragma unroll
            for (int j = 0; j < 4; j++) xv[j] = Xs[kk][tx * 4 + j];
#pragma unroll
            for (int i = 0; i < 8; i++)
#pragma unroll
                for (int j = 0; j < 4; j++) acc[i][j] += a[i] * xv[j];
        }
        __syncthreads();
    }

    float* out = &g_f[mat][b][0][0];
#pragma unroll
    for (int i = 0; i < 8; i++) {
        int d = ty * 8 + i;
        float bv = bias[d];
        float4 v = make_float4(acc[i][0] + bv, acc[i][1] + bv,
                               acc[i][2] + bv, acc[i][3] + bv);
        *reinterpret_cast<float4*>(&out[d * NN + tx * 4]) = v;
    }
}

// ============================================================================
// Prep: w2 (f32 [o][h]) -> fp16 image
// ============================================================================
__global__ void w2img_kernel(const float* __restrict__ w2)
{
    int idx = blockIdx.x * 256 + threadIdx.x;    // grid 128 -> 32768
    g_w2h[idx] = __float2half_rn(w2[idx]);
}

// ============================================================================
// Stage-2 merged kernel: sp (0..255) | g (256..319) | move (320..383)
// ============================================================================
__device__ void sp_body(float* sh, int bid, const float* __restrict__ w1,
                        const float* __restrict__ b1)
{
    const int type  = bid & 1;
    const int b     = (bid >> 1) & 63;
    const int hbase = (bid >> 7) * 128;
    float (*Ws)[132] = reinterpret_cast<float(*)[132]>(sh);          // 32x132
    float (*Fs)[68]  = reinterpret_cast<float(*)[68]>(sh + 4224);    // 32x68
    const int tid = threadIdx.x;
    const int tx  = tid & 15;
    const int ty  = tid >> 4;
    const int off = type * DD;

    float acc[4][8];
#pragma unroll
    for (int i = 0; i < 4; i++)
#pragma unroll
        for (int j = 0; j < 8; j++) acc[i][j] = 0.f;

#pragma unroll 1
    for (int d0 = 0; d0 < DD; d0 += 32) {
#pragma unroll
        for (int j = 0; j < 16; j++) {
            int i = tid + 256 * j;
            int h = i >> 5, kk = i & 31;
            Ws[kk][h] = w1[(hbase + h) * HH + off + d0 + kk];
        }
#pragma unroll
        for (int j = 0; j < 2; j++) {
            int i = tid + 256 * j;
            int kk = i >> 4, n4 = i & 15;
            *reinterpret_cast<float4*>(&Fs[kk][n4 * 4]) =
                *reinterpret_cast<const float4*>(&g_f[type][b][d0 + kk][n4 * 4]);
        }
        __syncthreads();
#pragma unroll
        for (int kk = 0; kk < 32; kk++) {
            float4 fv = *reinterpret_cast<const float4*>(&Fs[kk][ty * 4]);
            float4 w0 = *reinterpret_cast<const float4*>(&Ws[kk][tx * 8]);
            float4 w1v = *reinterpret_cast<const float4*>(&Ws[kk][tx * 8 + 4]);
            float f[4] = {fv.x, fv.y, fv.z, fv.w};
            float wv[8] = {w0.x, w0.y, w0.z, w0.w, w1v.x, w1v.y, w1v.z, w1v.w};
#pragma unroll
            for (int i = 0; i < 4; i++)
#pragma unroll
                for (int j = 0; j < 8; j++) acc[i][j] += f[i] * wv[j];
        }
        __syncthreads();
    }

    __half* out = (type == 0) ? &g_srcp_h[b][0][0] : &g_dstp_h[b][0][0];
    float bv[8];
#pragma unroll
    for (int j = 0; j < 8; j++)
        bv[j] = (type == 0) ? b1[hbase + tx * 8 + j] : 0.f;
#pragma unroll
    for (int i = 0; i < 4; i++) {
        int n = ty * 4 + i;
        uint4 v;
        v.x = packh2(acc[i][0] + bv[0], acc[i][1] + bv[1]);
        v.y = packh2(acc[i][2] + bv[2], acc[i][3] + bv[3]);
        v.z = packh2(acc[i][4] + bv[4], acc[i][5] + bv[5]);
        v.w = packh2(acc[i][6] + bv[6], acc[i][7] + bv[7]);
        *reinterpret_cast<uint4*>(&out[n * HH + hbase + tx * 8]) = v;
    }
}

__device__ void g_body(float* sh, int b, const float* __restrict__ w3,
                       const float* __restrict__ b3)
{
    float (*W3s)[132] = reinterpret_cast<float(*)[132]>(sh);          // 32x132
    float (*Fs)[68]   = reinterpret_cast<float(*)[68]>(sh + 4224);    // 32x68
    float* b3s        = sh + 4224 + 2176;                             // 32
    const int tid = threadIdx.x;
    const int tx  = tid & 15;
    const int ty  = tid >> 4;

    float acc[8][4];
    float cacc[4] = {0.f, 0.f, 0.f, 0.f};
#pragma unroll
    for (int i = 0; i < 8; i++)
#pragma unroll
        for (int j = 0; j < 4; j++) acc[i][j] = 0.f;

#pragma unroll 1
    for (int p0 = 0; p0 < DD; p0 += 32) {
#pragma unroll
        for (int j = 0; j < 16; j++) {
            int i = tid + 256 * j;
            int kk = i >> 7, o = i & 127;
            W3s[kk][o] = w3[(p0 + kk) * DD + o];
        }
#pragma unroll
        for (int j = 0; j < 8; j++) {
            int i = tid + 256 * j;
            int kk = i >> 6, k = i & 63;
            Fs[kk][k] = g_f[2][b][p0 + kk][k];
        }
        if (tid < 32) b3s[tid] = b3[p0 + tid];
        __syncthreads();
#pragma unroll
        for (int kk = 0; kk < 32; kk++) {
            float wv[8], fv[4];
#pragma unroll
            for (int i = 0; i < 8; i++) wv[i] = W3s[kk][ty * 8 + i];
#pragma unroll
            for (int j = 0; j < 4; j++) fv[j] = Fs[kk][tx * 4 + j];
#pragma unroll
            for (int i = 0; i < 8; i++)
#pragma unroll
                for (int j = 0; j < 4; j++) acc[i][j] += wv[i] * fv[j];
            if (ty == 0) {
                float bvv = b3s[kk];
#pragma unroll
                for (int j = 0; j < 4; j++) cacc[j] += bvv * fv[j];
            }
        }
        __syncthreads();
    }
#pragma unroll
    for (int i = 0; i < 8; i++) {
        int o = ty * 8 + i;
#pragma unroll
        for (int j = 0; j < 4; j++) {
            int k = tx * 4 + j;
            g_Gh[b * 8192 + k * 128 + o] = __float2half_rn(acc[i][j]);
        }
    }
    if (ty == 0) {
        float4 v = make_float4(cacc[0], cacc[1], cacc[2], cacc[3]);
        *reinterpret_cast<float4*>(&g_cv[b][tx * 4]) = v;
    }
}

__device__ void move_body(float* sh, int b, float* __restrict__ out_move)
{
    float (*Ss)[66] = reinterpret_cast<float(*)[66]>(sh);             // 64x66
    float (*Dm)[66] = reinterpret_cast<float(*)[66]>(sh + 4224);      // 64x66
    const int tid = threadIdx.x;
    const int tx  = tid & 15;
    const int ty  = tid >> 4;

    float acc[4][4];
#pragma unroll
    for (int i = 0; i < 4; i++)
#pragma unroll
        for (int j = 0; j < 4; j++) acc[i][j] = 0.f;

#pragma unroll 1
    for (int d0 = 0; d0 < DD; d0 += 64) {
#pragma unroll
        for (int j = 0; j < 16; j++) {
            int i = tid + 256 * j;
            int dd = i >> 6, n = i & 63;
            Ss[dd][n] = g_f[0][b][d0 + dd][n];
            Dm[dd][n] = g_f[1][b][d0 + dd][n];
        }
        __syncthreads();
#pragma unroll
        for (int dd = 0; dd < 64; dd++) {
            float sv[4], dv[4];
#pragma unroll
            for (int i = 0; i < 4; i++) sv[i] = Ss[dd][ty * 4 + i];
#pragma unroll
            for (int j = 0; j < 4; j++) dv[j] = Dm[dd][tx * 4 + j];
#pragma unroll
            for (int i = 0; i < 4; i++)
#pragma unroll
                for (int j = 0; j < 4; j++) acc[i][j] += sv[i] * dv[j];
        }
        __syncthreads();
    }
#pragma unroll
    for (int i = 0; i < 4; i++) {
        int n = ty * 4 + i;
        float4 v = make_float4(acc[i][0] * SCALE_V, acc[i][1] * SCALE_V,
                               acc[i][2] * SCALE_V, acc[i][3] * SCALE_V);
        *reinterpret_cast<float4*>(&out_move[(b * NN + n) * NN + tx * 4]) = v;
    }
}

__global__ void __launch_bounds__(256) stage2_kernel(
    const float* __restrict__ w1, const float* __restrict__ b1,
    const float* __restrict__ w3, const float* __restrict__ b3,
    float* __restrict__ out_move)
{
    __shared__ float sh[8448];
    const int bid = blockIdx.x;
    if (bid < 256)      sp_body(sh, bid, w1, b1);
    else if (bid < 320) g_body(sh, bid - 256, w3, b3);
    else                move_body(sh, bid - 320, out_move);
}

// ============================================================================
// Main (hot): warp-mma fp16, 4Mx2N warp tile, double-buffered pipelined A-gen,
// G loaded in the kc==3 prefetch slot, K-split GEMM2 + smem reduce.
// Dynamic SMEM (bytes):
//   [0,     65536)  W2 tiles [kc(4)][128 o][64 h]   (later fp32 reduce buf)
//   [65536, 81920)  A buf0   (later G tiles [kh(2)][64 k][64 o])
//   [81920, 98304)  A buf1
// ============================================================================
__global__ void __launch_bounds__(256, 2) main_kernel(
    const float* __restrict__ b2, float* __restrict__ out_arrow)
{
    extern __shared__ char smc[];
    __shared__ float  s_cv[64];
    __shared__ float  s_b2[128];
    __shared__ __half s_dst[2][256];

    const uint32_t sb = smem_u32(smc);
    const int tid  = threadIdx.x;
    const int wid  = tid >> 5;
    const int lane = tid & 31;
    const int mt = blockIdx.x, b = blockIdx.y, m0 = mt * 2;

    const int ABUF = 65536;        // buf0 at 65536, buf1 at 81920
    const int im = wid & 3;        // M group (32 rows)
    const int in = wid >> 2;       // N half (64 o cols / G kh half)

    // ---- per-lane ldmatrix address components ----
    const int rowinm = lane & 7, mi = lane >> 3;
    const int a_kx = mi >> 1;
    const int a_rl = ((mi & 1) << 3) + rowinm;
    const int b_rl = ((mi >> 1) << 3) + rowinm;
    const int b_sw = rowinm;
    const int b_kx = mi & 1;

    // ---- A generation indexing ----
    const int ag_grp  = tid & 7;
    const int ag_row0 = tid >> 3;   // 0..31

    // ---- prologue: w2 copy, small vectors, dstp rows, gen A(kc=0) ----
    {
        for (int i = tid; i < 4096; i += 256) {
            int o = i >> 5, grp = i & 31;
            int kc = grp >> 3, cgl = grp & 7;
            const uint4* src = reinterpret_cast<const uint4*>(g_w2h + o * 256 + grp * 8);
            uint32_t dst = (uint32_t)(kc * 16384 + o * 128 + ((cgl ^ (o & 7)) << 4));
            *reinterpret_cast<uint4*>(smc + dst) = *src;
        }
        if (tid < 64)  s_cv[tid] = g_cv[b][tid];
        if (tid < 128) s_b2[tid] = b2[tid];
        if (tid < 64) {
            int lm = tid >> 5, grp = tid & 31;
            *reinterpret_cast<uint4*>(&s_dst[lm][grp * 8]) =
                *reinterpret_cast<const uint4*>(&g_dstp_h[b][m0 + lm][grp * 8]);
        }
        // gen A chunk 0 into buf0
#pragma unroll
        for (int j = 0; j < 4; j++) {
            int row = ag_row0 + 32 * j;
            int n = row & 63, lm = row >> 6;
            uint4 s = *reinterpret_cast<const uint4*>(&g_srcp_h[b][n][ag_grp * 8]);
            uint4 d = *reinterpret_cast<const uint4*>(&g_dstp_h[b][m0 + lm][ag_grp * 8]);
            uint4 v = reluadd4(s, d);
            uint32_t off = (uint32_t)(row * 128 + ((ag_grp ^ (row & 7)) << 4));
            *reinterpret_cast<uint4*>(smc + ABUF + off) = v;
        }
    }
    __syncthreads();

    float c1[2][8][4];
#pragma unroll
    for (int m = 0; m < 2; m++)
#pragma unroll
        for (int i = 0; i < 8; i++)
#pragma unroll
            for (int j = 0; j < 4; j++) c1[m][i][j] = 0.f;

    // ================= GEMM1: 4 K-chunks of 64, pipelined ===================
#pragma unroll 1
    for (int kc = 0; kc < 4; kc++) {
        const uint32_t curA = sb + (uint32_t)(ABUF + ((kc & 1) << 14));
        const uint32_t wHi  = sb + (uint32_t)(kc * 16384);

        // -- prefetch: next A chunk's srcp, or (kc==3) the G image --
        uint4 ps[4];
        if (kc < 3) {
#pragma unroll
            for (int j = 0; j < 4; j++) {
                int row = ag_row0 + 32 * j;
                int n = row & 63;
                ps[j] = *reinterpret_cast<const uint4*>(
                    &g_srcp_h[b][n][(kc + 1) * 64 + ag_grp * 8]);
            }
        } else {
#pragma unroll
            for (int t = 0; t < 4; t++) {
                int i = tid + 256 * t;
                ps[t] = *reinterpret_cast<const uint4*>(
                    &g_Gh[b * 8192 + (i >> 4) * 128 + (i & 15) * 8]);
            }
        }

        // -- MMA segment 1: ks = 0,1 --
#pragma unroll
        for (int ks = 0; ks < 2; ks++) {
            uint32_t aH[2][4];
#pragma unroll
            for (int m = 0; m < 2; m++) {
                int a_r = im * 32 + m * 16 + a_rl;
                uint32_t co = (uint32_t)(((ks * 2 + a_kx) ^ (a_r & 7)) << 4);
                ldmx4(aH[m], curA + (uint32_t)(a_r * 128) + co);
            }
            uint32_t kco = (uint32_t)(((ks * 2 + b_kx) ^ b_sw) << 4);
            uint32_t bh[4][4];
#pragma unroll
            for (int q = 0; q < 4; q++) {
                int o_row = in * 64 + q * 16 + b_rl;
                ldmx4(bh[q], wHi + (uint32_t)(o_row * 128) + kco);
            }
#pragma unroll
            for (int q = 0; q < 4; q++)
#pragma unroll
                for (int m = 0; m < 2; m++) {
                    mma16816(c1[m][2 * q],     aH[m], bh[q][0], bh[q][1]);
                    mma16816(c1[m][2 * q + 1], aH[m], bh[q][2], bh[q][3]);
                }
        }

        // -- mid: finish prefetch math (frees half the registers) --
        uint4 pv[4];
        if (kc < 3) {
#pragma unroll
            for (int j = 0; j < 4; j++) {
                int row = ag_row0 + 32 * j;
                int lm = row >> 6;
                uint4 d = *reinterpret_cast<const uint4*>(
                    &s_dst[lm][(kc + 1) * 64 + ag_grp * 8]);
                pv[j] = reluadd4(ps[j], d);
            }
        } else {
#pragma unroll
            for (int t = 0; t < 4; t++) pv[t] = ps[t];
        }

        // -- MMA segment 2: ks = 2,3 --
#pragma unroll
        for (int ks = 2; ks < 4; ks++) {
            uint32_t aH[2][4];
#pragma unroll
            for (int m = 0; m < 2; m++) {
                int a_r = im * 32 + m * 16 + a_rl;
                uint32_t co = (uint32_t)(((ks * 2 + a_kx) ^ (a_r & 7)) << 4);
                ldmx4(aH[m], curA + (uint32_t)(a_r * 128) + co);
            }
            uint32_t kco = (uint32_t)(((ks * 2 + b_kx) ^ b_sw) << 4);
            uint32_t bh[4][4];
#pragma unroll
            for (int q = 0; q < 4; q++) {
                int o_row = in * 64 + q * 16 + b_rl;
                ldmx4(bh[q], wHi + (uint32_t)(o_row * 128) + kco);
            }
#pragma unroll
            for (int q = 0; q < 4; q++)
#pragma unroll
                for (int m = 0; m < 2; m++) {
                    mma16816(c1[m][2 * q],     aH[m], bh[q][0], bh[q][1]);
                    mma16816(c1[m][2 * q + 1], aH[m], bh[q][2], bh[q][3]);
                }
        }

        // -- store prefetched data (other A buf, or G into buf0 region) --
        if (kc < 3) {
            char* obuf = smc + ABUF + (((kc + 1) & 1) << 14);
#pragma unroll
            for (int j = 0; j < 4; j++) {
                int row = ag_row0 + 32 * j;
                uint32_t off = (uint32_t)(row * 128 + ((ag_grp ^ (row & 7)) << 4));
                *reinterpret_cast<uint4*>(obuf + off) = pv[j];
            }
        } else {
#pragma unroll
            for (int t = 0; t < 4; t++) {
                int i = tid + 256 * t;
                int r = i >> 4, grp = i & 15;
                int kh = grp >> 3, cgl = grp & 7;
                uint32_t dst = (uint32_t)(ABUF + kh * 8192 + r * 128 +
                                          ((cgl ^ (r & 7)) << 4));
                *reinterpret_cast<uint4*>(smc + dst) = pv[t];
            }
        }
        __syncthreads();
    }

    // ====== bias + relu + convert c1 -> GEMM2 A fragments (o-half K) ========
    const int ccol = (lane & 3) * 2;
    uint32_t aH2[2][4][4];
#pragma unroll
    for (int m = 0; m < 2; m++)
#pragma unroll
        for (int ko = 0; ko < 4; ko++) {
#pragma unroll
            for (int hn = 0; hn < 2; hn++) {
                int nt = 2 * ko + hn;
                float bv0 = s_b2[in * 64 + nt * 8 + ccol];
                float bv1 = s_b2[in * 64 + nt * 8 + ccol + 1];
                aH2[m][ko][hn * 2]     = packh2(fmaxf(c1[m][nt][0] + bv0, 0.f),
                                                fmaxf(c1[m][nt][1] + bv1, 0.f));
                aH2[m][ko][hn * 2 + 1] = packh2(fmaxf(c1[m][nt][2] + bv0, 0.f),
                                                fmaxf(c1[m][nt][3] + bv1, 0.f));
            }
        }

    // ================= GEMM2 partial: K = this warp's 64 o ==================
    float c2[2][8][4];
#pragma unroll
    for (int m = 0; m < 2; m++)
#pragma unroll
        for (int i = 0; i < 8; i++)
#pragma unroll
            for (int j = 0; j < 4; j++) c2[m][i][j] = 0.f;

    const uint32_t gBase = sb + (uint32_t)(ABUF + in * 8192);
#pragma unroll
    for (int ko = 0; ko < 4; ko++) {
        uint32_t kco = (uint32_t)(((ko * 2 + b_kx) ^ b_sw) << 4);
        uint32_t bh[4][4];
#pragma unroll
        for (int q = 0; q < 4; q++)
            ldmx4(bh[q], gBase + (uint32_t)((q * 16 + b_rl) * 128) + kco);
#pragma unroll
        for (int q = 0; q < 4; q++)
#pragma unroll
            for (int m = 0; m < 2; m++) {
                mma16816(c2[m][2 * q],     aH2[m][ko], bh[q][0], bh[q][1]);
                mma16816(c2[m][2 * q + 1], aH2[m][ko], bh[q][2], bh[q][3]);
            }
    }

    // ================= cross-warp K reduction + epilogue =====================
    float* rbuf = reinterpret_cast<float*>(smc);   // w2 region, dead now
    if (in == 1) {
#pragma unroll
        for (int m = 0; m < 2; m++) {
            int r0 = im * 32 + m * 16 + (lane >> 2);
#pragma unroll
            for (int kt = 0; kt < 8; kt++) {
                int k = kt * 8 + ccol;
                *reinterpret_cast<float2*>(&rbuf[r0 * 72 + k]) =
                    make_float2(c2[m][kt][0], c2[m][kt][1]);
                *reinterpret_cast<float2*>(&rbuf[(r0 + 8) * 72 + k]) =
                    make_float2(c2[m][kt][2], c2[m][kt][3]);
            }
        }
    }
    __syncthreads();
    if (in == 0) {
#pragma unroll
        for (int m = 0; m < 2; m++) {
            int r0 = im * 32 + m * 16 + (lane >> 2);
            int r1 = r0 + 8;
            float* p0 = out_arrow + (((size_t)b * 4096 +
                                      (size_t)(r0 & 63) * 64 + m0 + (r0 >> 6)) << 6);
            float* p1 = out_arrow + (((size_t)b * 4096 +
                                      (size_t)(r1 & 63) * 64 + m0 + (r1 >> 6)) << 6);
#pragma unroll
            for (int kt = 0; kt < 8; kt++) {
                int k = kt * 8 + ccol;
                float2 q0 = *reinterpret_cast<const float2*>(&rbuf[r0 * 72 + k]);
                float2 q1 = *reinterpret_cast<const float2*>(&rbuf[r1 * 72 + k]);
                float cv0 = s_cv[k], cv1 = s_cv[k + 1];
                float2 v0 = make_float2((c2[m][kt][0] + q0.x + cv0) * SCALE_V,
                                        (c2[m][kt][1] + q0.y + cv1) * SCALE_V);
                float2 v1 = make_float2((c2[m][kt][2] + q1.x + cv0) * SCALE_V,
                                        (c2[m][kt][3] + q1.y + cv1) * SCALE_V);
                *reinterpret_cast<float2*>(p0 + k) = v0;
                *reinterpret_cast<float2*>(p1 + k) = v1;
            }
        }
    }
}

// ============================================================================
// launch
// ============================================================================
extern "C" void kernel_launch(void* const* d_in, const int* in_sizes, int n_in,
                              void* d_out, int out_size)
{
    (void)in_sizes; (void)n_in; (void)out_size;
    const float* x     = (const float*)d_in[0];
    const float* w_src = (const float*)d_in[1];
    const float* b_src = (const float*)d_in[2];
    const float* w_dst = (const float*)d_in[3];
    const float* b_dst = (const float*)d_in[4];
    const float* w_arr = (const float*)d_in[5];
    const float* b_arr = (const float*)d_in[6];
    const float* w1    = (const float*)d_in[7];
    const float* b1    = (const float*)d_in[8];
    const float* w2    = (const float*)d_in[9];
    const float* b2    = (const float*)d_in[10];
    const float* w3    = (const float*)d_in[11];
    const float* b3    = (const float*)d_in[12];

    float* out_move  = (float*)d_out;                       // 64*64*64
    float* out_arrow = (float*)d_out + 64 * 64 * 64;        // 64*4096*64

    constexpr int SMEM_MAIN = 98304;
    cudaFuncSetAttribute(main_kernel, cudaFuncAttributeMaxDynamicSharedMemorySize,
                         SMEM_MAIN);

    proj_kernel<<<dim3(3, 64), 256>>>(x, w_src, b_src, w_dst, b_dst, w_arr, b_arr);
    w2img_kernel<<<128, 256>>>(w2);
    stage2_kernel<<<384, 256>>>(w1, b1, w3, b3, out_move);
    main_kernel<<<dim3(32, 64), 256, SMEM_MAIN>>>(b2, out_arrow);
}

// round 12
// speedup vs baseline: 4.1677x; 1.0992x over previous
#include <cuda_runtime.h>
#include <cuda_fp16.h>
#include <cstdint>

// ---------------- problem constants ----------------
#define BB 64
#define CC 256
#define DD 128
#define NN 64
#define HH 256
#define SCALE_V 0.08838834764831845f   // 1/sqrt(128)

// ---------------- device scratch ----------------
__device__ float g_farr[BB][DD][NN];     // f_arr (fp32, exact G/cv path)
__device__ float g_cv[BB][NN];           // c[b][k] = sum_p b3[p]*f_arr[b][p][k]
// fp16 images
__device__ __align__(16) __half g_ft[2][BB][NN][DD];    // f_src/f_dst transposed
__device__ __align__(16) __half g_w1h[HH][HH];          // w1 fp16 [h][2d]
__device__ __align__(16) __half g_srcp_h[BB][NN][HH];   // src_p (+b1), fp16
__device__ __align__(16) __half g_dstp_h[BB][NN][HH];   // dst_p, fp16
__device__ __align__(16) __half g_w2h[32768];           // [o(128)][h(256)]
__device__ __align__(16) __half g_Gh[BB * 8192];        // [b][k_out(64)][o(128)]

// ---------------- helpers ----------------
__device__ __forceinline__ uint32_t smem_u32(const void* p) {
    uint32_t a;
    asm("{ .reg .u64 t; cvta.to.shared.u64 t, %1; cvt.u32.u64 %0, t; }" : "=r"(a) : "l"(p));
    return a;
}
__device__ __forceinline__ void ldmx4(uint32_t r[4], uint32_t addr) {
    asm volatile("ldmatrix.sync.aligned.m8n8.x4.shared.b16 {%0,%1,%2,%3}, [%4];"
                 : "=r"(r[0]), "=r"(r[1]), "=r"(r[2]), "=r"(r[3]) : "r"(addr));
}
__device__ __forceinline__ void mma16816(float c[4], const uint32_t a[4],
                                         uint32_t b0, uint32_t b1) {
    asm volatile(
        "mma.sync.aligned.m16n8k16.row.col.f32.f16.f16.f32 "
        "{%0,%1,%2,%3}, {%4,%5,%6,%7}, {%8,%9}, {%0,%1,%2,%3};"
        : "+f"(c[0]), "+f"(c[1]), "+f"(c[2]), "+f"(c[3])
        : "r"(a[0]), "r"(a[1]), "r"(a[2]), "r"(a[3]), "r"(b0), "r"(b1));
}
__device__ __forceinline__ uint32_t packh2(float x, float y) {
    __half2 h = __floats2half2_rn(x, y);
    return *reinterpret_cast<uint32_t*>(&h);
}
__device__ __forceinline__ uint4 reluadd4(uint4 s, uint4 d) {
    const __half2 zz = __floats2half2_rn(0.f, 0.f);
    const __half2* sh2 = reinterpret_cast<const __half2*>(&s);
    const __half2* dh2 = reinterpret_cast<const __half2*>(&d);
    __half2 t0 = __hmax2(__hadd2(sh2[0], dh2[0]), zz);
    __half2 t1 = __hmax2(__hadd2(sh2[1], dh2[1]), zz);
    __half2 t2 = __hmax2(__hadd2(sh2[2], dh2[2]), zz);
    __half2 t3 = __hmax2(__hadd2(sh2[3], dh2[3]), zz);
    uint4 v;
    v.x = *reinterpret_cast<uint32_t*>(&t0);
    v.y = *reinterpret_cast<uint32_t*>(&t1);
    v.z = *reinterpret_cast<uint32_t*>(&t2);
    v.w = *reinterpret_cast<uint32_t*>(&t3);
    return v;
}

// ============================================================================
// Kernel P: projections. mats 0/1 -> fp16 transposed images; mat 2 -> fp32.
// ============================================================================
__global__ void __launch_bounds__(256) proj_kernel(
    const float* __restrict__ x,
    const float* __restrict__ w_src, const float* __restrict__ b_src,
    const float* __restrict__ w_dst, const float* __restrict__ b_dst,
    const float* __restrict__ w_arr, const float* __restrict__ b_arr)
{
    const int mat = blockIdx.x;
    const int b   = blockIdx.y;
    const float* w    = (mat == 0) ? w_src : (mat == 1) ? w_dst : w_arr;
    const float* bias = (mat == 0) ? b_src : (mat == 1) ? b_dst : b_arr;

    __shared__ float Ws[32][DD + 4];
    __shared__ float Xs[32][NN + 4];

    const int tid = threadIdx.x;
    const int tx  = tid & 15;
    const int ty  = tid >> 4;

    float acc[8][4];
#pragma unroll
    for (int i = 0; i < 8; i++)
#pragma unroll
        for (int j = 0; j < 4; j++) acc[i][j] = 0.f;

    const float* xb = x + (size_t)b * CC * NN;

#pragma unroll 1
    for (int c0 = 0; c0 < CC; c0 += 32) {
#pragma unroll
        for (int j = 0; j < 16; j++) {
            int i = tid + 256 * j;
            int d = i >> 5, kk = i & 31;
            Ws[kk][d] = w[d * CC + c0 + kk];
        }
#pragma unroll
        for (int j = 0; j < 8; j++) {
            int i = tid + 256 * j;
            int kk = i >> 6, n = i & 63;
            Xs[kk][n] = xb[(c0 + kk) * NN + n];
        }
        __syncthreads();
#pragma unroll
        for (int kk = 0; kk < 32; kk++) {
            float a[8], xv[4];
#pragma unroll
            for (int i = 0; i < 8; i++) a[i] = Ws[kk][ty * 8 + i];
#pragma unroll
            for (int j = 0; j < 4; j++) xv[j] = Xs[kk][tx * 4 + j];
#pragma unroll
            for (int i = 0; i < 8; i++)
#pragma unroll
                for (int j = 0; j < 4; j++) acc[i][j] += a[i] * xv[j];
        }
        __syncthreads();
    }

    float bd[8];
#pragma unroll
    for (int i = 0; i < 8; i++) bd[i] = bias[ty * 8 + i];

    if (mat < 2) {
        __half* ft = &g_ft[mat][b][0][0];
#pragma unroll
        for (int j = 0; j < 4; j++) {
            int n = tx * 4 + j;
            uint4 v;
            v.x = packh2(acc[0][j] + bd[0], acc[1][j] + bd[1]);
            v.y = packh2(acc[2][j] + bd[2], acc[3][j] + bd[3]);
            v.z = packh2(acc[4][j] + bd[4], acc[5][j] + bd[5]);
            v.w = packh2(acc[6][j] + bd[6], acc[7][j] + bd[7]);
            *reinterpret_cast<uint4*>(&ft[n * DD + ty * 8]) = v;
        }
    } else {
        float* out = &g_farr[b][0][0];
#pragma unroll
        for (int i = 0; i < 8; i++) {
            int d = ty * 8 + i;
            float4 v = make_float4(acc[i][0] + bd[i], acc[i][1] + bd[i],
                                   acc[i][2] + bd[i], acc[i][3] + bd[i]);
            *reinterpret_cast<float4*>(&out[d * NN + tx * 4]) = v;
        }
    }
}

// ============================================================================
// Prep: w2 -> fp16 (blocks 0..127), w1 -> fp16 (blocks 128..255)
// ============================================================================
__global__ void img_kernel(const float* __restrict__ w2,
                           const float* __restrict__ w1)
{
    int blk = blockIdx.x, tid = threadIdx.x;
    if (blk < 128) {
        int idx = blk * 256 + tid;                 // 32768 elems
        g_w2h[idx] = __float2half_rn(w2[idx]);
    } else {
        int base = (blk - 128) * 512 + tid;        // 65536 elems, 2/thread
        __half* w1h = &g_w1h[0][0];
        w1h[base]       = __float2half_rn(w1[base]);
        w1h[base + 256] = __float2half_rn(w1[base + 256]);
    }
}

// ============================================================================
// Stage-2: sp via HMMA (0..127) | move via HMMA (128..191) | g fp32 (192..255)
// ============================================================================

// sp: srcp^T[n][h] = f_t[type][b][n][d] @ w1[h][type*128+d], +b1 (type 0).
// M=64(n), N=256(h), K=128(d). smem: A [2kd][64][128B] @0, B [2kd][256][128B] @16384.
__device__ void sp_mma(char* smc, int type, int b, const float* __restrict__ b1)
{
    __shared__ float s_b1[256];
    const uint32_t sb = smem_u32(smc);
    const int tid = threadIdx.x, wid = tid >> 5, lane = tid & 31;

#pragma unroll
    for (int t = 0; t < 4; t++) {
        int i = tid + 256 * t;                     // 0..1023
        int n = i >> 4, g = i & 15, kd = g >> 3, cg = g & 7;
        uint4 v = *reinterpret_cast<const uint4*>(&g_ft[type][b][n][g * 8]);
        *reinterpret_cast<uint4*>(smc + kd * 8192 + n * 128 +
                                  ((cg ^ (n & 7)) << 4)) = v;
    }
#pragma unroll
    for (int t = 0; t < 16; t++) {
        int i = tid + 256 * t;                     // 0..4095
        int h = i >> 4, g = i & 15, kd = g >> 3, cg = g & 7;
        uint4 v = *reinterpret_cast<const uint4*>(&g_w1h[h][type * 128 + g * 8]);
        *reinterpret_cast<uint4*>(smc + 16384 + kd * 32768 + h * 128 +
                                  ((cg ^ (h & 7)) << 4)) = v;
    }
    s_b1[tid] = (type == 0) ? b1[tid] : 0.f;
    __syncthreads();

    const int im = wid & 3, ih = wid >> 2;
    const int rowinm = lane & 7, mi = lane >> 3;
    const int a_kx = mi >> 1, a_rl = ((mi & 1) << 3) + rowinm;
    const int b_rl = ((mi >> 1) << 3) + rowinm, b_sw = rowinm, b_kx = mi & 1;
    const int a_r = im * 16 + a_rl;

    float c[16][4];
#pragma unroll
    for (int i = 0; i < 16; i++)
#pragma unroll
        for (int j = 0; j < 4; j++) c[i][j] = 0.f;

#pragma unroll
    for (int ks = 0; ks < 8; ks++) {
        int kd = ks >> 2, ksl = ks & 3;
        uint32_t aH[4];
        ldmx4(aH, sb + (uint32_t)(kd * 8192 + a_r * 128 +
                                  (((ksl * 2 + a_kx) ^ (a_r & 7)) << 4)));
        uint32_t kco = (uint32_t)(((ksl * 2 + b_kx) ^ b_sw) << 4);
        uint32_t bbase = sb + (uint32_t)(16384 + kd * 32768);
#pragma unroll
        for (int q = 0; q < 8; q++) {
            uint32_t bh[4];
            ldmx4(bh, bbase + (uint32_t)((ih * 128 + q * 16 + b_rl) * 128) + kco);
            mma16816(c[2 * q],     aH, bh[0], bh[1]);
            mma16816(c[2 * q + 1], aH, bh[2], bh[3]);
        }
    }

    const int ccol = (lane & 3) * 2;
    __half* tgt = type ? &g_dstp_h[b][0][0] : &g_srcp_h[b][0][0];
    const int n0 = im * 16 + (lane >> 2);
#pragma unroll
    for (int nt = 0; nt < 16; nt++) {
        int h = ih * 128 + nt * 8 + ccol;
        float bv0 = s_b1[h], bv1 = s_b1[h + 1];
        *reinterpret_cast<uint32_t*>(&tgt[n0 * HH + h]) =
            packh2(c[nt][0] + bv0, c[nt][1] + bv1);
        *reinterpret_cast<uint32_t*>(&tgt[(n0 + 8) * HH + h]) =
            packh2(c[nt][2] + bv0, c[nt][3] + bv1);
    }
}

// move: move[n][m] = scale * f_src^T[n][d] . f_dst^T[m][d]. M=64, N=64, K=128.
__device__ void move_mma(char* smc, int b, float* __restrict__ out_move)
{
    const uint32_t sb = smem_u32(smc);
    const int tid = threadIdx.x, wid = tid >> 5, lane = tid & 31;

#pragma unroll
    for (int t = 0; t < 4; t++) {
        int i = tid + 256 * t;                     // 0..1023
        int n = i >> 4, g = i & 15, kd = g >> 3, cg = g & 7;
        uint32_t off = (uint32_t)(kd * 8192 + n * 128 + ((cg ^ (n & 7)) << 4));
        *reinterpret_cast<uint4*>(smc + off) =
            *reinterpret_cast<const uint4*>(&g_ft[0][b][n][g * 8]);
        *reinterpret_cast<uint4*>(smc + 16384 + off) =
            *reinterpret_cast<const uint4*>(&g_ft[1][b][n][g * 8]);
    }
    __syncthreads();

    const int im = wid & 3, in = wid >> 2;
    const int rowinm = lane & 7, mi = lane >> 3;
    const int a_kx = mi >> 1, a_rl = ((mi & 1) << 3) + rowinm;
    const int b_rl = ((mi >> 1) << 3) + rowinm, b_sw = rowinm, b_kx = mi & 1;
    const int a_r = im * 16 + a_rl;

    float c[4][4];
#pragma unroll
    for (int i = 0; i < 4; i++)
#pragma unroll
        for (int j = 0; j < 4; j++) c[i][j] = 0.f;

#pragma unroll
    for (int ks = 0; ks < 8; ks++) {
        int kd = ks >> 2, ksl = ks & 3;
        uint32_t aH[4];
        ldmx4(aH, sb + (uint32_t)(kd * 8192 + a_r * 128 +
                                  (((ksl * 2 + a_kx) ^ (a_r & 7)) << 4)));
        uint32_t kco = (uint32_t)(((ksl * 2 + b_kx) ^ b_sw) << 4);
#pragma unroll
        for (int q = 0; q < 2; q++) {
            uint32_t bh[4];
            ldmx4(bh, sb + (uint32_t)(16384 + kd * 8192 +
                                      (in * 32 + q * 16 + b_rl) * 128) + kco);
            mma16816(c[2 * q],     aH, bh[0], bh[1]);
            mma16816(c[2 * q + 1], aH, bh[2], bh[3]);
        }
    }

    const int ccol = (lane & 3) * 2;
    const int n0 = im * 16 + (lane >> 2);
#pragma unroll
    for (int nt = 0; nt < 4; nt++) {
        int m = in * 32 + nt * 8 + ccol;
        *reinterpret_cast<float2*>(&out_move[(b * NN + n0) * NN + m]) =
            make_float2(c[nt][0] * SCALE_V, c[nt][1] * SCALE_V);
        *reinterpret_cast<float2*>(&out_move[(b * NN + n0 + 8) * NN + m]) =
            make_float2(c[nt][2] * SCALE_V, c[nt][3] * SCALE_V);
    }
}

// g: fp32 exact fold of w3/b3 into f_arr -> g_Gh (fp16), g_cv (fp32)
__device__ void g_body(float* sh, int b, const float* __restrict__ w3,
                       const float* __restrict__ b3)
{
    float (*W3s)[132] = reinterpret_cast<float(*)[132]>(sh);          // 32x132
    float (*Fs)[68]   = reinterpret_cast<float(*)[68]>(sh + 4224);    // 32x68
    float* b3s        = sh + 4224 + 2176;                             // 32
    const int tid = threadIdx.x;
    const int tx  = tid & 15;
    const int ty  = tid >> 4;

    float acc[8][4];
    float cacc[4] = {0.f, 0.f, 0.f, 0.f};
#pragma unroll
    for (int i = 0; i < 8; i++)
#pragma unroll
        for (int j = 0; j < 4; j++) acc[i][j] = 0.f;

#pragma unroll 1
    for (int p0 = 0; p0 < DD; p0 += 32) {
#pragma unroll
        for (int j = 0; j < 16; j++) {
            int i = tid + 256 * j;
            int kk = i >> 7, o = i & 127;
            W3s[kk][o] = w3[(p0 + kk) * DD + o];
        }
#pragma unroll
        for (int j = 0; j < 8; j++) {
            int i = tid + 256 * j;
            int kk = i >> 6, k = i & 63;
            Fs[kk][k] = g_farr[b][p0 + kk][k];
        }
        if (tid < 32) b3s[tid] = b3[p0 + tid];
        __syncthreads();
#pragma unroll
        for (int kk = 0; kk < 32; kk++) {
            float wv[8], fv[4];
#pragma unroll
            for (int i = 0; i < 8; i++) wv[i] = W3s[kk][ty * 8 + i];
#pragma unroll
            for (int j = 0; j < 4; j++) fv[j] = Fs[kk][tx * 4 + j];
#pragma unroll
            for (int i = 0; i < 8; i++)
#pragma unroll
                for (int j = 0; j < 4; j++) acc[i][j] += wv[i] * fv[j];
            if (ty == 0) {
                float bvv = b3s[kk];
#pragma unroll
                for (int j = 0; j < 4; j++) cacc[j] += bvv * fv[j];
            }
        }
        __syncthreads();
    }
#pragma unroll
    for (int i = 0; i < 8; i++) {
        int o = ty * 8 + i;
#pragma unroll
        for (int j = 0; j < 4; j++) {
            int k = tx * 4 + j;
            g_Gh[b * 8192 + k * 128 + o] = __float2half_rn(acc[i][j]);
        }
    }
    if (ty == 0) {
        float4 v = make_float4(cacc[0], cacc[1], cacc[2], cacc[3]);
        *reinterpret_cast<float4*>(&g_cv[b][tx * 4]) = v;
    }
}

__global__ void __launch_bounds__(256) stage2_kernel(
    const float* __restrict__ b1,
    const float* __restrict__ w3, const float* __restrict__ b3,
    float* __restrict__ out_move)
{
    extern __shared__ char s2[];
    const int bid = blockIdx.x;
    if (bid < 128)      sp_mma(s2, bid & 1, bid >> 1, b1);
    else if (bid < 192) move_mma(s2, bid - 128, out_move);
    else                g_body(reinterpret_cast<float*>(s2), bid - 192, w3, b3);
}

// ============================================================================
// Main (hot): unchanged from R10 (bit-identical path).
// ============================================================================
__global__ void __launch_bounds__(256, 2) main_kernel(
    const float* __restrict__ b2, float* __restrict__ out_arrow)
{
    extern __shared__ char smc[];
    __shared__ float  s_cv[64];
    __shared__ float  s_b2[128];
    __shared__ __half s_dst[2][256];

    const uint32_t sb = smem_u32(smc);
    const int tid  = threadIdx.x;
    const int wid  = tid >> 5;
    const int lane = tid & 31;
    const int mt = blockIdx.x, b = blockIdx.y, m0 = mt * 2;

    const int ABUF = 65536;
    const int im = wid & 3;
    const int in = wid >> 2;

    const int rowinm = lane & 7, mi = lane >> 3;
    const int a_kx = mi >> 1;
    const int a_rl = ((mi & 1) << 3) + rowinm;
    const int b_rl = ((mi >> 1) << 3) + rowinm;
    const int b_sw = rowinm;
    const int b_kx = mi & 1;

    const int ag_grp  = tid & 7;
    const int ag_row0 = tid >> 3;

    {
        for (int i = tid; i < 4096; i += 256) {
            int o = i >> 5, grp = i & 31;
            int kc = grp >> 3, cgl = grp & 7;
            const uint4* src = reinterpret_cast<const uint4*>(g_w2h + o * 256 + grp * 8);
            uint32_t dst = (uint32_t)(kc * 16384 + o * 128 + ((cgl ^ (o & 7)) << 4));
            *reinterpret_cast<uint4*>(smc + dst) = *src;
        }
        if (tid < 64)  s_cv[tid] = g_cv[b][tid];
        if (tid < 128) s_b2[tid] = b2[tid];
        if (tid < 64) {
            int lm = tid >> 5, grp = tid & 31;
            *reinterpret_cast<uint4*>(&s_dst[lm][grp * 8]) =
                *reinterpret_cast<const uint4*>(&g_dstp_h[b][m0 + lm][grp * 8]);
        }
#pragma unroll
        for (int j = 0; j < 4; j++) {
            int row = ag_row0 + 32 * j;
            int n = row & 63, lm = row >> 6;
            uint4 s = *reinterpret_cast<const uint4*>(&g_srcp_h[b][n][ag_grp * 8]);
            uint4 d = *reinterpret_cast<const uint4*>(&g_dstp_h[b][m0 + lm][ag_grp * 8]);
            uint4 v = reluadd4(s, d);
            uint32_t off = (uint32_t)(row * 128 + ((ag_grp ^ (row & 7)) << 4));
            *reinterpret_cast<uint4*>(smc + ABUF + off) = v;
        }
    }
    __syncthreads();

    float c1[2][8][4];
#pragma unroll
    for (int m = 0; m < 2; m++)
#pragma unroll
        for (int i = 0; i < 8; i++)
#pragma unroll
            for (int j = 0; j < 4; j++) c1[m][i][j] = 0.f;

#pragma unroll 1
    for (int kc = 0; kc < 4; kc++) {
        const uint32_t curA = sb + (uint32_t)(ABUF + ((kc & 1) << 14));
        const uint32_t wHi  = sb + (uint32_t)(kc * 16384);

        uint4 ps[4];
        if (kc < 3) {
#pragma unroll
            for (int j = 0; j < 4; j++) {
                int row = ag_row0 + 32 * j;
                int n = row & 63;
                ps[j] = *reinterpret_cast<const uint4*>(
                    &g_srcp_h[b][n][(kc + 1) * 64 + ag_grp * 8]);
            }
        } else {
#pragma unroll
            for (int t = 0; t < 4; t++) {
                int i = tid + 256 * t;
                ps[t] = *reinterpret_cast<const uint4*>(
                    &g_Gh[b * 8192 + (i >> 4) * 128 + (i & 15) * 8]);
            }
        }

#pragma unroll
        for (int ks = 0; ks < 2; ks++) {
            uint32_t aH[2][4];
#pragma unroll
            for (int m = 0; m < 2; m++) {
                int a_r = im * 32 + m * 16 + a_rl;
                uint32_t co = (uint32_t)(((ks * 2 + a_kx) ^ (a_r & 7)) << 4);
                ldmx4(aH[m], curA + (uint32_t)(a_r * 128) + co);
            }
            uint32_t kco = (uint32_t)(((ks * 2 + b_kx) ^ b_sw) << 4);
            uint32_t bh[4][4];
#pragma unroll
            for (int q = 0; q < 4; q++) {
                int o_row = in * 64 + q * 16 + b_rl;
                ldmx4(bh[q], wHi + (uint32_t)(o_row * 128) + kco);
            }
#pragma unroll
            for (int q = 0; q < 4; q++)
#pragma unroll
                for (int m = 0; m < 2; m++) {
                    mma16816(c1[m][2 * q],     aH[m], bh[q][0], bh[q][1]);
                    mma16816(c1[m][2 * q + 1], aH[m], bh[q][2], bh[q][3]);
                }
        }

        uint4 pv[4];
        if (kc < 3) {
#pragma unroll
            for (int j = 0; j < 4; j++) {
                int row = ag_row0 + 32 * j;
                int lm = row >> 6;
                uint4 d = *reinterpret_cast<const uint4*>(
                    &s_dst[lm][(kc + 1) * 64 + ag_grp * 8]);
                pv[j] = reluadd4(ps[j], d);
            }
        } else {
#pragma unroll
            for (int t = 0; t < 4; t++) pv[t] = ps[t];
        }

#pragma unroll
        for (int ks = 2; ks < 4; ks++) {
            uint32_t aH[2][4];
#pragma unroll
            for (int m = 0; m < 2; m++) {
                int a_r = im * 32 + m * 16 + a_rl;
                uint32_t co = (uint32_t)(((ks * 2 + a_kx) ^ (a_r & 7)) << 4);
                ldmx4(aH[m], curA + (uint32_t)(a_r * 128) + co);
            }
            uint32_t kco = (uint32_t)(((ks * 2 + b_kx) ^ b_sw) << 4);
            uint32_t bh[4][4];
#pragma unroll
            for (int q = 0; q < 4; q++) {
                int o_row = in * 64 + q * 16 + b_rl;
                ldmx4(bh[q], wHi + (uint32_t)(o_row * 128) + kco);
            }
#pragma unroll
            for (int q = 0; q < 4; q++)
#pragma unroll
                for (int m = 0; m < 2; m++) {
                    mma16816(c1[m][2 * q],     aH[m], bh[q][0], bh[q][1]);
                    mma16816(c1[m][2 * q + 1], aH[m], bh[q][2], bh[q][3]);
                }
        }

        if (kc < 3) {
            char* obuf = smc + ABUF + (((kc + 1) & 1) << 14);
#pragma unroll
            for (int j = 0; j < 4; j++) {
                int row = ag_row0 + 32 * j;
                uint32_t off = (uint32_t)(row * 128 + ((ag_grp ^ (row & 7)) << 4));
                *reinterpret_cast<uint4*>(obuf + off) = pv[j];
            }
        } else {
#pragma unroll
            for (int t = 0; t < 4; t++) {
                int i = tid + 256 * t;
                int r = i >> 4, grp = i & 15;
                int kh = grp >> 3, cgl = grp & 7;
                uint32_t dst = (uint32_t)(ABUF + kh * 8192 + r * 128 +
                                          ((cgl ^ (r & 7)) << 4));
                *reinterpret_cast<uint4*>(smc + dst) = pv[t];
            }
        }
        __syncthreads();
    }

    const int ccol = (lane & 3) * 2;
    uint32_t aH2[2][4][4];
#pragma unroll
    for (int m = 0; m < 2; m++)
#pragma unroll
        for (int ko = 0; ko < 4; ko++) {
#pragma unroll
            for (int hn = 0; hn < 2; hn++) {
                int nt = 2 * ko + hn;
                float bv0 = s_b2[in * 64 + nt * 8 + ccol];
                float bv1 = s_b2[in * 64 + nt * 8 + ccol + 1];
                aH2[m][ko][hn * 2]     = packh2(fmaxf(c1[m][nt][0] + bv0, 0.f),
                                                fmaxf(c1[m][nt][1] + bv1, 0.f));
                aH2[m][ko][hn * 2 + 1] = packh2(fmaxf(c1[m][nt][2] + bv0, 0.f),
                                                fmaxf(c1[m][nt][3] + bv1, 0.f));
            }
        }

    float c2[2][8][4];
#pragma unroll
    for (int m = 0; m < 2; m++)
#pragma unroll
        for (int i = 0; i < 8; i++)
#pragma unroll
            for (int j = 0; j < 4; j++) c2[m][i][j] = 0.f;

    const uint32_t gBase = sb + (uint32_t)(ABUF + in * 8192);
#pragma unroll
    for (int ko = 0; ko < 4; ko++) {
        uint32_t kco = (uint32_t)(((ko * 2 + b_kx) ^ b_sw) << 4);
        uint32_t bh[4][4];
#pragma unroll
        for (int q = 0; q < 4; q++)
            ldmx4(bh[q], gBase + (uint32_t)((q * 16 + b_rl) * 128) + kco);
#pragma unroll
        for (int q = 0; q < 4; q++)
#pragma unroll
            for (int m = 0; m < 2; m++) {
                mma16816(c2[m][2 * q],     aH2[m][ko], bh[q][0], bh[q][1]);
                mma16816(c2[m][2 * q + 1], aH2[m][ko], bh[q][2], bh[q][3]);
            }
    }

    float* rbuf = reinterpret_cast<float*>(smc);
    if (in == 1) {
#pragma unroll
        for (int m = 0; m < 2; m++) {
            int r0 = im * 32 + m * 16 + (lane >> 2);
#pragma unroll
            for (int kt = 0; kt < 8; kt++) {
                int k = kt * 8 + ccol;
                *reinterpret_cast<float2*>(&rbuf[r0 * 72 + k]) =
                    make_float2(c2[m][kt][0], c2[m][kt][1]);
                *reinterpret_cast<float2*>(&rbuf[(r0 + 8) * 72 + k]) =
                    make_float2(c2[m][kt][2], c2[m][kt][3]);
            }
        }
    }
    __syncthreads();
    if (in == 0) {
#pragma unroll
        for (int m = 0; m < 2; m++) {
            int r0 = im * 32 + m * 16 + (lane >> 2);
            int r1 = r0 + 8;
            float* p0 = out_arrow + (((size_t)b * 4096 +
                                      (size_t)(r0 & 63) * 64 + m0 + (r0 >> 6)) << 6);
            float* p1 = out_arrow + (((size_t)b * 4096 +
                                      (size_t)(r1 & 63) * 64 + m0 + (r1 >> 6)) << 6);
#pragma unroll
            for (int kt = 0; kt < 8; kt++) {
                int k = kt * 8 + ccol;
                float2 q0 = *reinterpret_cast<const float2*>(&rbuf[r0 * 72 + k]);
                float2 q1 = *reinterpret_cast<const float2*>(&rbuf[r1 * 72 + k]);
                float cv0 = s_cv[k], cv1 = s_cv[k + 1];
                float2 v0 = make_float2((c2[m][kt][0] + q0.x + cv0) * SCALE_V,
                                        (c2[m][kt][1] + q0.y + cv1) * SCALE_V);
                float2 v1 = make_float2((c2[m][kt][2] + q1.x + cv0) * SCALE_V,
                                        (c2[m][kt][3] + q1.y + cv1) * SCALE_V);
                *reinterpret_cast<float2*>(p0 + k) = v0;
                *reinterpret_cast<float2*>(p1 + k) = v1;
            }
        }
    }
}

// ============================================================================
// launch
// ============================================================================
extern "C" void kernel_launch(void* const* d_in, const int* in_sizes, int n_in,
                              void* d_out, int out_size)
{
    (void)in_sizes; (void)n_in; (void)out_size;
    const float* x     = (const float*)d_in[0];
    const float* w_src = (const float*)d_in[1];
    const float* b_src = (const float*)d_in[2];
    const float* w_dst = (const float*)d_in[3];
    const float* b_dst = (const float*)d_in[4];
    const float* w_arr = (const float*)d_in[5];
    const float* b_arr = (const float*)d_in[6];
    const float* w1    = (const float*)d_in[7];
    const float* b1    = (const float*)d_in[8];
    const float* w2    = (const float*)d_in[9];
    const float* b2    = (const float*)d_in[10];
    const float* w3    = (const float*)d_in[11];
    const float* b3    = (const float*)d_in[12];

    float* out_move  = (float*)d_out;                       // 64*64*64
    float* out_arrow = (float*)d_out + 64 * 64 * 64;        // 64*4096*64

    constexpr int SMEM_MAIN = 98304;
    constexpr int SMEM_S2   = 81920;
    cudaFuncSetAttribute(main_kernel, cudaFuncAttributeMaxDynamicSharedMemorySize,
                         SMEM_MAIN);
    cudaFuncSetAttribute(stage2_kernel, cudaFuncAttributeMaxDynamicSharedMemorySize,
                         SMEM_S2);

    img_kernel<<<256, 256>>>(w2, w1);
    proj_kernel<<<dim3(3, 64), 256>>>(x, w_src, b_src, w_dst, b_dst, w_arr, b_arr);
    stage2_kernel<<<256, 256, SMEM_S2>>>(b1, w3, b3, out_move);
    main_kernel<<<dim3(32, 64), 256, SMEM_MAIN>>>(b2, out_arrow);
}

// round 13
// speedup vs baseline: 4.5625x; 1.0947x over previous
#include <cuda_runtime.h>
#include <cuda_fp16.h>
#include <cstdint>

// ---------------- problem constants ----------------
#define BB 64
#define CC 256
#define DD 128
#define NN 64
#define HH 256
#define SCALE_V 0.08838834764831845f   // 1/sqrt(128)

// ---------------- device scratch ----------------
__device__ float g_farr[BB][DD][NN];     // f_arr (fp32, exact cv path)
__device__ float g_cv[BB][NN];           // c[b][k]
// fp16 images
__device__ __align__(16) __half g_ft[2][BB][NN][DD];    // f_src/f_dst transposed
__device__ __align__(16) __half g_w1h[HH][HH];          // w1 fp16 [h][2d]
__device__ __align__(16) __half g_w3t[DD * DD];         // w3^T fp16 [o][p]
__device__ __align__(16) __half g_srcp_h[BB][NN][HH];   // src_p (+b1), fp16
__device__ __align__(16) __half g_dstp_h[BB][NN][HH];   // dst_p, fp16
__device__ __align__(16) __half g_w2h[32768];           // [o(128)][h(256)]
__device__ __align__(16) __half g_Gh[BB * 8192];        // [b][k_out(64)][o(128)]

// ---------------- helpers ----------------
__device__ __forceinline__ uint32_t smem_u32(const void* p) {
    uint32_t a;
    asm("{ .reg .u64 t; cvta.to.shared.u64 t, %1; cvt.u32.u64 %0, t; }" : "=r"(a) : "l"(p));
    return a;
}
__device__ __forceinline__ void ldmx4(uint32_t r[4], uint32_t addr) {
    asm volatile("ldmatrix.sync.aligned.m8n8.x4.shared.b16 {%0,%1,%2,%3}, [%4];"
                 : "=r"(r[0]), "=r"(r[1]), "=r"(r[2]), "=r"(r[3]) : "r"(addr));
}
__device__ __forceinline__ void mma16816(float c[4], const uint32_t a[4],
                                         uint32_t b0, uint32_t b1) {
    asm volatile(
        "mma.sync.aligned.m16n8k16.row.col.f32.f16.f16.f32 "
        "{%0,%1,%2,%3}, {%4,%5,%6,%7}, {%8,%9}, {%0,%1,%2,%3};"
        : "+f"(c[0]), "+f"(c[1]), "+f"(c[2]), "+f"(c[3])
        : "r"(a[0]), "r"(a[1]), "r"(a[2]), "r"(a[3]), "r"(b0), "r"(b1));
}
__device__ __forceinline__ uint32_t packh2(float x, float y) {
    __half2 h = __floats2half2_rn(x, y);
    return *reinterpret_cast<uint32_t*>(&h);
}
__device__ __forceinline__ uint4 reluadd4(uint4 s, uint4 d) {
    const __half2 zz = __floats2half2_rn(0.f, 0.f);
    const __half2* sh2 = reinterpret_cast<const __half2*>(&s);
    const __half2* dh2 = reinterpret_cast<const __half2*>(&d);
    __half2 t0 = __hmax2(__hadd2(sh2[0], dh2[0]), zz);
    __half2 t1 = __hmax2(__hadd2(sh2[1], dh2[1]), zz);
    __half2 t2 = __hmax2(__hadd2(sh2[2], dh2[2]), zz);
    __half2 t3 = __hmax2(__hadd2(sh2[3], dh2[3]), zz);
    uint4 v;
    v.x = *reinterpret_cast<uint32_t*>(&t0);
    v.y = *reinterpret_cast<uint32_t*>(&t1);
    v.z = *reinterpret_cast<uint32_t*>(&t2);
    v.w = *reinterpret_cast<uint32_t*>(&t3);
    return v;
}

// ============================================================================
// prep_kernel bodies
// ============================================================================

// HMMA projection for f_src / f_dst: C[n][d] = x^T[n][c] @ w[d][c], +bias -> fp16
// M=64(n), N=128(d), K=256(c). smem: A [4kd][64n][128B] @0, B [4kd][128d][128B] @32768.
__device__ void proj_mma(char* smc, int mat, int b,
                         const float* __restrict__ x,
                         const float* __restrict__ w,
                         const float* __restrict__ bias)
{
    __shared__ float s_bias[128];
    const uint32_t sb = smem_u32(smc);
    const int tid = threadIdx.x, wid = tid >> 5, lane = tid & 31;

    // A tiles: x^T fp16 swizzled
    {
        const float* xb = x + (size_t)b * CC * NN;
#pragma unroll
        for (int t = 0; t < 16; t++) {
            int i = tid + 256 * t;                 // 0..4095 float4 over n
            int c = i >> 4, n0 = (i & 15) * 4;
            float4 v = *reinterpret_cast<const float4*>(&xb[c * 64 + n0]);
            int kd = c >> 6, cl = c & 63;
            float vv[4] = {v.x, v.y, v.z, v.w};
#pragma unroll
            for (int j = 0; j < 4; j++) {
                int n = n0 + j;
                uint32_t addr = (uint32_t)(kd * 8192 + n * 128 +
                                ((((cl >> 3) ^ (n & 7)) << 4) | ((cl * 2) & 15)));
                *reinterpret_cast<__half*>(smc + addr) = __float2half_rn(vv[j]);
            }
        }
    }
    // B tiles: w fp16 swizzled (converted on the fly)
    {
#pragma unroll
        for (int t = 0; t < 64; t++) {
            int i = tid + 256 * t;                 // 0..16383 float2 pairs
            int d = i >> 7, c2 = i & 127;
            float2 v = *reinterpret_cast<const float2*>(&w[d * 256 + c2 * 2]);
            int c = c2 * 2, kd = c >> 6, cl = c & 63;
            uint32_t addr = (uint32_t)(32768 + kd * 16384 + d * 128 +
                            ((((cl >> 3) ^ (d & 7)) << 4) | ((cl * 2) & 15)));
            *reinterpret_cast<uint32_t*>(smc + addr) = packh2(v.x, v.y);
        }
    }
    if (tid < 128) s_bias[tid] = bias[tid];
    __syncthreads();

    const int im = wid & 3, ih = wid >> 2;
    const int rowinm = lane & 7, mi = lane >> 3;
    const int a_kx = mi >> 1, a_rl = ((mi & 1) << 3) + rowinm;
    const int b_rl = ((mi >> 1) << 3) + rowinm, b_sw = rowinm, b_kx = mi & 1;
    const int a_r = im * 16 + a_rl;

    float c[8][4];
#pragma unroll
    for (int i = 0; i < 8; i++)
#pragma unroll
        for (int j = 0; j < 4; j++) c[i][j] = 0.f;

#pragma unroll
    for (int ks = 0; ks < 16; ks++) {
        int kd = ks >> 2, ksl = ks & 3;
        uint32_t aH[4];
        ldmx4(aH, sb + (uint32_t)(kd * 8192 + a_r * 128 +
                                  (((ksl * 2 + a_kx) ^ (a_r & 7)) << 4)));
        uint32_t kco = (uint32_t)(((ksl * 2 + b_kx) ^ b_sw) << 4);
#pragma unroll
        for (int q = 0; q < 4; q++) {
            uint32_t bh[4];
            ldmx4(bh, sb + (uint32_t)(32768 + kd * 16384 +
                                      (ih * 64 + q * 16 + b_rl) * 128) + kco);
            mma16816(c[2 * q],     aH, bh[0], bh[1]);
            mma16816(c[2 * q + 1], aH, bh[2], bh[3]);
        }
    }

    const int ccol = (lane & 3) * 2;
    __half* tgt = &g_ft[mat][b][0][0];
    const int n0 = im * 16 + (lane >> 2);
#pragma unroll
    for (int nt = 0; nt < 8; nt++) {
        int d = ih * 64 + nt * 8 + ccol;
        float bv0 = s_bias[d], bv1 = s_bias[d + 1];
        *reinterpret_cast<uint32_t*>(&tgt[n0 * DD + d]) =
            packh2(c[nt][0] + bv0, c[nt][1] + bv1);
        *reinterpret_cast<uint32_t*>(&tgt[(n0 + 8) * DD + d]) =
            packh2(c[nt][2] + bv0, c[nt][3] + bv1);
    }
}

// exact fp32 projection for f_arr -> g_farr [d][n]
__device__ void proj_f32(float* sh, int b,
                         const float* __restrict__ x,
                         const float* __restrict__ w,
                         const float* __restrict__ bias)
{
    float (*Ws)[132] = reinterpret_cast<float(*)[132]>(sh);          // 32x132
    float (*Xs)[68]  = reinterpret_cast<float(*)[68]>(sh + 4224);    // 32x68
    const int tid = threadIdx.x;
    const int tx  = tid & 15;
    const int ty  = tid >> 4;

    float acc[8][4];
#pragma unroll
    for (int i = 0; i < 8; i++)
#pragma unroll
        for (int j = 0; j < 4; j++) acc[i][j] = 0.f;

    const float* xb = x + (size_t)b * CC * NN;

#pragma unroll 1
    for (int c0 = 0; c0 < CC; c0 += 32) {
#pragma unroll
        for (int j = 0; j < 16; j++) {
            int i = tid + 256 * j;
            int d = i >> 5, kk = i & 31;
            Ws[kk][d] = w[d * CC + c0 + kk];
        }
#pragma unroll
        for (int j = 0; j < 8; j++) {
            int i = tid + 256 * j;
            int kk = i >> 6, n = i & 63;
            Xs[kk][n] = xb[(c0 + kk) * NN + n];
        }
        __syncthreads();
#pragma unroll
        for (int kk = 0; kk < 32; kk++) {
            float a[8], xv[4];
#pragma unroll
            for (int i = 0; i < 8; i++) a[i] = Ws[kk][ty * 8 + i];
#pragma unroll
            for (int j = 0; j < 4; j++) xv[j] = Xs[kk][tx * 4 + j];
#pragma unroll
            for (int i = 0; i < 8; i++)
#pragma unroll
                for (int j = 0; j < 4; j++) acc[i][j] += a[i] * xv[j];
        }
        __syncthreads();
    }

    float* out = &g_farr[b][0][0];
#pragma unroll
    for (int i = 0; i < 8; i++) {
        int d = ty * 8 + i;
        float bv = bias[d];
        float4 v = make_float4(acc[i][0] + bv, acc[i][1] + bv,
                               acc[i][2] + bv, acc[i][3] + bv);
        *reinterpret_cast<float4*>(&out[d * NN + tx * 4]) = v;
    }
}

__global__ void __launch_bounds__(256) prep_kernel(
    const float* __restrict__ x,
    const float* __restrict__ w_src, const float* __restrict__ b_src,
    const float* __restrict__ w_dst, const float* __restrict__ b_dst,
    const float* __restrict__ w_arr, const float* __restrict__ b_arr,
    const float* __restrict__ w1, const float* __restrict__ w2,
    const float* __restrict__ w3)
{
    extern __shared__ char smc[];
    const int bid = blockIdx.x, tid = threadIdx.x;
    if (bid < 128) {
        int mat = bid >> 6, b = bid & 63;
        proj_mma(smc, mat, b, x, mat ? w_dst : w_src, mat ? b_dst : b_src);
    } else if (bid < 192) {
        proj_f32(reinterpret_cast<float*>(smc), bid - 128, x, w_arr, b_arr);
    } else if (bid < 320) {
        int idx = (bid - 192) * 256 + tid;                // 32768 elems
        g_w2h[idx] = __float2half_rn(w2[idx]);
    } else if (bid < 448) {
        int base = (bid - 320) * 512 + tid;               // 65536 elems
        __half* w1h = &g_w1h[0][0];
        w1h[base]       = __float2half_rn(w1[base]);
        w1h[base + 256] = __float2half_rn(w1[base + 256]);
    } else {
        int idx = (bid - 448) * 256 + tid;                // 16384 elems
        int o = idx >> 7, p = idx & 127;
        g_w3t[o * 128 + p] = __float2half_rn(w3[p * 128 + o]);
    }
}

// ============================================================================
// Stage-2: sp HMMA (0..127) | move HMMA (128..191) | g HMMA (192..255)
// ============================================================================

// sp: srcp^T[n][h] = f_t[type][b][n][d] @ w1[h][type*128+d], +b1 (type 0).
__device__ void sp_mma(char* smc, int type, int b, const float* __restrict__ b1)
{
    __shared__ float s_b1[256];
    const uint32_t sb = smem_u32(smc);
    const int tid = threadIdx.x, wid = tid >> 5, lane = tid & 31;

#pragma unroll
    for (int t = 0; t < 4; t++) {
        int i = tid + 256 * t;                     // 0..1023
        int n = i >> 4, g = i & 15, kd = g >> 3, cg = g & 7;
        uint4 v = *reinterpret_cast<const uint4*>(&g_ft[type][b][n][g * 8]);
        *reinterpret_cast<uint4*>(smc + kd * 8192 + n * 128 +
                                  ((cg ^ (n & 7)) << 4)) = v;
    }
#pragma unroll
    for (int t = 0; t < 16; t++) {
        int i = tid + 256 * t;                     // 0..4095
        int h = i >> 4, g = i & 15, kd = g >> 3, cg = g & 7;
        uint4 v = *reinterpret_cast<const uint4*>(&g_w1h[h][type * 128 + g * 8]);
        *reinterpret_cast<uint4*>(smc + 16384 + kd * 32768 + h * 128 +
                                  ((cg ^ (h & 7)) << 4)) = v;
    }
    s_b1[tid] = (type == 0) ? b1[tid] : 0.f;
    __syncthreads();

    const int im = wid & 3, ih = wid >> 2;
    const int rowinm = lane & 7, mi = lane >> 3;
    const int a_kx = mi >> 1, a_rl = ((mi & 1) << 3) + rowinm;
    const int b_rl = ((mi >> 1) << 3) + rowinm, b_sw = rowinm, b_kx = mi & 1;
    const int a_r = im * 16 + a_rl;

    float c[16][4];
#pragma unroll
    for (int i = 0; i < 16; i++)
#pragma unroll
        for (int j = 0; j < 4; j++) c[i][j] = 0.f;

#pragma unroll
    for (int ks = 0; ks < 8; ks++) {
        int kd = ks >> 2, ksl = ks & 3;
        uint32_t aH[4];
        ldmx4(aH, sb + (uint32_t)(kd * 8192 + a_r * 128 +
                                  (((ksl * 2 + a_kx) ^ (a_r & 7)) << 4)));
        uint32_t kco = (uint32_t)(((ksl * 2 + b_kx) ^ b_sw) << 4);
        uint32_t bbase = sb + (uint32_t)(16384 + kd * 32768);
#pragma unroll
        for (int q = 0; q < 8; q++) {
            uint32_t bh[4];
            ldmx4(bh, bbase + (uint32_t)((ih * 128 + q * 16 + b_rl) * 128) + kco);
            mma16816(c[2 * q],     aH, bh[0], bh[1]);
            mma16816(c[2 * q + 1], aH, bh[2], bh[3]);
        }
    }

    const int ccol = (lane & 3) * 2;
    __half* tgt = type ? &g_dstp_h[b][0][0] : &g_srcp_h[b][0][0];
    const int n0 = im * 16 + (lane >> 2);
#pragma unroll
    for (int nt = 0; nt < 16; nt++) {
        int h = ih * 128 + nt * 8 + ccol;
        float bv0 = s_b1[h], bv1 = s_b1[h + 1];
        *reinterpret_cast<uint32_t*>(&tgt[n0 * HH + h]) =
            packh2(c[nt][0] + bv0, c[nt][1] + bv1);
        *reinterpret_cast<uint32_t*>(&tgt[(n0 + 8) * HH + h]) =
            packh2(c[nt][2] + bv0, c[nt][3] + bv1);
    }
}

// move: move[n][m] = scale * f_src^T[n][d] . f_dst^T[m][d].
__device__ void move_mma(char* smc, int b, float* __restrict__ out_move)
{
    const uint32_t sb = smem_u32(smc);
    const int tid = threadIdx.x, wid = tid >> 5, lane = tid & 31;

#pragma unroll
    for (int t = 0; t < 4; t++) {
        int i = tid + 256 * t;                     // 0..1023
        int n = i >> 4, g = i & 15, kd = g >> 3, cg = g & 7;
        uint32_t off = (uint32_t)(kd * 8192 + n * 128 + ((cg ^ (n & 7)) << 4));
        *reinterpret_cast<uint4*>(smc + off) =
            *reinterpret_cast<const uint4*>(&g_ft[0][b][n][g * 8]);
        *reinterpret_cast<uint4*>(smc + 16384 + off) =
            *reinterpret_cast<const uint4*>(&g_ft[1][b][n][g * 8]);
    }
    __syncthreads();

    const int im = wid & 3, in = wid >> 2;
    const int rowinm = lane & 7, mi = lane >> 3;
    const int a_kx = mi >> 1, a_rl = ((mi & 1) << 3) + rowinm;
    const int b_rl = ((mi >> 1) << 3) + rowinm, b_sw = rowinm, b_kx = mi & 1;
    const int a_r = im * 16 + a_rl;

    float c[4][4];
#pragma unroll
    for (int i = 0; i < 4; i++)
#pragma unroll
        for (int j = 0; j < 4; j++) c[i][j] = 0.f;

#pragma unroll
    for (int ks = 0; ks < 8; ks++) {
        int kd = ks >> 2, ksl = ks & 3;
        uint32_t aH[4];
        ldmx4(aH, sb + (uint32_t)(kd * 8192 + a_r * 128 +
                                  (((ksl * 2 + a_kx) ^ (a_r & 7)) << 4)));
        uint32_t kco = (uint32_t)(((ksl * 2 + b_kx) ^ b_sw) << 4);
#pragma unroll
        for (int q = 0; q < 2; q++) {
            uint32_t bh[4];
            ldmx4(bh, sb + (uint32_t)(16384 + kd * 8192 +
                                      (in * 32 + q * 16 + b_rl) * 128) + kco);
            mma16816(c[2 * q],     aH, bh[0], bh[1]);
            mma16816(c[2 * q + 1], aH, bh[2], bh[3]);
        }
    }

    const int ccol = (lane & 3) * 2;
    const int n0 = im * 16 + (lane >> 2);
#pragma unroll
    for (int nt = 0; nt < 4; nt++) {
        int m = in * 32 + nt * 8 + ccol;
        *reinterpret_cast<float2*>(&out_move[(b * NN + n0) * NN + m]) =
            make_float2(c[nt][0] * SCALE_V, c[nt][1] * SCALE_V);
        *reinterpret_cast<float2*>(&out_move[(b * NN + n0 + 8) * NN + m]) =
            make_float2(c[nt][2] * SCALE_V, c[nt][3] * SCALE_V);
    }
}

// g: G^T[k][o] = f_arr^T[k][p] @ w3t[o][p]  (HMMA), cv exact fp32.
// smem: A [2kd][64k][128B] @0, B [2kd][128o][128B] @16384.
__device__ void g_mma(char* smc, int b, const float* __restrict__ b3)
{
    const uint32_t sb = smem_u32(smc);
    const int tid = threadIdx.x, wid = tid >> 5, lane = tid & 31;

    // A: transpose-convert g_farr [p][k] -> fp16 [kd][k][pl]
#pragma unroll
    for (int t = 0; t < 32; t++) {
        int i = tid + 256 * t;                     // 0..8191
        int p = i >> 6, k = i & 63;
        float v = g_farr[b][p][k];
        int kd = p >> 6, pl = p & 63;
        uint32_t addr = (uint32_t)(kd * 8192 + k * 128 +
                        ((((pl >> 3) ^ (k & 7)) << 4) | ((pl * 2) & 15)));
        *reinterpret_cast<__half*>(smc + addr) = __float2half_rn(v);
    }
    // B: w3t
#pragma unroll
    for (int t = 0; t < 8; t++) {
        int i = tid + 256 * t;                     // 0..2047 uint4
        int o = i >> 4, g = i & 15, kd = g >> 3, cg = g & 7;
        uint4 v = *reinterpret_cast<const uint4*>(&g_w3t[o * 128 + g * 8]);
        *reinterpret_cast<uint4*>(smc + 16384 + kd * 16384 + o * 128 +
                                  ((cg ^ (o & 7)) << 4)) = v;
    }
    __syncthreads();

    const int im = wid & 3, ih = wid >> 2;
    const int rowinm = lane & 7, mi = lane >> 3;
    const int a_kx = mi >> 1, a_rl = ((mi & 1) << 3) + rowinm;
    const int b_rl = ((mi >> 1) << 3) + rowinm, b_sw = rowinm, b_kx = mi & 1;
    const int a_r = im * 16 + a_rl;

    float c[8][4];
#pragma unroll
    for (int i = 0; i < 8; i++)
#pragma unroll
        for (int j = 0; j < 4; j++) c[i][j] = 0.f;

#pragma unroll
    for (int ks = 0; ks < 8; ks++) {
        int kd = ks >> 2, ksl = ks & 3;
        uint32_t aH[4];
        ldmx4(aH, sb + (uint32_t)(kd * 8192 + a_r * 128 +
                                  (((ksl * 2 + a_kx) ^ (a_r & 7)) << 4)));
        uint32_t kco = (uint32_t)(((ksl * 2 + b_kx) ^ b_sw) << 4);
#pragma unroll
        for (int q = 0; q < 4; q++) {
            uint32_t bh[4];
            ldmx4(bh, sb + (uint32_t)(16384 + kd * 16384 +
                                      (ih * 64 + q * 16 + b_rl) * 128) + kco);
            mma16816(c[2 * q],     aH, bh[0], bh[1]);
            mma16816(c[2 * q + 1], aH, bh[2], bh[3]);
        }
    }

    const int ccol = (lane & 3) * 2;
    const int k0 = im * 16 + (lane >> 2);
#pragma unroll
    for (int nt = 0; nt < 8; nt++) {
        int o = ih * 64 + nt * 8 + ccol;
        *reinterpret_cast<uint32_t*>(&g_Gh[b * 8192 + k0 * 128 + o]) =
            packh2(c[nt][0], c[nt][1]);
        *reinterpret_cast<uint32_t*>(&g_Gh[b * 8192 + (k0 + 8) * 128 + o]) =
            packh2(c[nt][2], c[nt][3]);
    }

    // cv exact fp32
    if (tid < 64) {
        float acc = 0.f;
#pragma unroll 4
        for (int p = 0; p < 128; p++)
            acc += b3[p] * g_farr[b][p][tid];
        g_cv[b][tid] = acc;
    }
}

__global__ void __launch_bounds__(256) stage2_kernel(
    const float* __restrict__ b1, const float* __restrict__ b3,
    float* __restrict__ out_move)
{
    extern __shared__ char s2[];
    const int bid = blockIdx.x;
    if (bid < 128)      sp_mma(s2, bid & 1, bid >> 1, b1);
    else if (bid < 192) move_mma(s2, bid - 128, out_move);
    else                g_mma(s2, bid - 192, b3);
}

// ============================================================================
// Main (hot): unchanged (bit-identical path).
// ============================================================================
__global__ void __launch_bounds__(256, 2) main_kernel(
    const float* __restrict__ b2, float* __restrict__ out_arrow)
{
    extern __shared__ char smc[];
    __shared__ float  s_cv[64];
    __shared__ float  s_b2[128];
    __shared__ __half s_dst[2][256];

    const uint32_t sb = smem_u32(smc);
    const int tid  = threadIdx.x;
    const int wid  = tid >> 5;
    const int lane = tid & 31;
    const int mt = blockIdx.x, b = blockIdx.y, m0 = mt * 2;

    const int ABUF = 65536;
    const int im = wid & 3;
    const int in = wid >> 2;

    const int rowinm = lane & 7, mi = lane >> 3;
    const int a_kx = mi >> 1;
    const int a_rl = ((mi & 1) << 3) + rowinm;
    const int b_rl = ((mi >> 1) << 3) + rowinm;
    const int b_sw = rowinm;
    const int b_kx = mi & 1;

    const int ag_grp  = tid & 7;
    const int ag_row0 = tid >> 3;

    {
        for (int i = tid; i < 4096; i += 256) {
            int o = i >> 5, grp = i & 31;
            int kc = grp >> 3, cgl = grp & 7;
            const uint4* src = reinterpret_cast<const uint4*>(g_w2h + o * 256 + grp * 8);
            uint32_t dst = (uint32_t)(kc * 16384 + o * 128 + ((cgl ^ (o & 7)) << 4));
            *reinterpret_cast<uint4*>(smc + dst) = *src;
        }
        if (tid < 64)  s_cv[tid] = g_cv[b][tid];
        if (tid < 128) s_b2[tid] = b2[tid];
        if (tid < 64) {
            int lm = tid >> 5, grp = tid & 31;
            *reinterpret_cast<uint4*>(&s_dst[lm][grp * 8]) =
                *reinterpret_cast<const uint4*>(&g_dstp_h[b][m0 + lm][grp * 8]);
        }
#pragma unroll
        for (int j = 0; j < 4; j++) {
            int row = ag_row0 + 32 * j;
            int n = row & 63, lm = row >> 6;
            uint4 s = *reinterpret_cast<const uint4*>(&g_srcp_h[b][n][ag_grp * 8]);
            uint4 d = *reinterpret_cast<const uint4*>(&g_dstp_h[b][m0 + lm][ag_grp * 8]);
            uint4 v = reluadd4(s, d);
            uint32_t off = (uint32_t)(row * 128 + ((ag_grp ^ (row & 7)) << 4));
            *reinterpret_cast<uint4*>(smc + ABUF + off) = v;
        }
    }
    __syncthreads();

    float c1[2][8][4];
#pragma unroll
    for (int m = 0; m < 2; m++)
#pragma unroll
        for (int i = 0; i < 8; i++)
#pragma unroll
            for (int j = 0; j < 4; j++) c1[m][i][j] = 0.f;

#pragma unroll 1
    for (int kc = 0; kc < 4; kc++) {
        const uint32_t curA = sb + (uint32_t)(ABUF + ((kc & 1) << 14));
        const uint32_t wHi  = sb + (uint32_t)(kc * 16384);

        uint4 ps[4];
        if (kc < 3) {
#pragma unroll
            for (int j = 0; j < 4; j++) {
                int row = ag_row0 + 32 * j;
                int n = row & 63;
                ps[j] = *reinterpret_cast<const uint4*>(
                    &g_srcp_h[b][n][(kc + 1) * 64 + ag_grp * 8]);
            }
        } else {
#pragma unroll
            for (int t = 0; t < 4; t++) {
                int i = tid + 256 * t;
                ps[t] = *reinterpret_cast<const uint4*>(
                    &g_Gh[b * 8192 + (i >> 4) * 128 + (i & 15) * 8]);
            }
        }

#pragma unroll
        for (int ks = 0; ks < 2; ks++) {
            uint32_t aH[2][4];
#pragma unroll
            for (int m = 0; m < 2; m++) {
                int a_r = im * 32 + m * 16 + a_rl;
                uint32_t co = (uint32_t)(((ks * 2 + a_kx) ^ (a_r & 7)) << 4);
                ldmx4(aH[m], curA + (uint32_t)(a_r * 128) + co);
            }
            uint32_t kco = (uint32_t)(((ks * 2 + b_kx) ^ b_sw) << 4);
            uint32_t bh[4][4];
#pragma unroll
            for (int q = 0; q < 4; q++) {
                int o_row = in * 64 + q * 16 + b_rl;
                ldmx4(bh[q], wHi + (uint32_t)(o_row * 128) + kco);
            }
#pragma unroll
            for (int q = 0; q < 4; q++)
#pragma unroll
                for (int m = 0; m < 2; m++) {
                    mma16816(c1[m][2 * q],     aH[m], bh[q][0], bh[q][1]);
                    mma16816(c1[m][2 * q + 1], aH[m], bh[q][2], bh[q][3]);
                }
        }

        uint4 pv[4];
        if (kc < 3) {
#pragma unroll
            for (int j = 0; j < 4; j++) {
                int row = ag_row0 + 32 * j;
                int lm = row >> 6;
                uint4 d = *reinterpret_cast<const uint4*>(
                    &s_dst[lm][(kc + 1) * 64 + ag_grp * 8]);
                pv[j] = reluadd4(ps[j], d);
            }
        } else {
#pragma unroll
            for (int t = 0; t < 4; t++) pv[t] = ps[t];
        }

#pragma unroll
        for (int ks = 2; ks < 4; ks++) {
            uint32_t aH[2][4];
#pragma unroll
            for (int m = 0; m < 2; m++) {
                int a_r = im * 32 + m * 16 + a_rl;
                uint32_t co = (uint32_t)(((ks * 2 + a_kx) ^ (a_r & 7)) << 4);
                ldmx4(aH[m], curA + (uint32_t)(a_r * 128) + co);
            }
            uint32_t kco = (uint32_t)(((ks * 2 + b_kx) ^ b_sw) << 4);
            uint32_t bh[4][4];
#pragma unroll
            for (int q = 0; q < 4; q++) {
                int o_row = in * 64 + q * 16 + b_rl;
                ldmx4(bh[q], wHi + (uint32_t)(o_row * 128) + kco);
            }
#pragma unroll
            for (int q = 0; q < 4; q++)
#pragma unroll
                for (int m = 0; m < 2; m++) {
                    mma16816(c1[m][2 * q],     aH[m], bh[q][0], bh[q][1]);
                    mma16816(c1[m][2 * q + 1], aH[m], bh[q][2], bh[q][3]);
                }
        }

        if (kc < 3) {
            char* obuf = smc + ABUF + (((kc + 1) & 1) << 14);
#pragma unroll
            for (int j = 0; j < 4; j++) {
                int row = ag_row0 + 32 * j;
                uint32_t off = (uint32_t)(row * 128 + ((ag_grp ^ (row & 7)) << 4));
                *reinterpret_cast<uint4*>(obuf + off) = pv[j];
            }
        } else {
#pragma unroll
            for (int t = 0; t < 4; t++) {
                int i = tid + 256 * t;
                int r = i >> 4, grp = i & 15;
                int kh = grp >> 3, cgl = grp & 7;
                uint32_t dst = (uint32_t)(ABUF + kh * 8192 + r * 128 +
                                          ((cgl ^ (r & 7)) << 4));
                *reinterpret_cast<uint4*>(smc + dst) = pv[t];
            }
        }
        __syncthreads();
    }

    const int ccol = (lane & 3) * 2;
    uint32_t aH2[2][4][4];
#pragma unroll
    for (int m = 0; m < 2; m++)
#pragma unroll
        for (int ko = 0; ko < 4; ko++) {
#pragma unroll
            for (int hn = 0; hn < 2; hn++) {
                int nt = 2 * ko + hn;
                float bv0 = s_b2[in * 64 + nt * 8 + ccol];
                float bv1 = s_b2[in * 64 + nt * 8 + ccol + 1];
                aH2[m][ko][hn * 2]     = packh2(fmaxf(c1[m][nt][0] + bv0, 0.f),
                                                fmaxf(c1[m][nt][1] + bv1, 0.f));
                aH2[m][ko][hn * 2 + 1] = packh2(fmaxf(c1[m][nt][2] + bv0, 0.f),
                                                fmaxf(c1[m][nt][3] + bv1, 0.f));
            }
        }

    float c2[2][8][4];
#pragma unroll
    for (int m = 0; m < 2; m++)
#pragma unroll
        for (int i = 0; i < 8; i++)
#pragma unroll
            for (int j = 0; j < 4; j++) c2[m][i][j] = 0.f;

    const uint32_t gBase = sb + (uint32_t)(ABUF + in * 8192);
#pragma unroll
    for (int ko = 0; ko < 4; ko++) {
        uint32_t kco = (uint32_t)(((ko * 2 + b_kx) ^ b_sw) << 4);
        uint32_t bh[4][4];
#pragma unroll
        for (int q = 0; q < 4; q++)
            ldmx4(bh[q], gBase + (uint32_t)((q * 16 + b_rl) * 128) + kco);
#pragma unroll
        for (int q = 0; q < 4; q++)
#pragma unroll
            for (int m = 0; m < 2; m++) {
                mma16816(c2[m][2 * q],     aH2[m][ko], bh[q][0], bh[q][1]);
                mma16816(c2[m][2 * q + 1], aH2[m][ko], bh[q][2], bh[q][3]);
            }
    }

    float* rbuf = reinterpret_cast<float*>(smc);
    if (in == 1) {
#pragma unroll
        for (int m = 0; m < 2; m++) {
            int r0 = im * 32 + m * 16 + (lane >> 2);
#pragma unroll
            for (int kt = 0; kt < 8; kt++) {
                int k = kt * 8 + ccol;
                *reinterpret_cast<float2*>(&rbuf[r0 * 72 + k]) =
                    make_float2(c2[m][kt][0], c2[m][kt][1]);
                *reinterpret_cast<float2*>(&rbuf[(r0 + 8) * 72 + k]) =
                    make_float2(c2[m][kt][2], c2[m][kt][3]);
            }
        }
    }
    __syncthreads();
    if (in == 0) {
#pragma unroll
        for (int m = 0; m < 2; m++) {
            int r0 = im * 32 + m * 16 + (lane >> 2);
            int r1 = r0 + 8;
            float* p0 = out_arrow + (((size_t)b * 4096 +
                                      (size_t)(r0 & 63) * 64 + m0 + (r0 >> 6)) << 6);
            float* p1 = out_arrow + (((size_t)b * 4096 +
                                      (size_t)(r1 & 63) * 64 + m0 + (r1 >> 6)) << 6);
#pragma unroll
            for (int kt = 0; kt < 8; kt++) {
                int k = kt * 8 + ccol;
                float2 q0 = *reinterpret_cast<const float2*>(&rbuf[r0 * 72 + k]);
                float2 q1 = *reinterpret_cast<const float2*>(&rbuf[r1 * 72 + k]);
                float cv0 = s_cv[k], cv1 = s_cv[k + 1];
                float2 v0 = make_float2((c2[m][kt][0] + q0.x + cv0) * SCALE_V,
                                        (c2[m][kt][1] + q0.y + cv1) * SCALE_V);
                float2 v1 = make_float2((c2[m][kt][2] + q1.x + cv0) * SCALE_V,
                                        (c2[m][kt][3] + q1.y + cv1) * SCALE_V);
                *reinterpret_cast<float2*>(p0 + k) = v0;
                *reinterpret_cast<float2*>(p1 + k) = v1;
            }
        }
    }
}

// ============================================================================
// launch
// ============================================================================
extern "C" void kernel_launch(void* const* d_in, const int* in_sizes, int n_in,
                              void* d_out, int out_size)
{
    (void)in_sizes; (void)n_in; (void)out_size;
    const float* x     = (const float*)d_in[0];
    const float* w_src = (const float*)d_in[1];
    const float* b_src = (const float*)d_in[2];
    const float* w_dst = (const float*)d_in[3];
    const float* b_dst = (const float*)d_in[4];
    const float* w_arr = (const float*)d_in[5];
    const float* b_arr = (const float*)d_in[6];
    const float* w1    = (const float*)d_in[7];
    const float* b1    = (const float*)d_in[8];
    const float* w2    = (const float*)d_in[9];
    const float* b2    = (const float*)d_in[10];
    const float* w3    = (const float*)d_in[11];
    const float* b3    = (const float*)d_in[12];

    float* out_move  = (float*)d_out;                       // 64*64*64
    float* out_arrow = (float*)d_out + 64 * 64 * 64;        // 64*4096*64

    constexpr int SMEM_MAIN = 98304;
    constexpr int SMEM_S2   = 81920;
    cudaFuncSetAttribute(main_kernel, cudaFuncAttributeMaxDynamicSharedMemorySize,
                         SMEM_MAIN);
    cudaFuncSetAttribute(stage2_kernel, cudaFuncAttributeMaxDynamicSharedMemorySize,
                         SMEM_S2);
    cudaFuncSetAttribute(prep_kernel, cudaFuncAttributeMaxDynamicSharedMemorySize,
                         SMEM_MAIN);

    prep_kernel<<<512, 256, SMEM_MAIN>>>(x, w_src, b_src, w_dst, b_dst,
                                         w_arr, b_arr, w1, w2, w3);
    stage2_kernel<<<256, 256, SMEM_S2>>>(b1, b3, out_move);
    main_kernel<<<dim3(32, 64), 256, SMEM_MAIN>>>(b2, out_arrow);
}